// round 5
// baseline (speedup 1.0000x reference)
#include <cuda_runtime.h>
#include <cuda_bf16.h>
#include <cstdint>
#include <math.h>

// Problem constants
#define B_  2
#define T_  2048
#define E_  2048
#define H_  32
#define HKV_ 8
#define D_  64
#define BT_ (B_*T_)  // 4096

// ---------------------------------------------------------------------------
// Scratch (static device globals — allocation-free rule)
// ---------------------------------------------------------------------------
__device__ float g_Q[BT_ * H_ * D_];
__device__ float g_K[BT_ * HKV_ * D_];

__device__ __nv_bfloat16 g_xh[BT_ * E_],  g_xl[BT_ * E_];
__device__ __nv_bfloat16 g_Yh[BT_ * E_],  g_Yl[BT_ * E_];
__device__ __nv_bfloat16 g_Qh[BT_ * H_ * D_],   g_Ql[BT_ * H_ * D_];
__device__ __nv_bfloat16 g_Kh[BT_ * HKV_ * D_], g_Kl[BT_ * HKV_ * D_];
__device__ __nv_bfloat16 g_Vh[BT_ * HKV_ * D_], g_Vl[BT_ * HKV_ * D_];
// Transposed weights [N, K] split hi/lo
__device__ __nv_bfloat16 g_Wqh[E_ * H_ * D_],   g_Wql[E_ * H_ * D_];
__device__ __nv_bfloat16 g_Wkh[E_ * HKV_ * D_], g_Wkl[E_ * HKV_ * D_];
__device__ __nv_bfloat16 g_Wvh[E_ * HKV_ * D_], g_Wvl[E_ * HKV_ * D_];
__device__ __nv_bfloat16 g_Woh[E_ * E_],        g_Wol[E_ * E_];

// ---------------------------------------------------------------------------
// PTX helpers (sm_80+ path: mma.sync / ldmatrix / cp.async)
// ---------------------------------------------------------------------------
__device__ __forceinline__ uint32_t smem_u32(const void* p) {
    uint32_t a;
    asm("{ .reg .u64 t; cvta.to.shared.u64 t, %1; cvt.u32.u64 %0, t; }" : "=r"(a) : "l"(p));
    return a;
}

__device__ __forceinline__ void ldmx4(uint32_t* r, uint32_t addr) {
    asm volatile("ldmatrix.sync.aligned.m8n8.x4.shared.b16 {%0,%1,%2,%3}, [%4];"
                 : "=r"(r[0]), "=r"(r[1]), "=r"(r[2]), "=r"(r[3]) : "r"(addr));
}
__device__ __forceinline__ void ldmx4t(uint32_t* r, uint32_t addr) {
    asm volatile("ldmatrix.sync.aligned.m8n8.x4.trans.shared.b16 {%0,%1,%2,%3}, [%4];"
                 : "=r"(r[0]), "=r"(r[1]), "=r"(r[2]), "=r"(r[3]) : "r"(addr));
}

__device__ __forceinline__ void mma_bf16(float* acc, const uint32_t* a, const uint32_t b0,
                                         const uint32_t b1) {
    asm volatile(
        "mma.sync.aligned.m16n8k16.row.col.f32.bf16.bf16.f32 "
        "{%0,%1,%2,%3}, {%4,%5,%6,%7}, {%8,%9}, {%0,%1,%2,%3};"
        : "+f"(acc[0]), "+f"(acc[1]), "+f"(acc[2]), "+f"(acc[3])
        : "r"(a[0]), "r"(a[1]), "r"(a[2]), "r"(a[3]), "r"(b0), "r"(b1));
}

__device__ __forceinline__ void cp_async16(uint32_t saddr, const void* gaddr) {
    asm volatile("cp.async.cg.shared.global [%0], [%1], 16;" :: "r"(saddr), "l"(gaddr));
}
#define CP_COMMIT() asm volatile("cp.async.commit_group;" ::: "memory")
#define CP_WAIT(n)  asm volatile("cp.async.wait_group %0;" :: "n"(n) : "memory")

__device__ __forceinline__ uint32_t pack_bf16x2(float lo, float hi) {
    __nv_bfloat162 v = __floats2bfloat162_rn(lo, hi);
    return *reinterpret_cast<uint32_t*>(&v);
}

// ---------------------------------------------------------------------------
// bf16x3 split-precision GEMM via mma.sync, 4-stage cp.async pipeline.
// C[M,N](fp32 or bf16-h/l) = Ah·Bh^T + Ah·Bl^T + Al·Bh^T; A[M,K], B[N,K] K-major.
// 128x128 CTA tile, BK=32, 256 threads. Term-major MMA passes (no dep chains).
// ---------------------------------------------------------------------------
#define ROWB   80
#define REGB   (128 * ROWB)          // 10240 per region
#define STGB   (4 * REGB)            // 40960 per stage (Ah,Al,Bh,Bl)
#define NSTG   4
#define GEMM_SMEM_TOTAL (NSTG * STGB)  // 163840

__device__ __forceinline__ void issue_buf(uint32_t sbuf,
                                          const __nv_bfloat16* ah, const __nv_bfloat16* al,
                                          const __nv_bfloat16* bh, const __nv_bfloat16* bl,
                                          int K, int tid) {
    const __nv_bfloat16* srcs[4] = {ah, al, bh, bl};
#pragma unroll
    for (int reg = 0; reg < 4; ++reg) {
        const __nv_bfloat16* s = srcs[reg];
        uint32_t sr = sbuf + reg * REGB;
#pragma unroll
        for (int j = 0; j < 2; ++j) {
            int c = tid + j * 256;
            int row = c >> 2, part = c & 3;
            cp_async16(sr + row * ROWB + part * 16, s + (size_t)row * K + part * 8);
        }
    }
}

__global__ __launch_bounds__(256)
void gemm3_kernel(float* __restrict__ C,
                  __nv_bfloat16* __restrict__ Ch, __nv_bfloat16* __restrict__ Cl,
                  const __nv_bfloat16* __restrict__ Ah, const __nv_bfloat16* __restrict__ Al,
                  const __nv_bfloat16* __restrict__ Bh, const __nv_bfloat16* __restrict__ Bl,
                  int M, int N, int K, int bf16out) {
    extern __shared__ char smem[];
    const uint32_t sbase = smem_u32(smem);
    const int tid = threadIdx.x;
    const int wid = tid >> 5, lane = tid & 31;
    const int warp_m = wid >> 2;          // 0..1 -> 64-row slab
    const int warp_n = wid & 3;           // 0..3 -> 32-col slab
    const int bm = blockIdx.y * 128, bn = blockIdx.x * 128;

    const __nv_bfloat16* pAh = Ah + (size_t)bm * K;
    const __nv_bfloat16* pAl = Al + (size_t)bm * K;
    const __nv_bfloat16* pBh = Bh + (size_t)bn * K;
    const __nv_bfloat16* pBl = Bl + (size_t)bn * K;

    float acc[4][4][4];
#pragma unroll
    for (int i = 0; i < 4; ++i)
#pragma unroll
        for (int j = 0; j < 4; ++j)
#pragma unroll
            for (int k = 0; k < 4; ++k) acc[i][j][k] = 0.0f;

    const int NIT = K / 32;               // 64

    const uint32_t a_row = warp_m * 64 + (lane & 15);
    const uint32_t a_coff = (lane >> 4) * 16;
    const uint32_t b_rowbase = warp_n * 32 + (lane & 15);
    const uint32_t b_coff = (lane >> 4) * 16;

    // Prologue: issue stages 0..NSTG-2
#pragma unroll
    for (int s = 0; s < NSTG - 1; ++s) {
        issue_buf(sbase + s * STGB, pAh + s * 32, pAl + s * 32,
                  pBh + s * 32, pBl + s * 32, K, tid);
        CP_COMMIT();
    }

    for (int it = 0; it < NIT; ++it) {
        CP_WAIT(NSTG - 2);                // stage `it` complete
        __syncthreads();                  // also frees buffer (it-1)%NSTG

        const int nx = it + NSTG - 1;
        if (nx < NIT) {
            issue_buf(sbase + (nx & (NSTG - 1)) * STGB,
                      pAh + nx * 32, pAl + nx * 32, pBh + nx * 32, pBl + nx * 32, K, tid);
        }
        CP_COMMIT();                      // empty group near the tail keeps counts aligned

        const uint32_t sbuf = sbase + (it & (NSTG - 1)) * STGB;
        const uint32_t sAh = sbuf, sAl = sbuf + REGB;
        const uint32_t sBh = sbuf + 2 * REGB, sBl = sbuf + 3 * REGB;

#pragma unroll
        for (int ks = 0; ks < 2; ++ks) {
            const uint32_t kb = ks * 32;
            uint32_t bhf[8], blf[8];
#pragma unroll
            for (int p = 0; p < 2; ++p) {
                uint32_t ba = (b_rowbase + p * 16) * ROWB + kb + b_coff;
                ldmx4(&bhf[p * 4], sBh + ba);
                ldmx4(&blf[p * 4], sBl + ba);
            }
            uint32_t ahf[4][4], alf[4][4];
#pragma unroll
            for (int mi = 0; mi < 4; ++mi) {
                uint32_t aa = (a_row + mi * 16) * ROWB + kb + a_coff;
                ldmx4(ahf[mi], sAh + aa);
                ldmx4(alf[mi], sAl + aa);
            }
            // pass 1: Ah·Bh  (16 independent accs)
#pragma unroll
            for (int mi = 0; mi < 4; ++mi)
#pragma unroll
                for (int ni = 0; ni < 4; ++ni) {
                    const int p = ni >> 1, q = ni & 1;
                    mma_bf16(acc[mi][ni], ahf[mi], bhf[p * 4 + q], bhf[p * 4 + q + 2]);
                }
            // pass 2: Ah·Bl
#pragma unroll
            for (int mi = 0; mi < 4; ++mi)
#pragma unroll
                for (int ni = 0; ni < 4; ++ni) {
                    const int p = ni >> 1, q = ni & 1;
                    mma_bf16(acc[mi][ni], ahf[mi], blf[p * 4 + q], blf[p * 4 + q + 2]);
                }
            // pass 3: Al·Bh
#pragma unroll
            for (int mi = 0; mi < 4; ++mi)
#pragma unroll
                for (int ni = 0; ni < 4; ++ni) {
                    const int p = ni >> 1, q = ni & 1;
                    mma_bf16(acc[mi][ni], alf[mi], bhf[p * 4 + q], bhf[p * 4 + q + 2]);
                }
        }
    }

    // Epilogue
    const int rbase = bm + warp_m * 64 + (lane >> 2);
    const int cbase = bn + warp_n * 32 + (lane & 3) * 2;
    if (!bf16out) {
#pragma unroll
        for (int mi = 0; mi < 4; ++mi)
#pragma unroll
            for (int ni = 0; ni < 4; ++ni) {
                float* c0 = C + (size_t)(rbase + mi * 16) * N + cbase + ni * 8;
                float* c1 = C + (size_t)(rbase + mi * 16 + 8) * N + cbase + ni * 8;
                *(float2*)c0 = make_float2(acc[mi][ni][0], acc[mi][ni][1]);
                *(float2*)c1 = make_float2(acc[mi][ni][2], acc[mi][ni][3]);
            }
    } else {
#pragma unroll
        for (int mi = 0; mi < 4; ++mi)
#pragma unroll
            for (int ni = 0; ni < 4; ++ni) {
                float v0 = acc[mi][ni][0], v1 = acc[mi][ni][1];
                float v2 = acc[mi][ni][2], v3 = acc[mi][ni][3];
                uint32_t h01 = pack_bf16x2(v0, v1);
                uint32_t h23 = pack_bf16x2(v2, v3);
                __nv_bfloat162 hb01 = *reinterpret_cast<__nv_bfloat162*>(&h01);
                __nv_bfloat162 hb23 = *reinterpret_cast<__nv_bfloat162*>(&h23);
                uint32_t l01 = pack_bf16x2(v0 - __low2float(hb01), v1 - __high2float(hb01));
                uint32_t l23 = pack_bf16x2(v2 - __low2float(hb23), v3 - __high2float(hb23));
                size_t o0 = (size_t)(rbase + mi * 16) * N + cbase + ni * 8;
                size_t o1 = (size_t)(rbase + mi * 16 + 8) * N + cbase + ni * 8;
                *(uint32_t*)&Ch[o0] = h01;
                *(uint32_t*)&Ch[o1] = h23;
                *(uint32_t*)&Cl[o0] = l01;
                *(uint32_t*)&Cl[o1] = l23;
            }
    }
}

// ---------------------------------------------------------------------------
// fp32 -> bf16 hi/lo split
// ---------------------------------------------------------------------------
__global__ __launch_bounds__(256)
void split_kernel(const float* __restrict__ in, __nv_bfloat16* __restrict__ hi,
                  __nv_bfloat16* __restrict__ lo, int n) {
    int i = blockIdx.x * blockDim.x + threadIdx.x;
    if (i >= n) return;
    float v = in[i];
    __nv_bfloat16 h = __float2bfloat16(v);
    hi[i] = h;
    lo[i] = __float2bfloat16(v - __bfloat162float(h));
}

// ---------------------------------------------------------------------------
// Transpose + split: W[K,N] fp32 -> Th/Tl[N,K] bf16
// ---------------------------------------------------------------------------
__global__ __launch_bounds__(256)
void tsplit_kernel(const float* __restrict__ W, __nv_bfloat16* __restrict__ Th,
                   __nv_bfloat16* __restrict__ Tl, int K, int N) {
    __shared__ float t[32][33];
    const int tx = threadIdx.x, ty = threadIdx.y;
    const int n0 = blockIdx.x * 32, k0 = blockIdx.y * 32;
#pragma unroll
    for (int i = 0; i < 4; ++i)
        t[ty + i * 8][tx] = W[(size_t)(k0 + ty + i * 8) * N + n0 + tx];
    __syncthreads();
#pragma unroll
    for (int i = 0; i < 4; ++i) {
        float v = t[tx][ty + i * 8];
        __nv_bfloat16 h = __float2bfloat16(v);
        size_t o = (size_t)(n0 + ty + i * 8) * K + k0 + tx;
        Th[o] = h;
        Tl[o] = __float2bfloat16(v - __bfloat162float(h));
    }
}

// ---------------------------------------------------------------------------
// RoPE + hi/lo split (fused): reads fp32, writes rotated bf16 hi/lo
// ---------------------------------------------------------------------------
__global__ __launch_bounds__(256)
void rope_split_kernel(const float* __restrict__ buf, __nv_bfloat16* __restrict__ hi,
                       __nv_bfloat16* __restrict__ lo, int nh) {
    int idx = blockIdx.x * blockDim.x + threadIdx.x;
    int total = B_ * T_ * nh * 32;
    if (idx >= total) return;
    int i = idx & 31;
    int h = (idx >> 5) % nh;
    int t = (idx / (32 * nh)) % T_;
    int b = idx / (32 * nh * T_);

    float inv_freq = expf(-(float)i * (9.210340371976184f / 32.0f));
    float ang = (float)t * inv_freq;
    float c = cosf(ang), s = sinf(ang);

    size_t off = ((size_t)(b * T_ + t) * nh + h) * 64;
    float x1 = buf[off + i];
    float x2 = buf[off + 32 + i];
    float r1 = x1 * c - x2 * s;
    float r2 = x2 * c + x1 * s;
    __nv_bfloat16 h1 = __float2bfloat16(r1);
    __nv_bfloat16 h2 = __float2bfloat16(r2);
    hi[off + i] = h1;              lo[off + i] = __float2bfloat16(r1 - __bfloat162float(h1));
    hi[off + 32 + i] = h2;         lo[off + 32 + i] = __float2bfloat16(r2 - __bfloat162float(h2));
}

// ---------------------------------------------------------------------------
// FA2-style causal attention with mma.sync, bf16x3 split precision.
// Grid (T/128, H, B), 256 threads (8 warps x 16 q-rows). Writes Yh/Yl bf16.
// ---------------------------------------------------------------------------
#define AROWB 144
#define KVREG (64 * AROWB)
#define KVBUF (4 * KVREG)
#define QREG  (128 * AROWB)
#define ATT_SMEM (2 * QREG + 2 * KVBUF)

__global__ __launch_bounds__(256)
void attn_mma_kernel(__nv_bfloat16* __restrict__ Yh, __nv_bfloat16* __restrict__ Yl,
                     const __nv_bfloat16* __restrict__ Qh, const __nv_bfloat16* __restrict__ Ql,
                     const __nv_bfloat16* __restrict__ Kh, const __nv_bfloat16* __restrict__ Kl,
                     const __nv_bfloat16* __restrict__ Vh, const __nv_bfloat16* __restrict__ Vl) {
    extern __shared__ char smem[];
    const uint32_t sbase = smem_u32(smem);
    const uint32_t sQh = sbase, sQl = sbase + QREG;
    const uint32_t sKV = sbase + 2 * QREG;

    const int tid = threadIdx.x;
    const int wid = tid >> 5, lane = tid & 31;
    const int qb = blockIdx.x;
    const int h  = blockIdx.y;
    const int b  = blockIdx.z;
    const int kh = h >> 2;
    const int bT0 = b * T_;

    const int row0 = qb * 128 + wid * 16 + (lane >> 2);
    const int row1 = row0 + 8;
    const int rowmin_w = qb * 128 + wid * 16;
    const int rowmax_w = rowmin_w + 15;

    {
        const __nv_bfloat16* srcs[2] = {Qh, Ql};
#pragma unroll
        for (int j = 0; j < 8; ++j) {
            int c = tid + j * 256;
            int reg = c >> 10, idx = c & 1023;
            int row = idx >> 3, part = idx & 7;
            uint32_t dst = (reg ? sQl : sQh) + row * AROWB + part * 16;
            cp_async16(dst, srcs[reg] + ((size_t)(bT0 + qb * 128 + row) * H_ + h) * 64 + part * 8);
        }
    }
    const __nv_bfloat16* kvsrc[4] = {Kh, Kl, Vh, Vl};
    {
#pragma unroll
        for (int j = 0; j < 8; ++j) {
            int c = tid + j * 256;
            int reg = c >> 9, idx = c & 511;
            int row = idx >> 3, part = idx & 7;
            uint32_t dst = sKV + reg * KVREG + row * AROWB + part * 16;
            cp_async16(dst, kvsrc[reg] + ((size_t)(bT0 + row) * HKV_ + kh) * 64 + part * 8);
        }
    }
    CP_COMMIT();
    CP_WAIT(0);
    __syncthreads();

    uint32_t qfh[4][4], qfl[4][4];
#pragma unroll
    for (int ks = 0; ks < 4; ++ks) {
        uint32_t qa = (wid * 16 + (lane & 15)) * AROWB + ks * 32 + (lane >> 4) * 16;
        ldmx4(qfh[ks], sQh + qa);
        ldmx4(qfl[ks], sQl + qa);
    }

    float o[8][4];
#pragma unroll
    for (int j = 0; j < 8; ++j)
#pragma unroll
        for (int k = 0; k < 4; ++k) o[j][k] = 0.0f;
    float m0 = -1e30f, m1 = -1e30f, l0 = 0.0f, l1 = 0.0f;
    const float scale = 0.125f;

    const int NT = 2 * qb + 2;
    for (int it = 0; it < NT; ++it) {
        if (it + 1 < NT) {
            uint32_t sb = sKV + ((it + 1) & 1) * KVBUF;
#pragma unroll
            for (int j = 0; j < 8; ++j) {
                int c = tid + j * 256;
                int reg = c >> 9, idx = c & 511;
                int row = idx >> 3, part = idx & 7;
                cp_async16(sb + reg * KVREG + row * AROWB + part * 16,
                           kvsrc[reg] + ((size_t)(bT0 + (it + 1) * 64 + row) * HKV_ + kh) * 64 + part * 8);
            }
            CP_COMMIT();
            CP_WAIT(1);
        } else {
            CP_WAIT(0);
        }
        __syncthreads();

        const int kt = it;
        if (kt * 64 <= rowmax_w) {
            const uint32_t sb = sKV + (it & 1) * KVBUF;
            const uint32_t sKh = sb, sKl = sb + KVREG;
            const uint32_t sVh = sb + 2 * KVREG, sVl = sb + 3 * KVREG;

            float s[8][4];
#pragma unroll
            for (int j = 0; j < 8; ++j)
#pragma unroll
                for (int k = 0; k < 4; ++k) s[j][k] = 0.0f;

#pragma unroll
            for (int ks = 0; ks < 4; ++ks) {
#pragma unroll
                for (int pg = 0; pg < 2; ++pg) {
                    uint32_t kfh[2][4], kfl[2][4];
#pragma unroll
                    for (int pp = 0; pp < 2; ++pp) {
                        uint32_t ka = ((2 * pg + pp) * 16 + (lane & 15)) * AROWB + ks * 32 + (lane >> 4) * 16;
                        ldmx4(kfh[pp], sKh + ka);
                        ldmx4(kfl[pp], sKl + ka);
                    }
#pragma unroll
                    for (int pp = 0; pp < 2; ++pp)
#pragma unroll
                        for (int q = 0; q < 2; ++q)
                            mma_bf16(s[(2 * pg + pp) * 2 + q], qfh[ks], kfh[pp][q], kfh[pp][q + 2]);
#pragma unroll
                    for (int pp = 0; pp < 2; ++pp)
#pragma unroll
                        for (int q = 0; q < 2; ++q)
                            mma_bf16(s[(2 * pg + pp) * 2 + q], qfh[ks], kfl[pp][q], kfl[pp][q + 2]);
#pragma unroll
                    for (int pp = 0; pp < 2; ++pp)
#pragma unroll
                        for (int q = 0; q < 2; ++q)
                            mma_bf16(s[(2 * pg + pp) * 2 + q], qfl[ks], kfh[pp][q], kfh[pp][q + 2]);
                }
            }

            const bool needs_mask = (kt * 64 + 63) > rowmin_w;
#pragma unroll
            for (int j = 0; j < 8; ++j) {
#pragma unroll
                for (int k = 0; k < 4; ++k) s[j][k] *= scale;
                if (needs_mask) {
                    int colb = kt * 64 + j * 8 + 2 * (lane & 3);
                    if (colb > row0)     s[j][0] = -1e30f;
                    if (colb + 1 > row0) s[j][1] = -1e30f;
                    if (colb > row1)     s[j][2] = -1e30f;
                    if (colb + 1 > row1) s[j][3] = -1e30f;
                }
            }

            float mx0 = -1e30f, mx1 = -1e30f;
#pragma unroll
            for (int j = 0; j < 8; ++j) {
                mx0 = fmaxf(mx0, fmaxf(s[j][0], s[j][1]));
                mx1 = fmaxf(mx1, fmaxf(s[j][2], s[j][3]));
            }
            mx0 = fmaxf(mx0, __shfl_xor_sync(0xFFFFFFFF, mx0, 1));
            mx0 = fmaxf(mx0, __shfl_xor_sync(0xFFFFFFFF, mx0, 2));
            mx1 = fmaxf(mx1, __shfl_xor_sync(0xFFFFFFFF, mx1, 1));
            mx1 = fmaxf(mx1, __shfl_xor_sync(0xFFFFFFFF, mx1, 2));

            float mn0 = fmaxf(m0, mx0), mn1 = fmaxf(m1, mx1);
            float c0 = __expf(m0 - mn0), c1 = __expf(m1 - mn1);
            m0 = mn0; m1 = mn1;
            l0 *= c0; l1 *= c1;
#pragma unroll
            for (int j = 0; j < 8; ++j) {
                o[j][0] *= c0; o[j][1] *= c0; o[j][2] *= c1; o[j][3] *= c1;
            }
#pragma unroll
            for (int j = 0; j < 8; ++j) {
                s[j][0] = __expf(s[j][0] - mn0);
                s[j][1] = __expf(s[j][1] - mn0);
                s[j][2] = __expf(s[j][2] - mn1);
                s[j][3] = __expf(s[j][3] - mn1);
                l0 += s[j][0] + s[j][1];
                l1 += s[j][2] + s[j][3];
            }

#pragma unroll
            for (int ks = 0; ks < 4; ++ks) {
                uint32_t pah[4], pal[4];
                {
                    float p00 = s[2 * ks][0], p01 = s[2 * ks][1];
                    float p02 = s[2 * ks][2], p03 = s[2 * ks][3];
                    float p10 = s[2 * ks + 1][0], p11 = s[2 * ks + 1][1];
                    float p12 = s[2 * ks + 1][2], p13 = s[2 * ks + 1][3];
                    pah[0] = pack_bf16x2(p00, p01);
                    pah[1] = pack_bf16x2(p02, p03);
                    pah[2] = pack_bf16x2(p10, p11);
                    pah[3] = pack_bf16x2(p12, p13);
                    __nv_bfloat162 h0 = *reinterpret_cast<__nv_bfloat162*>(&pah[0]);
                    __nv_bfloat162 h1 = *reinterpret_cast<__nv_bfloat162*>(&pah[1]);
                    __nv_bfloat162 h2 = *reinterpret_cast<__nv_bfloat162*>(&pah[2]);
                    __nv_bfloat162 h3 = *reinterpret_cast<__nv_bfloat162*>(&pah[3]);
                    pal[0] = pack_bf16x2(p00 - __low2float(h0), p01 - __high2float(h0));
                    pal[1] = pack_bf16x2(p02 - __low2float(h1), p03 - __high2float(h1));
                    pal[2] = pack_bf16x2(p10 - __low2float(h2), p11 - __high2float(h2));
                    pal[3] = pack_bf16x2(p12 - __low2float(h3), p13 - __high2float(h3));
                }
#pragma unroll
                for (int pg = 0; pg < 2; ++pg) {
                    uint32_t vfh[2][4], vfl[2][4];
#pragma unroll
                    for (int pp = 0; pp < 2; ++pp) {
                        uint32_t va = (ks * 16 + (lane & 15)) * AROWB + (2 * pg + pp) * 32 + (lane >> 4) * 16;
                        ldmx4t(vfh[pp], sVh + va);
                        ldmx4t(vfl[pp], sVl + va);
                    }
#pragma unroll
                    for (int pp = 0; pp < 2; ++pp)
#pragma unroll
                        for (int q = 0; q < 2; ++q)
                            mma_bf16(o[(2 * pg + pp) * 2 + q], pah, vfh[pp][2 * q], vfh[pp][2 * q + 1]);
#pragma unroll
                    for (int pp = 0; pp < 2; ++pp)
#pragma unroll
                        for (int q = 0; q < 2; ++q)
                            mma_bf16(o[(2 * pg + pp) * 2 + q], pal, vfh[pp][2 * q], vfh[pp][2 * q + 1]);
#pragma unroll
                    for (int pp = 0; pp < 2; ++pp)
#pragma unroll
                        for (int q = 0; q < 2; ++q)
                            mma_bf16(o[(2 * pg + pp) * 2 + q], pah, vfl[pp][2 * q], vfl[pp][2 * q + 1]);
                }
            }
        }
        __syncthreads();
    }

    l0 += __shfl_xor_sync(0xFFFFFFFF, l0, 1);
    l0 += __shfl_xor_sync(0xFFFFFFFF, l0, 2);
    l1 += __shfl_xor_sync(0xFFFFFFFF, l1, 1);
    l1 += __shfl_xor_sync(0xFFFFFFFF, l1, 2);
    float inv0 = 1.0f / l0, inv1 = 1.0f / l1;

#pragma unroll
    for (int j = 0; j < 8; ++j) {
        int col = j * 8 + 2 * (lane & 3);
        float y0 = o[j][0] * inv0, y1 = o[j][1] * inv0;
        float y2 = o[j][2] * inv1, y3 = o[j][3] * inv1;
        size_t a0 = ((size_t)(bT0 + row0) * H_ + h) * 64 + col;
        size_t a1 = ((size_t)(bT0 + row1) * H_ + h) * 64 + col;
        uint32_t h01 = pack_bf16x2(y0, y1);
        uint32_t h23 = pack_bf16x2(y2, y3);
        __nv_bfloat162 hb01 = *reinterpret_cast<__nv_bfloat162*>(&h01);
        __nv_bfloat162 hb23 = *reinterpret_cast<__nv_bfloat162*>(&h23);
        uint32_t l01 = pack_bf16x2(y0 - __low2float(hb01), y1 - __high2float(hb01));
        uint32_t l23 = pack_bf16x2(y2 - __low2float(hb23), y3 - __high2float(hb23));
        *(uint32_t*)&Yh[a0] = h01;
        *(uint32_t*)&Yh[a1] = h23;
        *(uint32_t*)&Yl[a0] = l01;
        *(uint32_t*)&Yl[a1] = l23;
    }
}

// ---------------------------------------------------------------------------
// kernel_launch
// ---------------------------------------------------------------------------
extern "C" void kernel_launch(void* const* d_in, const int* in_sizes, int n_in,
                              void* d_out, int out_size) {
    const float* x  = (const float*)d_in[0];
    const float* Wq = (const float*)d_in[1];
    const float* Wk = (const float*)d_in[2];
    const float* Wv = (const float*)d_in[3];
    const float* Wo = (const float*)d_in[4];
    float* out = (float*)d_out;

    float *pQ, *pK;
    cudaGetSymbolAddress((void**)&pQ, g_Q);
    cudaGetSymbolAddress((void**)&pK, g_K);
    __nv_bfloat16 *pxh, *pxl, *pYh, *pYl;
    __nv_bfloat16 *pQh, *pQl, *pKh, *pKl, *pVh, *pVl;
    __nv_bfloat16 *pWqh, *pWql, *pWkh, *pWkl, *pWvh, *pWvl, *pWoh, *pWol;
    cudaGetSymbolAddress((void**)&pxh, g_xh);   cudaGetSymbolAddress((void**)&pxl, g_xl);
    cudaGetSymbolAddress((void**)&pYh, g_Yh);   cudaGetSymbolAddress((void**)&pYl, g_Yl);
    cudaGetSymbolAddress((void**)&pQh, g_Qh);   cudaGetSymbolAddress((void**)&pQl, g_Ql);
    cudaGetSymbolAddress((void**)&pKh, g_Kh);   cudaGetSymbolAddress((void**)&pKl, g_Kl);
    cudaGetSymbolAddress((void**)&pVh, g_Vh);   cudaGetSymbolAddress((void**)&pVl, g_Vl);
    cudaGetSymbolAddress((void**)&pWqh, g_Wqh); cudaGetSymbolAddress((void**)&pWql, g_Wql);
    cudaGetSymbolAddress((void**)&pWkh, g_Wkh); cudaGetSymbolAddress((void**)&pWkl, g_Wkl);
    cudaGetSymbolAddress((void**)&pWvh, g_Wvh); cudaGetSymbolAddress((void**)&pWvl, g_Wvl);
    cudaGetSymbolAddress((void**)&pWoh, g_Woh); cudaGetSymbolAddress((void**)&pWol, g_Wol);

    cudaFuncSetAttribute(gemm3_kernel, cudaFuncAttributeMaxDynamicSharedMemorySize,
                         GEMM_SMEM_TOTAL);
    cudaFuncSetAttribute(attn_mma_kernel, cudaFuncAttributeMaxDynamicSharedMemorySize,
                         ATT_SMEM);

    // 1) split x
    {
        int n = BT_ * E_;
        split_kernel<<<(n + 255) / 256, 256>>>(x, pxh, pxl, n);
    }
    // 2-4) transpose+split Wq, Wk, Wv
    tsplit_kernel<<<dim3((H_ * D_) / 32, E_ / 32), dim3(32, 8)>>>(Wq, pWqh, pWql, E_, H_ * D_);
    tsplit_kernel<<<dim3((HKV_ * D_) / 32, E_ / 32), dim3(32, 8)>>>(Wk, pWkh, pWkl, E_, HKV_ * D_);
    tsplit_kernel<<<dim3((HKV_ * D_) / 32, E_ / 32), dim3(32, 8)>>>(Wv, pWvh, pWvl, E_, HKV_ * D_);

    // 5) Q projection  <- launch #5, ncu profiles this
    gemm3_kernel<<<dim3((H_ * D_) / 128, BT_ / 128), 256, GEMM_SMEM_TOTAL>>>(
        pQ, nullptr, nullptr, pxh, pxl, pWqh, pWql, BT_, H_ * D_, E_, 0);
    // 6) K projection
    gemm3_kernel<<<dim3((HKV_ * D_) / 128, BT_ / 128), 256, GEMM_SMEM_TOTAL>>>(
        pK, nullptr, nullptr, pxh, pxl, pWkh, pWkl, BT_, HKV_ * D_, E_, 0);
    // 7) V projection (bf16 hi/lo out, split fused)
    gemm3_kernel<<<dim3((HKV_ * D_) / 128, BT_ / 128), 256, GEMM_SMEM_TOTAL>>>(
        nullptr, pVh, pVl, pxh, pxl, pWvh, pWvl, BT_, HKV_ * D_, E_, 1);

    // 8) transpose+split Wo (overlaps tail; needed only by final gemm)
    tsplit_kernel<<<dim3(E_ / 32, E_ / 32), dim3(32, 8)>>>(Wo, pWoh, pWol, E_, E_);

    // 9-10) RoPE + split Q, K
    {
        int nq = B_ * T_ * H_ * 32;
        rope_split_kernel<<<(nq + 255) / 256, 256>>>(pQ, pQh, pQl, H_);
        int nk = B_ * T_ * HKV_ * 32;
        rope_split_kernel<<<(nk + 255) / 256, 256>>>(pK, pKh, pKl, HKV_);
    }

    // 11) attention
    attn_mma_kernel<<<dim3(T_ / 128, H_, B_), 256, ATT_SMEM>>>(
        pYh, pYl, pQh, pQl, pKh, pKl, pVh, pVl);

    // 12) output projection
    gemm3_kernel<<<dim3(E_ / 128, BT_ / 128), 256, GEMM_SMEM_TOTAL>>>(
        out, nullptr, nullptr, pYh, pYl, pWoh, pWol, BT_, E_, E_, 0);
}

// round 6
// speedup vs baseline: 1.0570x; 1.0570x over previous
#include <cuda_runtime.h>
#include <cuda_bf16.h>
#include <cstdint>
#include <math.h>

// Problem constants
#define B_  2
#define T_  2048
#define E_  2048
#define H_  32
#define HKV_ 8
#define D_  64
#define BT_ (B_*T_)  // 4096

// ---------------------------------------------------------------------------
// Scratch (static device globals — allocation-free rule)
// ---------------------------------------------------------------------------
__device__ float g_Q[BT_ * H_ * D_];
__device__ float g_K[BT_ * HKV_ * D_];

__device__ __nv_bfloat16 g_xh[BT_ * E_],  g_xl[BT_ * E_];
__device__ __nv_bfloat16 g_Yh[BT_ * E_],  g_Yl[BT_ * E_];
__device__ __nv_bfloat16 g_Qh[BT_ * H_ * D_],   g_Ql[BT_ * H_ * D_];
__device__ __nv_bfloat16 g_Kh[BT_ * HKV_ * D_], g_Kl[BT_ * HKV_ * D_];
__device__ __nv_bfloat16 g_Vh[BT_ * HKV_ * D_], g_Vl[BT_ * HKV_ * D_];
// Transposed weights [N, K] split hi/lo
__device__ __nv_bfloat16 g_Wqh[E_ * H_ * D_],   g_Wql[E_ * H_ * D_];
__device__ __nv_bfloat16 g_Wkh[E_ * HKV_ * D_], g_Wkl[E_ * HKV_ * D_];
__device__ __nv_bfloat16 g_Wvh[E_ * HKV_ * D_], g_Wvl[E_ * HKV_ * D_];
__device__ __nv_bfloat16 g_Woh[E_ * E_],        g_Wol[E_ * E_];

// ---------------------------------------------------------------------------
// PTX helpers (sm_80+ path: mma.sync / ldmatrix / cp.async)
// ---------------------------------------------------------------------------
__device__ __forceinline__ uint32_t smem_u32(const void* p) {
    uint32_t a;
    asm("{ .reg .u64 t; cvta.to.shared.u64 t, %1; cvt.u32.u64 %0, t; }" : "=r"(a) : "l"(p));
    return a;
}

__device__ __forceinline__ void ldmx4(uint32_t* r, uint32_t addr) {
    asm volatile("ldmatrix.sync.aligned.m8n8.x4.shared.b16 {%0,%1,%2,%3}, [%4];"
                 : "=r"(r[0]), "=r"(r[1]), "=r"(r[2]), "=r"(r[3]) : "r"(addr));
}
__device__ __forceinline__ void ldmx4t(uint32_t* r, uint32_t addr) {
    asm volatile("ldmatrix.sync.aligned.m8n8.x4.trans.shared.b16 {%0,%1,%2,%3}, [%4];"
                 : "=r"(r[0]), "=r"(r[1]), "=r"(r[2]), "=r"(r[3]) : "r"(addr));
}

__device__ __forceinline__ void mma_bf16(float* acc, const uint32_t* a, const uint32_t b0,
                                         const uint32_t b1) {
    asm volatile(
        "mma.sync.aligned.m16n8k16.row.col.f32.bf16.bf16.f32 "
        "{%0,%1,%2,%3}, {%4,%5,%6,%7}, {%8,%9}, {%0,%1,%2,%3};"
        : "+f"(acc[0]), "+f"(acc[1]), "+f"(acc[2]), "+f"(acc[3])
        : "r"(a[0]), "r"(a[1]), "r"(a[2]), "r"(a[3]), "r"(b0), "r"(b1));
}

__device__ __forceinline__ void cp_async16(uint32_t saddr, const void* gaddr) {
    asm volatile("cp.async.cg.shared.global [%0], [%1], 16;" :: "r"(saddr), "l"(gaddr));
}
#define CP_COMMIT() asm volatile("cp.async.commit_group;" ::: "memory")
#define CP_WAIT(n)  asm volatile("cp.async.wait_group %0;" :: "n"(n) : "memory")

__device__ __forceinline__ uint32_t pack_bf16x2(float lo, float hi) {
    __nv_bfloat162 v = __floats2bfloat162_rn(lo, hi);
    return *reinterpret_cast<uint32_t*>(&v);
}

// ---------------------------------------------------------------------------
// bf16x3 split-precision GEMM via mma.sync, 2-stage cp.async (2 CTAs/SM).
// C = Ah·Bh^T + Ah·Bl^T + Al·Bh^T; A[M,K], B[N,K] bf16 K-major.
// 128x128 CTA tile, BK=32, 256 threads. Term-major MMA passes.
// ---------------------------------------------------------------------------
#define ROWB   80
#define REGB   (128 * ROWB)          // 10240 per region
#define BUFB   (4 * REGB)            // 40960 per stage
#define GEMM_SMEM_TOTAL (2 * BUFB)   // 81920 -> 2 CTAs/SM

__device__ __forceinline__ void issue_buf(uint32_t sbuf,
                                          const __nv_bfloat16* ah, const __nv_bfloat16* al,
                                          const __nv_bfloat16* bh, const __nv_bfloat16* bl,
                                          int K, int tid) {
    const __nv_bfloat16* srcs[4] = {ah, al, bh, bl};
#pragma unroll
    for (int reg = 0; reg < 4; ++reg) {
        const __nv_bfloat16* s = srcs[reg];
        uint32_t sr = sbuf + reg * REGB;
#pragma unroll
        for (int j = 0; j < 2; ++j) {
            int c = tid + j * 256;
            int row = c >> 2, part = c & 3;
            cp_async16(sr + row * ROWB + part * 16, s + (size_t)row * K + part * 8);
        }
    }
}

__global__ __launch_bounds__(256)
void gemm3_kernel(float* __restrict__ C,
                  __nv_bfloat16* __restrict__ Ch, __nv_bfloat16* __restrict__ Cl,
                  const __nv_bfloat16* __restrict__ Ah, const __nv_bfloat16* __restrict__ Al,
                  const __nv_bfloat16* __restrict__ Bh, const __nv_bfloat16* __restrict__ Bl,
                  int M, int N, int K, int bf16out) {
    extern __shared__ char smem[];
    const uint32_t sbase = smem_u32(smem);
    const int tid = threadIdx.x;
    const int wid = tid >> 5, lane = tid & 31;
    const int warp_m = wid >> 2;          // 0..1 -> 64-row slab
    const int warp_n = wid & 3;           // 0..3 -> 32-col slab
    const int bm = blockIdx.y * 128, bn = blockIdx.x * 128;

    const __nv_bfloat16* pAh = Ah + (size_t)bm * K;
    const __nv_bfloat16* pAl = Al + (size_t)bm * K;
    const __nv_bfloat16* pBh = Bh + (size_t)bn * K;
    const __nv_bfloat16* pBl = Bl + (size_t)bn * K;

    float acc[4][4][4];
#pragma unroll
    for (int i = 0; i < 4; ++i)
#pragma unroll
        for (int j = 0; j < 4; ++j)
#pragma unroll
            for (int k = 0; k < 4; ++k) acc[i][j][k] = 0.0f;

    const int NIT = K / 32;

    const uint32_t a_row = warp_m * 64 + (lane & 15);
    const uint32_t a_coff = (lane >> 4) * 16;
    const uint32_t b_rowbase = warp_n * 32 + (lane & 15);
    const uint32_t b_coff = (lane >> 4) * 16;

    issue_buf(sbase, pAh, pAl, pBh, pBl, K, tid);
    CP_COMMIT();

    for (int it = 0; it < NIT; ++it) {
        const uint32_t sbuf = sbase + (it & 1) * BUFB;
        if (it + 1 < NIT) {
            issue_buf(sbase + ((it + 1) & 1) * BUFB,
                      pAh + (it + 1) * 32, pAl + (it + 1) * 32,
                      pBh + (it + 1) * 32, pBl + (it + 1) * 32, K, tid);
            CP_COMMIT();
            CP_WAIT(1);
        } else {
            CP_WAIT(0);
        }
        __syncthreads();

        const uint32_t sAh = sbuf, sAl = sbuf + REGB;
        const uint32_t sBh = sbuf + 2 * REGB, sBl = sbuf + 3 * REGB;

#pragma unroll
        for (int ks = 0; ks < 2; ++ks) {
            const uint32_t kb = ks * 32;
            uint32_t bhf[8], blf[8];
#pragma unroll
            for (int p = 0; p < 2; ++p) {
                uint32_t ba = (b_rowbase + p * 16) * ROWB + kb + b_coff;
                ldmx4(&bhf[p * 4], sBh + ba);
                ldmx4(&blf[p * 4], sBl + ba);
            }
            uint32_t ahf[4][4], alf[4][4];
#pragma unroll
            for (int mi = 0; mi < 4; ++mi) {
                uint32_t aa = (a_row + mi * 16) * ROWB + kb + a_coff;
                ldmx4(ahf[mi], sAh + aa);
                ldmx4(alf[mi], sAl + aa);
            }
            // term-major passes: every acc touched once per 16 MMAs
#pragma unroll
            for (int mi = 0; mi < 4; ++mi)
#pragma unroll
                for (int ni = 0; ni < 4; ++ni) {
                    const int p = ni >> 1, q = ni & 1;
                    mma_bf16(acc[mi][ni], ahf[mi], bhf[p * 4 + q], bhf[p * 4 + q + 2]);
                }
#pragma unroll
            for (int mi = 0; mi < 4; ++mi)
#pragma unroll
                for (int ni = 0; ni < 4; ++ni) {
                    const int p = ni >> 1, q = ni & 1;
                    mma_bf16(acc[mi][ni], ahf[mi], blf[p * 4 + q], blf[p * 4 + q + 2]);
                }
#pragma unroll
            for (int mi = 0; mi < 4; ++mi)
#pragma unroll
                for (int ni = 0; ni < 4; ++ni) {
                    const int p = ni >> 1, q = ni & 1;
                    mma_bf16(acc[mi][ni], alf[mi], bhf[p * 4 + q], bhf[p * 4 + q + 2]);
                }
        }
        __syncthreads();
    }

    const int rbase = bm + warp_m * 64 + (lane >> 2);
    const int cbase = bn + warp_n * 32 + (lane & 3) * 2;
    if (!bf16out) {
#pragma unroll
        for (int mi = 0; mi < 4; ++mi)
#pragma unroll
            for (int ni = 0; ni < 4; ++ni) {
                float* c0 = C + (size_t)(rbase + mi * 16) * N + cbase + ni * 8;
                float* c1 = C + (size_t)(rbase + mi * 16 + 8) * N + cbase + ni * 8;
                *(float2*)c0 = make_float2(acc[mi][ni][0], acc[mi][ni][1]);
                *(float2*)c1 = make_float2(acc[mi][ni][2], acc[mi][ni][3]);
            }
    } else {
#pragma unroll
        for (int mi = 0; mi < 4; ++mi)
#pragma unroll
            for (int ni = 0; ni < 4; ++ni) {
                float v0 = acc[mi][ni][0], v1 = acc[mi][ni][1];
                float v2 = acc[mi][ni][2], v3 = acc[mi][ni][3];
                uint32_t h01 = pack_bf16x2(v0, v1);
                uint32_t h23 = pack_bf16x2(v2, v3);
                __nv_bfloat162 hb01 = *reinterpret_cast<__nv_bfloat162*>(&h01);
                __nv_bfloat162 hb23 = *reinterpret_cast<__nv_bfloat162*>(&h23);
                uint32_t l01 = pack_bf16x2(v0 - __low2float(hb01), v1 - __high2float(hb01));
                uint32_t l23 = pack_bf16x2(v2 - __low2float(hb23), v3 - __high2float(hb23));
                size_t o0 = (size_t)(rbase + mi * 16) * N + cbase + ni * 8;
                size_t o1 = (size_t)(rbase + mi * 16 + 8) * N + cbase + ni * 8;
                *(uint32_t*)&Ch[o0] = h01;
                *(uint32_t*)&Ch[o1] = h23;
                *(uint32_t*)&Cl[o0] = l01;
                *(uint32_t*)&Cl[o1] = l23;
            }
    }
}

// ---------------------------------------------------------------------------
// fp32 -> bf16 hi/lo split
// ---------------------------------------------------------------------------
__global__ __launch_bounds__(256)
void split_kernel(const float* __restrict__ in, __nv_bfloat16* __restrict__ hi,
                  __nv_bfloat16* __restrict__ lo, int n) {
    int i = blockIdx.x * blockDim.x + threadIdx.x;
    if (i >= n) return;
    float v = in[i];
    __nv_bfloat16 h = __float2bfloat16(v);
    hi[i] = h;
    lo[i] = __float2bfloat16(v - __bfloat162float(h));
}

// ---------------------------------------------------------------------------
// Transpose + split: W[K,N] fp32 -> Th/Tl[N,K] bf16
// ---------------------------------------------------------------------------
__global__ __launch_bounds__(256)
void tsplit_kernel(const float* __restrict__ W, __nv_bfloat16* __restrict__ Th,
                   __nv_bfloat16* __restrict__ Tl, int K, int N) {
    __shared__ float t[32][33];
    const int tx = threadIdx.x, ty = threadIdx.y;
    const int n0 = blockIdx.x * 32, k0 = blockIdx.y * 32;
#pragma unroll
    for (int i = 0; i < 4; ++i)
        t[ty + i * 8][tx] = W[(size_t)(k0 + ty + i * 8) * N + n0 + tx];
    __syncthreads();
#pragma unroll
    for (int i = 0; i < 4; ++i) {
        float v = t[tx][ty + i * 8];
        __nv_bfloat16 h = __float2bfloat16(v);
        size_t o = (size_t)(n0 + ty + i * 8) * K + k0 + tx;
        Th[o] = h;
        Tl[o] = __float2bfloat16(v - __bfloat162float(h));
    }
}

// ---------------------------------------------------------------------------
// RoPE + hi/lo split (fused)
// ---------------------------------------------------------------------------
__global__ __launch_bounds__(256)
void rope_split_kernel(const float* __restrict__ buf, __nv_bfloat16* __restrict__ hi,
                       __nv_bfloat16* __restrict__ lo, int nh) {
    int idx = blockIdx.x * blockDim.x + threadIdx.x;
    int total = B_ * T_ * nh * 32;
    if (idx >= total) return;
    int i = idx & 31;
    int h = (idx >> 5) % nh;
    int t = (idx / (32 * nh)) % T_;
    int b = idx / (32 * nh * T_);

    float inv_freq = expf(-(float)i * (9.210340371976184f / 32.0f));
    float ang = (float)t * inv_freq;
    float c = cosf(ang), s = sinf(ang);

    size_t off = ((size_t)(b * T_ + t) * nh + h) * 64;
    float x1 = buf[off + i];
    float x2 = buf[off + 32 + i];
    float r1 = x1 * c - x2 * s;
    float r2 = x2 * c + x1 * s;
    __nv_bfloat16 h1 = __float2bfloat16(r1);
    __nv_bfloat16 h2 = __float2bfloat16(r2);
    hi[off + i] = h1;              lo[off + i] = __float2bfloat16(r1 - __bfloat162float(h1));
    hi[off + 32 + i] = h2;         lo[off + 32 + i] = __float2bfloat16(r2 - __bfloat162float(h2));
}

// ---------------------------------------------------------------------------
// FA2-style causal attention with mma.sync, bf16x3 split precision.
// ---------------------------------------------------------------------------
#define AROWB 144
#define KVREG (64 * AROWB)
#define KVBUF (4 * KVREG)
#define QREG  (128 * AROWB)
#define ATT_SMEM (2 * QREG + 2 * KVBUF)

__global__ __launch_bounds__(256)
void attn_mma_kernel(__nv_bfloat16* __restrict__ Yh, __nv_bfloat16* __restrict__ Yl,
                     const __nv_bfloat16* __restrict__ Qh, const __nv_bfloat16* __restrict__ Ql,
                     const __nv_bfloat16* __restrict__ Kh, const __nv_bfloat16* __restrict__ Kl,
                     const __nv_bfloat16* __restrict__ Vh, const __nv_bfloat16* __restrict__ Vl) {
    extern __shared__ char smem[];
    const uint32_t sbase = smem_u32(smem);
    const uint32_t sQh = sbase, sQl = sbase + QREG;
    const uint32_t sKV = sbase + 2 * QREG;

    const int tid = threadIdx.x;
    const int wid = tid >> 5, lane = tid & 31;
    const int qb = blockIdx.x;
    const int h  = blockIdx.y;
    const int b  = blockIdx.z;
    const int kh = h >> 2;
    const int bT0 = b * T_;

    const int row0 = qb * 128 + wid * 16 + (lane >> 2);
    const int row1 = row0 + 8;
    const int rowmin_w = qb * 128 + wid * 16;
    const int rowmax_w = rowmin_w + 15;

    {
        const __nv_bfloat16* srcs[2] = {Qh, Ql};
#pragma unroll
        for (int j = 0; j < 8; ++j) {
            int c = tid + j * 256;
            int reg = c >> 10, idx = c & 1023;
            int row = idx >> 3, part = idx & 7;
            uint32_t dst = (reg ? sQl : sQh) + row * AROWB + part * 16;
            cp_async16(dst, srcs[reg] + ((size_t)(bT0 + qb * 128 + row) * H_ + h) * 64 + part * 8);
        }
    }
    const __nv_bfloat16* kvsrc[4] = {Kh, Kl, Vh, Vl};
    {
#pragma unroll
        for (int j = 0; j < 8; ++j) {
            int c = tid + j * 256;
            int reg = c >> 9, idx = c & 511;
            int row = idx >> 3, part = idx & 7;
            uint32_t dst = sKV + reg * KVREG + row * AROWB + part * 16;
            cp_async16(dst, kvsrc[reg] + ((size_t)(bT0 + row) * HKV_ + kh) * 64 + part * 8);
        }
    }
    CP_COMMIT();
    CP_WAIT(0);
    __syncthreads();

    uint32_t qfh[4][4], qfl[4][4];
#pragma unroll
    for (int ks = 0; ks < 4; ++ks) {
        uint32_t qa = (wid * 16 + (lane & 15)) * AROWB + ks * 32 + (lane >> 4) * 16;
        ldmx4(qfh[ks], sQh + qa);
        ldmx4(qfl[ks], sQl + qa);
    }

    float o[8][4];
#pragma unroll
    for (int j = 0; j < 8; ++j)
#pragma unroll
        for (int k = 0; k < 4; ++k) o[j][k] = 0.0f;
    float m0 = -1e30f, m1 = -1e30f, l0 = 0.0f, l1 = 0.0f;
    const float scale = 0.125f;

    const int NT = 2 * qb + 2;
    for (int it = 0; it < NT; ++it) {
        if (it + 1 < NT) {
            uint32_t sb = sKV + ((it + 1) & 1) * KVBUF;
#pragma unroll
            for (int j = 0; j < 8; ++j) {
                int c = tid + j * 256;
                int reg = c >> 9, idx = c & 511;
                int row = idx >> 3, part = idx & 7;
                cp_async16(sb + reg * KVREG + row * AROWB + part * 16,
                           kvsrc[reg] + ((size_t)(bT0 + (it + 1) * 64 + row) * HKV_ + kh) * 64 + part * 8);
            }
            CP_COMMIT();
            CP_WAIT(1);
        } else {
            CP_WAIT(0);
        }
        __syncthreads();

        const int kt = it;
        if (kt * 64 <= rowmax_w) {
            const uint32_t sb = sKV + (it & 1) * KVBUF;
            const uint32_t sKh = sb, sKl = sb + KVREG;
            const uint32_t sVh = sb + 2 * KVREG, sVl = sb + 3 * KVREG;

            float s[8][4];
#pragma unroll
            for (int j = 0; j < 8; ++j)
#pragma unroll
                for (int k = 0; k < 4; ++k) s[j][k] = 0.0f;

#pragma unroll
            for (int ks = 0; ks < 4; ++ks) {
#pragma unroll
                for (int pg = 0; pg < 2; ++pg) {
                    uint32_t kfh[2][4], kfl[2][4];
#pragma unroll
                    for (int pp = 0; pp < 2; ++pp) {
                        uint32_t ka = ((2 * pg + pp) * 16 + (lane & 15)) * AROWB + ks * 32 + (lane >> 4) * 16;
                        ldmx4(kfh[pp], sKh + ka);
                        ldmx4(kfl[pp], sKl + ka);
                    }
#pragma unroll
                    for (int pp = 0; pp < 2; ++pp)
#pragma unroll
                        for (int q = 0; q < 2; ++q)
                            mma_bf16(s[(2 * pg + pp) * 2 + q], qfh[ks], kfh[pp][q], kfh[pp][q + 2]);
#pragma unroll
                    for (int pp = 0; pp < 2; ++pp)
#pragma unroll
                        for (int q = 0; q < 2; ++q)
                            mma_bf16(s[(2 * pg + pp) * 2 + q], qfh[ks], kfl[pp][q], kfl[pp][q + 2]);
#pragma unroll
                    for (int pp = 0; pp < 2; ++pp)
#pragma unroll
                        for (int q = 0; q < 2; ++q)
                            mma_bf16(s[(2 * pg + pp) * 2 + q], qfl[ks], kfh[pp][q], kfh[pp][q + 2]);
                }
            }

            const bool needs_mask = (kt * 64 + 63) > rowmin_w;
#pragma unroll
            for (int j = 0; j < 8; ++j) {
#pragma unroll
                for (int k = 0; k < 4; ++k) s[j][k] *= scale;
                if (needs_mask) {
                    int colb = kt * 64 + j * 8 + 2 * (lane & 3);
                    if (colb > row0)     s[j][0] = -1e30f;
                    if (colb + 1 > row0) s[j][1] = -1e30f;
                    if (colb > row1)     s[j][2] = -1e30f;
                    if (colb + 1 > row1) s[j][3] = -1e30f;
                }
            }

            float mx0 = -1e30f, mx1 = -1e30f;
#pragma unroll
            for (int j = 0; j < 8; ++j) {
                mx0 = fmaxf(mx0, fmaxf(s[j][0], s[j][1]));
                mx1 = fmaxf(mx1, fmaxf(s[j][2], s[j][3]));
            }
            mx0 = fmaxf(mx0, __shfl_xor_sync(0xFFFFFFFF, mx0, 1));
            mx0 = fmaxf(mx0, __shfl_xor_sync(0xFFFFFFFF, mx0, 2));
            mx1 = fmaxf(mx1, __shfl_xor_sync(0xFFFFFFFF, mx1, 1));
            mx1 = fmaxf(mx1, __shfl_xor_sync(0xFFFFFFFF, mx1, 2));

            float mn0 = fmaxf(m0, mx0), mn1 = fmaxf(m1, mx1);
            float c0 = __expf(m0 - mn0), c1 = __expf(m1 - mn1);
            m0 = mn0; m1 = mn1;
            l0 *= c0; l1 *= c1;
#pragma unroll
            for (int j = 0; j < 8; ++j) {
                o[j][0] *= c0; o[j][1] *= c0; o[j][2] *= c1; o[j][3] *= c1;
            }
#pragma unroll
            for (int j = 0; j < 8; ++j) {
                s[j][0] = __expf(s[j][0] - mn0);
                s[j][1] = __expf(s[j][1] - mn0);
                s[j][2] = __expf(s[j][2] - mn1);
                s[j][3] = __expf(s[j][3] - mn1);
                l0 += s[j][0] + s[j][1];
                l1 += s[j][2] + s[j][3];
            }

#pragma unroll
            for (int ks = 0; ks < 4; ++ks) {
                uint32_t pah[4], pal[4];
                {
                    float p00 = s[2 * ks][0], p01 = s[2 * ks][1];
                    float p02 = s[2 * ks][2], p03 = s[2 * ks][3];
                    float p10 = s[2 * ks + 1][0], p11 = s[2 * ks + 1][1];
                    float p12 = s[2 * ks + 1][2], p13 = s[2 * ks + 1][3];
                    pah[0] = pack_bf16x2(p00, p01);
                    pah[1] = pack_bf16x2(p02, p03);
                    pah[2] = pack_bf16x2(p10, p11);
                    pah[3] = pack_bf16x2(p12, p13);
                    __nv_bfloat162 h0 = *reinterpret_cast<__nv_bfloat162*>(&pah[0]);
                    __nv_bfloat162 h1 = *reinterpret_cast<__nv_bfloat162*>(&pah[1]);
                    __nv_bfloat162 h2 = *reinterpret_cast<__nv_bfloat162*>(&pah[2]);
                    __nv_bfloat162 h3 = *reinterpret_cast<__nv_bfloat162*>(&pah[3]);
                    pal[0] = pack_bf16x2(p00 - __low2float(h0), p01 - __high2float(h0));
                    pal[1] = pack_bf16x2(p02 - __low2float(h1), p03 - __high2float(h1));
                    pal[2] = pack_bf16x2(p10 - __low2float(h2), p11 - __high2float(h2));
                    pal[3] = pack_bf16x2(p12 - __low2float(h3), p13 - __high2float(h3));
                }
#pragma unroll
                for (int pg = 0; pg < 2; ++pg) {
                    uint32_t vfh[2][4], vfl[2][4];
#pragma unroll
                    for (int pp = 0; pp < 2; ++pp) {
                        uint32_t va = (ks * 16 + (lane & 15)) * AROWB + (2 * pg + pp) * 32 + (lane >> 4) * 16;
                        ldmx4t(vfh[pp], sVh + va);
                        ldmx4t(vfl[pp], sVl + va);
                    }
#pragma unroll
                    for (int pp = 0; pp < 2; ++pp)
#pragma unroll
                        for (int q = 0; q < 2; ++q)
                            mma_bf16(o[(2 * pg + pp) * 2 + q], pah, vfh[pp][2 * q], vfh[pp][2 * q + 1]);
#pragma unroll
                    for (int pp = 0; pp < 2; ++pp)
#pragma unroll
                        for (int q = 0; q < 2; ++q)
                            mma_bf16(o[(2 * pg + pp) * 2 + q], pal, vfh[pp][2 * q], vfh[pp][2 * q + 1]);
#pragma unroll
                    for (int pp = 0; pp < 2; ++pp)
#pragma unroll
                        for (int q = 0; q < 2; ++q)
                            mma_bf16(o[(2 * pg + pp) * 2 + q], pah, vfl[pp][2 * q], vfl[pp][2 * q + 1]);
                }
            }
        }
        __syncthreads();
    }

    l0 += __shfl_xor_sync(0xFFFFFFFF, l0, 1);
    l0 += __shfl_xor_sync(0xFFFFFFFF, l0, 2);
    l1 += __shfl_xor_sync(0xFFFFFFFF, l1, 1);
    l1 += __shfl_xor_sync(0xFFFFFFFF, l1, 2);
    float inv0 = 1.0f / l0, inv1 = 1.0f / l1;

#pragma unroll
    for (int j = 0; j < 8; ++j) {
        int col = j * 8 + 2 * (lane & 3);
        float y0 = o[j][0] * inv0, y1 = o[j][1] * inv0;
        float y2 = o[j][2] * inv1, y3 = o[j][3] * inv1;
        size_t a0 = ((size_t)(bT0 + row0) * H_ + h) * 64 + col;
        size_t a1 = ((size_t)(bT0 + row1) * H_ + h) * 64 + col;
        uint32_t h01 = pack_bf16x2(y0, y1);
        uint32_t h23 = pack_bf16x2(y2, y3);
        __nv_bfloat162 hb01 = *reinterpret_cast<__nv_bfloat162*>(&h01);
        __nv_bfloat162 hb23 = *reinterpret_cast<__nv_bfloat162*>(&h23);
        uint32_t l01 = pack_bf16x2(y0 - __low2float(hb01), y1 - __high2float(hb01));
        uint32_t l23 = pack_bf16x2(y2 - __low2float(hb23), y3 - __high2float(hb23));
        *(uint32_t*)&Yh[a0] = h01;
        *(uint32_t*)&Yh[a1] = h23;
        *(uint32_t*)&Yl[a0] = l01;
        *(uint32_t*)&Yl[a1] = l23;
    }
}

// ---------------------------------------------------------------------------
// kernel_launch — ordered so gemm3(Q) is our 4th launch (ncu captures #4)
// ---------------------------------------------------------------------------
extern "C" void kernel_launch(void* const* d_in, const int* in_sizes, int n_in,
                              void* d_out, int out_size) {
    const float* x  = (const float*)d_in[0];
    const float* Wq = (const float*)d_in[1];
    const float* Wk = (const float*)d_in[2];
    const float* Wv = (const float*)d_in[3];
    const float* Wo = (const float*)d_in[4];
    float* out = (float*)d_out;

    float *pQ, *pK;
    cudaGetSymbolAddress((void**)&pQ, g_Q);
    cudaGetSymbolAddress((void**)&pK, g_K);
    __nv_bfloat16 *pxh, *pxl, *pYh, *pYl;
    __nv_bfloat16 *pQh, *pQl, *pKh, *pKl, *pVh, *pVl;
    __nv_bfloat16 *pWqh, *pWql, *pWkh, *pWkl, *pWvh, *pWvl, *pWoh, *pWol;
    cudaGetSymbolAddress((void**)&pxh, g_xh);   cudaGetSymbolAddress((void**)&pxl, g_xl);
    cudaGetSymbolAddress((void**)&pYh, g_Yh);   cudaGetSymbolAddress((void**)&pYl, g_Yl);
    cudaGetSymbolAddress((void**)&pQh, g_Qh);   cudaGetSymbolAddress((void**)&pQl, g_Ql);
    cudaGetSymbolAddress((void**)&pKh, g_Kh);   cudaGetSymbolAddress((void**)&pKl, g_Kl);
    cudaGetSymbolAddress((void**)&pVh, g_Vh);   cudaGetSymbolAddress((void**)&pVl, g_Vl);
    cudaGetSymbolAddress((void**)&pWqh, g_Wqh); cudaGetSymbolAddress((void**)&pWql, g_Wql);
    cudaGetSymbolAddress((void**)&pWkh, g_Wkh); cudaGetSymbolAddress((void**)&pWkl, g_Wkl);
    cudaGetSymbolAddress((void**)&pWvh, g_Wvh); cudaGetSymbolAddress((void**)&pWvl, g_Wvl);
    cudaGetSymbolAddress((void**)&pWoh, g_Woh); cudaGetSymbolAddress((void**)&pWol, g_Wol);

    cudaFuncSetAttribute(gemm3_kernel, cudaFuncAttributeMaxDynamicSharedMemorySize,
                         GEMM_SMEM_TOTAL);
    cudaFuncSetAttribute(attn_mma_kernel, cudaFuncAttributeMaxDynamicSharedMemorySize,
                         ATT_SMEM);

    // #1 split x
    {
        int n = BT_ * E_;
        split_kernel<<<(n + 255) / 256, 256>>>(x, pxh, pxl, n);
    }
    // #2, #3
    tsplit_kernel<<<dim3((H_ * D_) / 32, E_ / 32), dim3(32, 8)>>>(Wq, pWqh, pWql, E_, H_ * D_);
    tsplit_kernel<<<dim3((HKV_ * D_) / 32, E_ / 32), dim3(32, 8)>>>(Wk, pWkh, pWkl, E_, HKV_ * D_);

    // #4 Q projection  <- ncu capture target
    gemm3_kernel<<<dim3((H_ * D_) / 128, BT_ / 128), 256, GEMM_SMEM_TOTAL>>>(
        pQ, nullptr, nullptr, pxh, pxl, pWqh, pWql, BT_, H_ * D_, E_, 0);

    // #5
    tsplit_kernel<<<dim3((HKV_ * D_) / 32, E_ / 32), dim3(32, 8)>>>(Wv, pWvh, pWvl, E_, HKV_ * D_);
    // #6 K projection
    gemm3_kernel<<<dim3((HKV_ * D_) / 128, BT_ / 128), 256, GEMM_SMEM_TOTAL>>>(
        pK, nullptr, nullptr, pxh, pxl, pWkh, pWkl, BT_, HKV_ * D_, E_, 0);
    // #7 V projection (bf16 hi/lo out)
    gemm3_kernel<<<dim3((HKV_ * D_) / 128, BT_ / 128), 256, GEMM_SMEM_TOTAL>>>(
        nullptr, pVh, pVl, pxh, pxl, pWvh, pWvl, BT_, HKV_ * D_, E_, 1);

    // #8
    tsplit_kernel<<<dim3(E_ / 32, E_ / 32), dim3(32, 8)>>>(Wo, pWoh, pWol, E_, E_);

    // #9, #10 RoPE + split Q, K
    {
        int nq = B_ * T_ * H_ * 32;
        rope_split_kernel<<<(nq + 255) / 256, 256>>>(pQ, pQh, pQl, H_);
        int nk = B_ * T_ * HKV_ * 32;
        rope_split_kernel<<<(nk + 255) / 256, 256>>>(pK, pKh, pKl, HKV_);
    }

    // #11 attention
    attn_mma_kernel<<<dim3(T_ / 128, H_, B_), 256, ATT_SMEM>>>(
        pYh, pYl, pQh, pQl, pKh, pKl, pVh, pVl);

    // #12 output projection
    gemm3_kernel<<<dim3(E_ / 128, BT_ / 128), 256, GEMM_SMEM_TOTAL>>>(
        out, nullptr, nullptr, pYh, pYl, pWoh, pWol, BT_, E_, E_, 0);
}

// round 7
// speedup vs baseline: 1.3211x; 1.2498x over previous
#include <cuda_runtime.h>
#include <cuda_bf16.h>
#include <cuda_fp16.h>
#include <cstdint>
#include <math.h>

// Problem constants
#define B_  2
#define T_  2048
#define E_  2048
#define H_  32
#define HKV_ 8
#define D_  64
#define BT_ (B_*T_)  // 4096
#define NQKV 3072    // 2048 Q + 512 K + 512 V
#define NQK  2560    // fp32 part of fused output (Q+K)

// ---------------------------------------------------------------------------
// Scratch (static device globals — allocation-free rule)
// ---------------------------------------------------------------------------
__device__ float g_QKV[BT_ * NQK];                 // Q (cols 0-2047) + K (2048-2559), pre-rope fp32
__device__ __half g_Qf[BT_ * H_ * D_];
__device__ __half g_Kf[BT_ * HKV_ * D_];
__device__ __half g_Vf[BT_ * HKV_ * D_];
__device__ __nv_bfloat16 g_xh[BT_ * E_],  g_xl[BT_ * E_];
__device__ __nv_bfloat16 g_Yh[BT_ * E_],  g_Yl[BT_ * E_];
__device__ __nv_bfloat16 g_Wch[NQKV * E_], g_Wcl[NQKV * E_];  // concat Wq|Wk|Wv, [N,K]
__device__ __nv_bfloat16 g_Woh[E_ * E_],   g_Wol[E_ * E_];

// ---------------------------------------------------------------------------
// PTX helpers
// ---------------------------------------------------------------------------
__device__ __forceinline__ uint32_t smem_u32(const void* p) {
    uint32_t a;
    asm("{ .reg .u64 t; cvta.to.shared.u64 t, %1; cvt.u32.u64 %0, t; }" : "=r"(a) : "l"(p));
    return a;
}
__device__ __forceinline__ void ldmx4(uint32_t* r, uint32_t addr) {
    asm volatile("ldmatrix.sync.aligned.m8n8.x4.shared.b16 {%0,%1,%2,%3}, [%4];"
                 : "=r"(r[0]), "=r"(r[1]), "=r"(r[2]), "=r"(r[3]) : "r"(addr));
}
__device__ __forceinline__ void ldmx4t(uint32_t* r, uint32_t addr) {
    asm volatile("ldmatrix.sync.aligned.m8n8.x4.trans.shared.b16 {%0,%1,%2,%3}, [%4];"
                 : "=r"(r[0]), "=r"(r[1]), "=r"(r[2]), "=r"(r[3]) : "r"(addr));
}
__device__ __forceinline__ void mma_bf16(float* acc, const uint32_t* a, const uint32_t b0,
                                         const uint32_t b1) {
    asm volatile(
        "mma.sync.aligned.m16n8k16.row.col.f32.bf16.bf16.f32 "
        "{%0,%1,%2,%3}, {%4,%5,%6,%7}, {%8,%9}, {%0,%1,%2,%3};"
        : "+f"(acc[0]), "+f"(acc[1]), "+f"(acc[2]), "+f"(acc[3])
        : "r"(a[0]), "r"(a[1]), "r"(a[2]), "r"(a[3]), "r"(b0), "r"(b1));
}
__device__ __forceinline__ void mma_f16(float* acc, const uint32_t* a, const uint32_t b0,
                                        const uint32_t b1) {
    asm volatile(
        "mma.sync.aligned.m16n8k16.row.col.f32.f16.f16.f32 "
        "{%0,%1,%2,%3}, {%4,%5,%6,%7}, {%8,%9}, {%0,%1,%2,%3};"
        : "+f"(acc[0]), "+f"(acc[1]), "+f"(acc[2]), "+f"(acc[3])
        : "r"(a[0]), "r"(a[1]), "r"(a[2]), "r"(a[3]), "r"(b0), "r"(b1));
}
__device__ __forceinline__ void cp_async16(uint32_t saddr, const void* gaddr) {
    asm volatile("cp.async.cg.shared.global [%0], [%1], 16;" :: "r"(saddr), "l"(gaddr));
}
#define CP_COMMIT() asm volatile("cp.async.commit_group;" ::: "memory")
#define CP_WAIT(n)  asm volatile("cp.async.wait_group %0;" :: "n"(n) : "memory")

__device__ __forceinline__ uint32_t pack_bf16x2(float lo, float hi) {
    __nv_bfloat162 v = __floats2bfloat162_rn(lo, hi);
    return *reinterpret_cast<uint32_t*>(&v);
}
__device__ __forceinline__ uint32_t pack_h2(float lo, float hi) {
    __half2 v = __floats2half2_rn(lo, hi);
    return *reinterpret_cast<uint32_t*>(&v);
}

// ---------------------------------------------------------------------------
// bf16x3 split-precision GEMM via mma.sync, 2-stage cp.async.
// mode 0: C fp32 [M,N].   mode 1: fused QKV epilogue (Q/K -> g_QKV fp32
// stride NQK; V -> Cv fp16 stride 512).
// ---------------------------------------------------------------------------
#define ROWB   80
#define REGB   (128 * ROWB)
#define BUFB   (4 * REGB)
#define GEMM_SMEM_TOTAL (2 * BUFB)   // 81920 -> 2 CTAs/SM

__device__ __forceinline__ void issue_buf(uint32_t sbuf,
                                          const __nv_bfloat16* ah, const __nv_bfloat16* al,
                                          const __nv_bfloat16* bh, const __nv_bfloat16* bl,
                                          int K, int tid) {
    const __nv_bfloat16* srcs[4] = {ah, al, bh, bl};
#pragma unroll
    for (int reg = 0; reg < 4; ++reg) {
        const __nv_bfloat16* s = srcs[reg];
        uint32_t sr = sbuf + reg * REGB;
#pragma unroll
        for (int j = 0; j < 2; ++j) {
            int c = tid + j * 256;
            int row = c >> 2, part = c & 3;
            cp_async16(sr + row * ROWB + part * 16, s + (size_t)row * K + part * 8);
        }
    }
}

__global__ __launch_bounds__(256)
void gemm3_kernel(float* __restrict__ C, __half* __restrict__ Cv,
                  const __nv_bfloat16* __restrict__ Ah, const __nv_bfloat16* __restrict__ Al,
                  const __nv_bfloat16* __restrict__ Bh, const __nv_bfloat16* __restrict__ Bl,
                  int M, int N, int K, int mode) {
    extern __shared__ char smem[];
    const uint32_t sbase = smem_u32(smem);
    const int tid = threadIdx.x;
    const int wid = tid >> 5, lane = tid & 31;
    const int warp_m = wid >> 2;
    const int warp_n = wid & 3;
    const int bm = blockIdx.y * 128, bn = blockIdx.x * 128;

    const __nv_bfloat16* pAh = Ah + (size_t)bm * K;
    const __nv_bfloat16* pAl = Al + (size_t)bm * K;
    const __nv_bfloat16* pBh = Bh + (size_t)bn * K;
    const __nv_bfloat16* pBl = Bl + (size_t)bn * K;

    float acc[4][4][4];
#pragma unroll
    for (int i = 0; i < 4; ++i)
#pragma unroll
        for (int j = 0; j < 4; ++j)
#pragma unroll
            for (int k = 0; k < 4; ++k) acc[i][j][k] = 0.0f;

    const int NIT = K / 32;

    const uint32_t a_row = warp_m * 64 + (lane & 15);
    const uint32_t a_coff = (lane >> 4) * 16;
    const uint32_t b_rowbase = warp_n * 32 + (lane & 15);
    const uint32_t b_coff = (lane >> 4) * 16;

    issue_buf(sbase, pAh, pAl, pBh, pBl, K, tid);
    CP_COMMIT();

    for (int it = 0; it < NIT; ++it) {
        const uint32_t sbuf = sbase + (it & 1) * BUFB;
        if (it + 1 < NIT) {
            issue_buf(sbase + ((it + 1) & 1) * BUFB,
                      pAh + (it + 1) * 32, pAl + (it + 1) * 32,
                      pBh + (it + 1) * 32, pBl + (it + 1) * 32, K, tid);
            CP_COMMIT();
            CP_WAIT(1);
        } else {
            CP_WAIT(0);
        }
        __syncthreads();

        const uint32_t sAh = sbuf, sAl = sbuf + REGB;
        const uint32_t sBh = sbuf + 2 * REGB, sBl = sbuf + 3 * REGB;

#pragma unroll
        for (int ks = 0; ks < 2; ++ks) {
            const uint32_t kb = ks * 32;
            uint32_t bhf[8], blf[8];
#pragma unroll
            for (int p = 0; p < 2; ++p) {
                uint32_t ba = (b_rowbase + p * 16) * ROWB + kb + b_coff;
                ldmx4(&bhf[p * 4], sBh + ba);
                ldmx4(&blf[p * 4], sBl + ba);
            }
            uint32_t ahf[4][4], alf[4][4];
#pragma unroll
            for (int mi = 0; mi < 4; ++mi) {
                uint32_t aa = (a_row + mi * 16) * ROWB + kb + a_coff;
                ldmx4(ahf[mi], sAh + aa);
                ldmx4(alf[mi], sAl + aa);
            }
#pragma unroll
            for (int mi = 0; mi < 4; ++mi)
#pragma unroll
                for (int ni = 0; ni < 4; ++ni) {
                    const int p = ni >> 1, q = ni & 1;
                    mma_bf16(acc[mi][ni], ahf[mi], bhf[p * 4 + q], bhf[p * 4 + q + 2]);
                }
#pragma unroll
            for (int mi = 0; mi < 4; ++mi)
#pragma unroll
                for (int ni = 0; ni < 4; ++ni) {
                    const int p = ni >> 1, q = ni & 1;
                    mma_bf16(acc[mi][ni], ahf[mi], blf[p * 4 + q], blf[p * 4 + q + 2]);
                }
#pragma unroll
            for (int mi = 0; mi < 4; ++mi)
#pragma unroll
                for (int ni = 0; ni < 4; ++ni) {
                    const int p = ni >> 1, q = ni & 1;
                    mma_bf16(acc[mi][ni], alf[mi], bhf[p * 4 + q], bhf[p * 4 + q + 2]);
                }
        }
        __syncthreads();
    }

    const int rbase = bm + warp_m * 64 + (lane >> 2);
    const int cbase = bn + warp_n * 32 + (lane & 3) * 2;

    if (mode == 0) {
#pragma unroll
        for (int mi = 0; mi < 4; ++mi)
#pragma unroll
            for (int ni = 0; ni < 4; ++ni) {
                float* c0 = C + (size_t)(rbase + mi * 16) * N + cbase + ni * 8;
                float* c1 = C + (size_t)(rbase + mi * 16 + 8) * N + cbase + ni * 8;
                *(float2*)c0 = make_float2(acc[mi][ni][0], acc[mi][ni][1]);
                *(float2*)c1 = make_float2(acc[mi][ni][2], acc[mi][ni][3]);
            }
    } else if (bn < NQK) {
        // Q/K columns -> fp32, stride NQK
#pragma unroll
        for (int mi = 0; mi < 4; ++mi)
#pragma unroll
            for (int ni = 0; ni < 4; ++ni) {
                float* c0 = C + (size_t)(rbase + mi * 16) * NQK + cbase + ni * 8;
                float* c1 = C + (size_t)(rbase + mi * 16 + 8) * NQK + cbase + ni * 8;
                *(float2*)c0 = make_float2(acc[mi][ni][0], acc[mi][ni][1]);
                *(float2*)c1 = make_float2(acc[mi][ni][2], acc[mi][ni][3]);
            }
    } else {
        // V columns -> fp16, stride 512
        const int cb = cbase - NQK;
#pragma unroll
        for (int mi = 0; mi < 4; ++mi)
#pragma unroll
            for (int ni = 0; ni < 4; ++ni) {
                uint32_t h01 = pack_h2(acc[mi][ni][0], acc[mi][ni][1]);
                uint32_t h23 = pack_h2(acc[mi][ni][2], acc[mi][ni][3]);
                *(uint32_t*)&Cv[(size_t)(rbase + mi * 16) * 512 + cb + ni * 8] = h01;
                *(uint32_t*)&Cv[(size_t)(rbase + mi * 16 + 8) * 512 + cb + ni * 8] = h23;
            }
    }
}

// ---------------------------------------------------------------------------
// fp32 -> bf16 hi/lo split
// ---------------------------------------------------------------------------
__global__ __launch_bounds__(256)
void split_kernel(const float* __restrict__ in, __nv_bfloat16* __restrict__ hi,
                  __nv_bfloat16* __restrict__ lo, int n) {
    int i = blockIdx.x * blockDim.x + threadIdx.x;
    if (i >= n) return;
    float v = in[i];
    __nv_bfloat16 h = __float2bfloat16(v);
    hi[i] = h;
    lo[i] = __float2bfloat16(v - __bfloat162float(h));
}

// ---------------------------------------------------------------------------
// Transpose + split: W[K,N] fp32 -> Th/Tl[N,K] bf16 (single weight)
// ---------------------------------------------------------------------------
__global__ __launch_bounds__(256)
void tsplit_kernel(const float* __restrict__ W, __nv_bfloat16* __restrict__ Th,
                   __nv_bfloat16* __restrict__ Tl, int K, int N) {
    __shared__ float t[32][33];
    const int tx = threadIdx.x, ty = threadIdx.y;
    const int n0 = blockIdx.x * 32, k0 = blockIdx.y * 32;
#pragma unroll
    for (int i = 0; i < 4; ++i)
        t[ty + i * 8][tx] = W[(size_t)(k0 + ty + i * 8) * N + n0 + tx];
    __syncthreads();
#pragma unroll
    for (int i = 0; i < 4; ++i) {
        float v = t[tx][ty + i * 8];
        __nv_bfloat16 h = __float2bfloat16(v);
        size_t o = (size_t)(n0 + ty + i * 8) * K + k0 + tx;
        Th[o] = h;
        Tl[o] = __float2bfloat16(v - __bfloat162float(h));
    }
}

// ---------------------------------------------------------------------------
// Fused transpose+split of Wq|Wk|Wv into concat buffer (z selects matrix)
// ---------------------------------------------------------------------------
__global__ __launch_bounds__(256)
void tsplit3_kernel(const float* __restrict__ Wq, const float* __restrict__ Wk,
                    const float* __restrict__ Wv,
                    __nv_bfloat16* __restrict__ Th, __nv_bfloat16* __restrict__ Tl) {
    __shared__ float t[32][33];
    const int z = blockIdx.z;
    const float* W = (z == 0) ? Wq : (z == 1) ? Wk : Wv;
    const int N = (z == 0) ? (H_ * D_) : (HKV_ * D_);
    const int nofs = (z == 0) ? 0 : (z == 1) ? 2048 : 2560;
    const int n0 = blockIdx.x * 32, k0 = blockIdx.y * 32;
    if (n0 >= N) return;
    const int tx = threadIdx.x, ty = threadIdx.y;
#pragma unroll
    for (int i = 0; i < 4; ++i)
        t[ty + i * 8][tx] = W[(size_t)(k0 + ty + i * 8) * N + n0 + tx];
    __syncthreads();
#pragma unroll
    for (int i = 0; i < 4; ++i) {
        float v = t[tx][ty + i * 8];
        __nv_bfloat16 h = __float2bfloat16(v);
        size_t o = (size_t)(nofs + n0 + ty + i * 8) * E_ + k0 + tx;
        Th[o] = h;
        Tl[o] = __float2bfloat16(v - __bfloat162float(h));
    }
}

// ---------------------------------------------------------------------------
// RoPE from fused fp32 buffer -> fp16
// ---------------------------------------------------------------------------
__global__ __launch_bounds__(256)
void rope_f16_kernel(const float* __restrict__ qkv, __half* __restrict__ out,
                     int nh, int colbase) {
    int idx = blockIdx.x * blockDim.x + threadIdx.x;
    int total = B_ * T_ * nh * 32;
    if (idx >= total) return;
    int i = idx & 31;
    int h = (idx >> 5) % nh;
    int t = (idx / (32 * nh)) % T_;
    int b = idx / (32 * nh * T_);

    float inv_freq = expf(-(float)i * (9.210340371976184f / 32.0f));
    float ang = (float)t * inv_freq;
    float c = cosf(ang), s = sinf(ang);

    size_t row = (size_t)(b * T_ + t);
    const float* src = qkv + row * NQK + colbase + h * 64;
    float x1 = src[i];
    float x2 = src[32 + i];
    __half* dst = out + row * nh * 64 + h * 64;
    dst[i]      = __float2half_rn(x1 * c - x2 * s);
    dst[32 + i] = __float2half_rn(x2 * c + x1 * s);
}

// ---------------------------------------------------------------------------
// FA2-style causal attention, fp16 single-term mma.sync.
// Grid (T/128, H, B), 256 threads (8 warps x 16 q-rows). Writes Yh/Yl bf16.
// ---------------------------------------------------------------------------
#define AROWB 144
#define KVREG (64 * AROWB)              // 9216
#define KVBUF (2 * KVREG)               // K,V = 18432
#define QREG  (128 * AROWB)             // 18432
#define ATT_SMEM (QREG + 2 * KVBUF)     // 55296

__global__ __launch_bounds__(256)
void attn_f16_kernel(__nv_bfloat16* __restrict__ Yh, __nv_bfloat16* __restrict__ Yl,
                     const __half* __restrict__ Qf, const __half* __restrict__ Kf,
                     const __half* __restrict__ Vf) {
    extern __shared__ char smem[];
    const uint32_t sbase = smem_u32(smem);
    const uint32_t sQ = sbase;
    const uint32_t sKV = sbase + QREG;

    const int tid = threadIdx.x;
    const int wid = tid >> 5, lane = tid & 31;
    const int qb = blockIdx.x;
    const int h  = blockIdx.y;
    const int b  = blockIdx.z;
    const int kh = h >> 2;
    const int bT0 = b * T_;

    const int row0 = qb * 128 + wid * 16 + (lane >> 2);
    const int row1 = row0 + 8;
    const int rowmin_w = qb * 128 + wid * 16;
    const int rowmax_w = rowmin_w + 15;

    // Q tile: 128 rows x 64 halves
#pragma unroll
    for (int j = 0; j < 4; ++j) {
        int c = tid + j * 256;
        int row = c >> 3, part = c & 7;
        cp_async16(sQ + row * AROWB + part * 16,
                   Qf + (size_t)(bT0 + qb * 128 + row) * (H_ * D_) + h * 64 + part * 8);
    }
    // KV tile 0
#pragma unroll
    for (int j = 0; j < 4; ++j) {
        int c = tid + j * 256;
        int reg = c >> 9, idx = c & 511;
        int row = idx >> 3, part = idx & 7;
        const __half* src = reg ? Vf : Kf;
        cp_async16(sKV + reg * KVREG + row * AROWB + part * 16,
                   src + (size_t)(bT0 + row) * (HKV_ * D_) + kh * 64 + part * 8);
    }
    CP_COMMIT();
    CP_WAIT(0);
    __syncthreads();

    uint32_t qf[4][4];
#pragma unroll
    for (int ks = 0; ks < 4; ++ks) {
        uint32_t qa = (wid * 16 + (lane & 15)) * AROWB + ks * 32 + (lane >> 4) * 16;
        ldmx4(qf[ks], sQ + qa);
    }

    float o[8][4];
#pragma unroll
    for (int j = 0; j < 8; ++j)
#pragma unroll
        for (int k = 0; k < 4; ++k) o[j][k] = 0.0f;
    float m0 = -1e30f, m1 = -1e30f, l0 = 0.0f, l1 = 0.0f;
    const float scale = 0.125f;

    const int NT = 2 * qb + 2;
    for (int it = 0; it < NT; ++it) {
        if (it + 1 < NT) {
            uint32_t sb = sKV + ((it + 1) & 1) * KVBUF;
#pragma unroll
            for (int j = 0; j < 4; ++j) {
                int c = tid + j * 256;
                int reg = c >> 9, idx = c & 511;
                int row = idx >> 3, part = idx & 7;
                const __half* src = reg ? Vf : Kf;
                cp_async16(sb + reg * KVREG + row * AROWB + part * 16,
                           src + (size_t)(bT0 + (it + 1) * 64 + row) * (HKV_ * D_) + kh * 64 + part * 8);
            }
            CP_COMMIT();
            CP_WAIT(1);
        } else {
            CP_WAIT(0);
        }
        __syncthreads();

        const int kt = it;
        if (kt * 64 <= rowmax_w) {
            const uint32_t sb = sKV + (it & 1) * KVBUF;
            const uint32_t sK = sb, sV = sb + KVREG;

            float s[8][4];
#pragma unroll
            for (int j = 0; j < 8; ++j)
#pragma unroll
                for (int k = 0; k < 4; ++k) s[j][k] = 0.0f;

#pragma unroll
            for (int ks = 0; ks < 4; ++ks) {
#pragma unroll
                for (int pg = 0; pg < 2; ++pg) {
                    uint32_t kf[2][4];
#pragma unroll
                    for (int pp = 0; pp < 2; ++pp) {
                        uint32_t ka = ((2 * pg + pp) * 16 + (lane & 15)) * AROWB + ks * 32 + (lane >> 4) * 16;
                        ldmx4(kf[pp], sK + ka);
                    }
#pragma unroll
                    for (int pp = 0; pp < 2; ++pp)
#pragma unroll
                        for (int q = 0; q < 2; ++q)
                            mma_f16(s[(2 * pg + pp) * 2 + q], qf[ks], kf[pp][q], kf[pp][q + 2]);
                }
            }

            const bool needs_mask = (kt * 64 + 63) > rowmin_w;
#pragma unroll
            for (int j = 0; j < 8; ++j) {
#pragma unroll
                for (int k = 0; k < 4; ++k) s[j][k] *= scale;
                if (needs_mask) {
                    int colb = kt * 64 + j * 8 + 2 * (lane & 3);
                    if (colb > row0)     s[j][0] = -1e30f;
                    if (colb + 1 > row0) s[j][1] = -1e30f;
                    if (colb > row1)     s[j][2] = -1e30f;
                    if (colb + 1 > row1) s[j][3] = -1e30f;
                }
            }

            float mx0 = -1e30f, mx1 = -1e30f;
#pragma unroll
            for (int j = 0; j < 8; ++j) {
                mx0 = fmaxf(mx0, fmaxf(s[j][0], s[j][1]));
                mx1 = fmaxf(mx1, fmaxf(s[j][2], s[j][3]));
            }
            mx0 = fmaxf(mx0, __shfl_xor_sync(0xFFFFFFFF, mx0, 1));
            mx0 = fmaxf(mx0, __shfl_xor_sync(0xFFFFFFFF, mx0, 2));
            mx1 = fmaxf(mx1, __shfl_xor_sync(0xFFFFFFFF, mx1, 1));
            mx1 = fmaxf(mx1, __shfl_xor_sync(0xFFFFFFFF, mx1, 2));

            float mn0 = fmaxf(m0, mx0), mn1 = fmaxf(m1, mx1);
            float c0 = __expf(m0 - mn0), c1 = __expf(m1 - mn1);
            m0 = mn0; m1 = mn1;
            l0 *= c0; l1 *= c1;
#pragma unroll
            for (int j = 0; j < 8; ++j) {
                o[j][0] *= c0; o[j][1] *= c0; o[j][2] *= c1; o[j][3] *= c1;
            }
#pragma unroll
            for (int j = 0; j < 8; ++j) {
                s[j][0] = __expf(s[j][0] - mn0);
                s[j][1] = __expf(s[j][1] - mn0);
                s[j][2] = __expf(s[j][2] - mn1);
                s[j][3] = __expf(s[j][3] - mn1);
                l0 += s[j][0] + s[j][1];
                l1 += s[j][2] + s[j][3];
            }

#pragma unroll
            for (int ks = 0; ks < 4; ++ks) {
                uint32_t pa[4];
                pa[0] = pack_h2(s[2 * ks][0], s[2 * ks][1]);
                pa[1] = pack_h2(s[2 * ks][2], s[2 * ks][3]);
                pa[2] = pack_h2(s[2 * ks + 1][0], s[2 * ks + 1][1]);
                pa[3] = pack_h2(s[2 * ks + 1][2], s[2 * ks + 1][3]);
#pragma unroll
                for (int pg = 0; pg < 2; ++pg) {
                    uint32_t vf[2][4];
#pragma unroll
                    for (int pp = 0; pp < 2; ++pp) {
                        uint32_t va = (ks * 16 + (lane & 15)) * AROWB + (2 * pg + pp) * 32 + (lane >> 4) * 16;
                        ldmx4t(vf[pp], sV + va);
                    }
#pragma unroll
                    for (int pp = 0; pp < 2; ++pp)
#pragma unroll
                        for (int q = 0; q < 2; ++q)
                            mma_f16(o[(2 * pg + pp) * 2 + q], pa, vf[pp][2 * q], vf[pp][2 * q + 1]);
                }
            }
        }
        __syncthreads();
    }

    l0 += __shfl_xor_sync(0xFFFFFFFF, l0, 1);
    l0 += __shfl_xor_sync(0xFFFFFFFF, l0, 2);
    l1 += __shfl_xor_sync(0xFFFFFFFF, l1, 1);
    l1 += __shfl_xor_sync(0xFFFFFFFF, l1, 2);
    float inv0 = 1.0f / l0, inv1 = 1.0f / l1;

#pragma unroll
    for (int j = 0; j < 8; ++j) {
        int col = j * 8 + 2 * (lane & 3);
        float y0 = o[j][0] * inv0, y1 = o[j][1] * inv0;
        float y2 = o[j][2] * inv1, y3 = o[j][3] * inv1;
        size_t a0 = ((size_t)(bT0 + row0) * H_ + h) * 64 + col;
        size_t a1 = ((size_t)(bT0 + row1) * H_ + h) * 64 + col;
        uint32_t h01 = pack_bf16x2(y0, y1);
        uint32_t h23 = pack_bf16x2(y2, y3);
        __nv_bfloat162 hb01 = *reinterpret_cast<__nv_bfloat162*>(&h01);
        __nv_bfloat162 hb23 = *reinterpret_cast<__nv_bfloat162*>(&h23);
        uint32_t l01 = pack_bf16x2(y0 - __low2float(hb01), y1 - __high2float(hb01));
        uint32_t l23 = pack_bf16x2(y2 - __low2float(hb23), y3 - __high2float(hb23));
        *(uint32_t*)&Yh[a0] = h01;
        *(uint32_t*)&Yh[a1] = h23;
        *(uint32_t*)&Yl[a0] = l01;
        *(uint32_t*)&Yl[a1] = l23;
    }
}

// ---------------------------------------------------------------------------
// kernel_launch — fused-QKV gemm is our 4th launch (ncu capture target)
// ---------------------------------------------------------------------------
extern "C" void kernel_launch(void* const* d_in, const int* in_sizes, int n_in,
                              void* d_out, int out_size) {
    const float* x  = (const float*)d_in[0];
    const float* Wq = (const float*)d_in[1];
    const float* Wk = (const float*)d_in[2];
    const float* Wv = (const float*)d_in[3];
    const float* Wo = (const float*)d_in[4];
    float* out = (float*)d_out;

    float* pQKV;
    cudaGetSymbolAddress((void**)&pQKV, g_QKV);
    __half *pQf, *pKf, *pVf;
    cudaGetSymbolAddress((void**)&pQf, g_Qf);
    cudaGetSymbolAddress((void**)&pKf, g_Kf);
    cudaGetSymbolAddress((void**)&pVf, g_Vf);
    __nv_bfloat16 *pxh, *pxl, *pYh, *pYl, *pWch, *pWcl, *pWoh, *pWol;
    cudaGetSymbolAddress((void**)&pxh, g_xh);   cudaGetSymbolAddress((void**)&pxl, g_xl);
    cudaGetSymbolAddress((void**)&pYh, g_Yh);   cudaGetSymbolAddress((void**)&pYl, g_Yl);
    cudaGetSymbolAddress((void**)&pWch, g_Wch); cudaGetSymbolAddress((void**)&pWcl, g_Wcl);
    cudaGetSymbolAddress((void**)&pWoh, g_Woh); cudaGetSymbolAddress((void**)&pWol, g_Wol);

    cudaFuncSetAttribute(gemm3_kernel, cudaFuncAttributeMaxDynamicSharedMemorySize,
                         GEMM_SMEM_TOTAL);
    cudaFuncSetAttribute(attn_f16_kernel, cudaFuncAttributeMaxDynamicSharedMemorySize,
                         ATT_SMEM);

    // #1 split x
    {
        int n = BT_ * E_;
        split_kernel<<<(n + 255) / 256, 256>>>(x, pxh, pxl, n);
    }
    // #2 fused transpose+split of Wq|Wk|Wv
    tsplit3_kernel<<<dim3(64, 64, 3), dim3(32, 8)>>>(Wq, Wk, Wv, pWch, pWcl);
    // #3 transpose+split Wo
    tsplit_kernel<<<dim3(E_ / 32, E_ / 32), dim3(32, 8)>>>(Wo, pWoh, pWol, E_, E_);

    // #4 fused QKV projection (ncu capture target)
    gemm3_kernel<<<dim3(NQKV / 128, BT_ / 128), 256, GEMM_SMEM_TOTAL>>>(
        pQKV, pVf, pxh, pxl, pWch, pWcl, BT_, NQKV, E_, 1);

    // #5, #6 RoPE -> fp16
    {
        int nq = B_ * T_ * H_ * 32;
        rope_f16_kernel<<<(nq + 255) / 256, 256>>>(pQKV, pQf, H_, 0);
        int nk = B_ * T_ * HKV_ * 32;
        rope_f16_kernel<<<(nk + 255) / 256, 256>>>(pQKV, pKf, HKV_, 2048);
    }

    // #7 attention (fp16 single-term)
    attn_f16_kernel<<<dim3(T_ / 128, H_, B_), 256, ATT_SMEM>>>(
        pYh, pYl, pQf, pKf, pVf);

    // #8 output projection (bf16x3)
    gemm3_kernel<<<dim3(E_ / 128, BT_ / 128), 256, GEMM_SMEM_TOTAL>>>(
        out, nullptr, pYh, pYl, pWoh, pWol, BT_, E_, E_, 0);
}

// round 8
// speedup vs baseline: 2.2417x; 1.6968x over previous
#include <cuda_runtime.h>
#include <cuda_bf16.h>
#include <cuda_fp16.h>
#include <cstdint>
#include <math.h>

// Problem constants
#define B_  2
#define T_  2048
#define E_  2048
#define H_  32
#define HKV_ 8
#define D_  64
#define BT_ (B_*T_)  // 4096
#define NQKV 3072    // 2048 Q + 512 K + 512 V
#define NQK  2560    // fp32 part of fused output (Q+K)

// ---------------------------------------------------------------------------
// Scratch (static device globals — allocation-free rule)
// ---------------------------------------------------------------------------
__device__ float  g_QKV[BT_ * NQK];             // pre-rope Q|K fp32
__device__ __half g_xf[BT_ * E_];               // x in fp16
__device__ __half g_Qf[BT_ * H_ * D_];
__device__ __half g_Kf[BT_ * HKV_ * D_];
__device__ __half g_Vf[BT_ * HKV_ * D_];
__device__ __half g_Yf[BT_ * E_];               // attention output fp16
__device__ __half g_Wcf[NQKV * E_];             // concat Wq|Wk|Wv transposed [N,K] fp16
__device__ __half g_Woh[E_ * E_], g_Wol[E_ * E_]; // Wo transposed, fp16 hi/lo

// ---------------------------------------------------------------------------
// PTX helpers
// ---------------------------------------------------------------------------
__device__ __forceinline__ uint32_t smem_u32(const void* p) {
    uint32_t a;
    asm("{ .reg .u64 t; cvta.to.shared.u64 t, %1; cvt.u32.u64 %0, t; }" : "=r"(a) : "l"(p));
    return a;
}
__device__ __forceinline__ void ldmx4(uint32_t* r, uint32_t addr) {
    asm volatile("ldmatrix.sync.aligned.m8n8.x4.shared.b16 {%0,%1,%2,%3}, [%4];"
                 : "=r"(r[0]), "=r"(r[1]), "=r"(r[2]), "=r"(r[3]) : "r"(addr));
}
__device__ __forceinline__ void ldmx4t(uint32_t* r, uint32_t addr) {
    asm volatile("ldmatrix.sync.aligned.m8n8.x4.trans.shared.b16 {%0,%1,%2,%3}, [%4];"
                 : "=r"(r[0]), "=r"(r[1]), "=r"(r[2]), "=r"(r[3]) : "r"(addr));
}
__device__ __forceinline__ void mma_f16(float* acc, const uint32_t* a, const uint32_t b0,
                                        const uint32_t b1) {
    asm volatile(
        "mma.sync.aligned.m16n8k16.row.col.f32.f16.f16.f32 "
        "{%0,%1,%2,%3}, {%4,%5,%6,%7}, {%8,%9}, {%0,%1,%2,%3};"
        : "+f"(acc[0]), "+f"(acc[1]), "+f"(acc[2]), "+f"(acc[3])
        : "r"(a[0]), "r"(a[1]), "r"(a[2]), "r"(a[3]), "r"(b0), "r"(b1));
}
__device__ __forceinline__ void cp_async16(uint32_t saddr, const void* gaddr) {
    asm volatile("cp.async.cg.shared.global [%0], [%1], 16;" :: "r"(saddr), "l"(gaddr));
}
#define CP_COMMIT() asm volatile("cp.async.commit_group;" ::: "memory")
#define CP_WAIT(n)  asm volatile("cp.async.wait_group %0;" :: "n"(n) : "memory")

__device__ __forceinline__ uint32_t pack_h2(float lo, float hi) {
    __half2 v = __floats2half2_rn(lo, hi);
    return *reinterpret_cast<uint32_t*>(&v);
}

#define ROWB   80
#define REGB   (128 * ROWB)          // 10240 bytes per 128-row region

// ---------------------------------------------------------------------------
// gemm1: single-term fp16 GEMM. A[M,K], B[N,K] fp16. 128x128 tile, BK=32.
// mode 1 epilogue: bn<NQK -> fp32 (stride NQK); else V -> fp16 (stride 512).
// smem 2 stages x (A,B) = 40960 bytes.
// ---------------------------------------------------------------------------
#define G1_STG (2 * REGB)
#define G1_SMEM (2 * G1_STG)

__device__ __forceinline__ void g1_issue(uint32_t sbuf, const __half* a, const __half* b,
                                         int K, int tid) {
    const __half* srcs[2] = {a, b};
#pragma unroll
    for (int reg = 0; reg < 2; ++reg) {
        const __half* s = srcs[reg];
        uint32_t sr = sbuf + reg * REGB;
#pragma unroll
        for (int j = 0; j < 2; ++j) {
            int c = tid + j * 256;
            int row = c >> 2, part = c & 3;
            cp_async16(sr + row * ROWB + part * 16, s + (size_t)row * K + part * 8);
        }
    }
}

__global__ __launch_bounds__(256)
void gemm1_kernel(float* __restrict__ C, __half* __restrict__ Cv,
                  const __half* __restrict__ A, const __half* __restrict__ B,
                  int M, int N, int K, int mode) {
    extern __shared__ char smem[];
    const uint32_t sbase = smem_u32(smem);
    const int tid = threadIdx.x;
    const int wid = tid >> 5, lane = tid & 31;
    const int warp_m = wid >> 2;
    const int warp_n = wid & 3;
    const int bm = blockIdx.y * 128, bn = blockIdx.x * 128;

    const __half* pA = A + (size_t)bm * K;
    const __half* pB = B + (size_t)bn * K;

    float acc[4][4][4];
#pragma unroll
    for (int i = 0; i < 4; ++i)
#pragma unroll
        for (int j = 0; j < 4; ++j)
#pragma unroll
            for (int k = 0; k < 4; ++k) acc[i][j][k] = 0.0f;

    const int NIT = K / 32;

    const uint32_t a_row = warp_m * 64 + (lane & 15);
    const uint32_t a_coff = (lane >> 4) * 16;
    const uint32_t b_rowbase = warp_n * 32 + (lane & 15);
    const uint32_t b_coff = (lane >> 4) * 16;

    g1_issue(sbase, pA, pB, K, tid);
    CP_COMMIT();

    for (int it = 0; it < NIT; ++it) {
        const uint32_t sbuf = sbase + (it & 1) * G1_STG;
        if (it + 1 < NIT) {
            g1_issue(sbase + ((it + 1) & 1) * G1_STG, pA + (it + 1) * 32, pB + (it + 1) * 32, K, tid);
            CP_COMMIT();
            CP_WAIT(1);
        } else {
            CP_WAIT(0);
        }
        __syncthreads();

        const uint32_t sA = sbuf, sB = sbuf + REGB;
#pragma unroll
        for (int ks = 0; ks < 2; ++ks) {
            const uint32_t kb = ks * 32;
            uint32_t bf[8];
#pragma unroll
            for (int p = 0; p < 2; ++p) {
                uint32_t ba = (b_rowbase + p * 16) * ROWB + kb + b_coff;
                ldmx4(&bf[p * 4], sB + ba);
            }
            uint32_t af[4][4];
#pragma unroll
            for (int mi = 0; mi < 4; ++mi) {
                uint32_t aa = (a_row + mi * 16) * ROWB + kb + a_coff;
                ldmx4(af[mi], sA + aa);
            }
#pragma unroll
            for (int mi = 0; mi < 4; ++mi)
#pragma unroll
                for (int ni = 0; ni < 4; ++ni) {
                    const int p = ni >> 1, q = ni & 1;
                    mma_f16(acc[mi][ni], af[mi], bf[p * 4 + q], bf[p * 4 + q + 2]);
                }
        }
        __syncthreads();
    }

    const int rbase = bm + warp_m * 64 + (lane >> 2);
    const int cbase = bn + warp_n * 32 + (lane & 3) * 2;

    if (mode == 0 || bn < NQK) {
        const int ldc = (mode == 0) ? N : NQK;
#pragma unroll
        for (int mi = 0; mi < 4; ++mi)
#pragma unroll
            for (int ni = 0; ni < 4; ++ni) {
                float* c0 = C + (size_t)(rbase + mi * 16) * ldc + cbase + ni * 8;
                float* c1 = C + (size_t)(rbase + mi * 16 + 8) * ldc + cbase + ni * 8;
                *(float2*)c0 = make_float2(acc[mi][ni][0], acc[mi][ni][1]);
                *(float2*)c1 = make_float2(acc[mi][ni][2], acc[mi][ni][3]);
            }
    } else {
        const int cb = cbase - NQK;
#pragma unroll
        for (int mi = 0; mi < 4; ++mi)
#pragma unroll
            for (int ni = 0; ni < 4; ++ni) {
                *(uint32_t*)&Cv[(size_t)(rbase + mi * 16) * 512 + cb + ni * 8] =
                    pack_h2(acc[mi][ni][0], acc[mi][ni][1]);
                *(uint32_t*)&Cv[(size_t)(rbase + mi * 16 + 8) * 512 + cb + ni * 8] =
                    pack_h2(acc[mi][ni][2], acc[mi][ni][3]);
            }
    }
}

// ---------------------------------------------------------------------------
// gemm2: 2-term fp16 GEMM for output projection: C = A·(Bh+Bl)^T, fp32 out.
// smem 2 stages x (A,Bh,Bl) = 61440 bytes.
// ---------------------------------------------------------------------------
#define G2_STG (3 * REGB)
#define G2_SMEM (2 * G2_STG)

__device__ __forceinline__ void g2_issue(uint32_t sbuf, const __half* a,
                                         const __half* bh, const __half* bl,
                                         int K, int tid) {
    const __half* srcs[3] = {a, bh, bl};
#pragma unroll
    for (int reg = 0; reg < 3; ++reg) {
        const __half* s = srcs[reg];
        uint32_t sr = sbuf + reg * REGB;
#pragma unroll
        for (int j = 0; j < 2; ++j) {
            int c = tid + j * 256;
            int row = c >> 2, part = c & 3;
            cp_async16(sr + row * ROWB + part * 16, s + (size_t)row * K + part * 8);
        }
    }
}

__global__ __launch_bounds__(256)
void gemm2_kernel(float* __restrict__ C, const __half* __restrict__ A,
                  const __half* __restrict__ Bh, const __half* __restrict__ Bl,
                  int M, int N, int K) {
    extern __shared__ char smem[];
    const uint32_t sbase = smem_u32(smem);
    const int tid = threadIdx.x;
    const int wid = tid >> 5, lane = tid & 31;
    const int warp_m = wid >> 2;
    const int warp_n = wid & 3;
    const int bm = blockIdx.y * 128, bn = blockIdx.x * 128;

    const __half* pA = A + (size_t)bm * K;
    const __half* pBh = Bh + (size_t)bn * K;
    const __half* pBl = Bl + (size_t)bn * K;

    float acc[4][4][4];
#pragma unroll
    for (int i = 0; i < 4; ++i)
#pragma unroll
        for (int j = 0; j < 4; ++j)
#pragma unroll
            for (int k = 0; k < 4; ++k) acc[i][j][k] = 0.0f;

    const int NIT = K / 32;

    const uint32_t a_row = warp_m * 64 + (lane & 15);
    const uint32_t a_coff = (lane >> 4) * 16;
    const uint32_t b_rowbase = warp_n * 32 + (lane & 15);
    const uint32_t b_coff = (lane >> 4) * 16;

    g2_issue(sbase, pA, pBh, pBl, K, tid);
    CP_COMMIT();

    for (int it = 0; it < NIT; ++it) {
        const uint32_t sbuf = sbase + (it & 1) * G2_STG;
        if (it + 1 < NIT) {
            g2_issue(sbase + ((it + 1) & 1) * G2_STG,
                     pA + (it + 1) * 32, pBh + (it + 1) * 32, pBl + (it + 1) * 32, K, tid);
            CP_COMMIT();
            CP_WAIT(1);
        } else {
            CP_WAIT(0);
        }
        __syncthreads();

        const uint32_t sA = sbuf, sBh = sbuf + REGB, sBl = sbuf + 2 * REGB;
#pragma unroll
        for (int ks = 0; ks < 2; ++ks) {
            const uint32_t kb = ks * 32;
            uint32_t bhf[8], blf[8];
#pragma unroll
            for (int p = 0; p < 2; ++p) {
                uint32_t ba = (b_rowbase + p * 16) * ROWB + kb + b_coff;
                ldmx4(&bhf[p * 4], sBh + ba);
                ldmx4(&blf[p * 4], sBl + ba);
            }
            uint32_t af[4][4];
#pragma unroll
            for (int mi = 0; mi < 4; ++mi) {
                uint32_t aa = (a_row + mi * 16) * ROWB + kb + a_coff;
                ldmx4(af[mi], sA + aa);
            }
#pragma unroll
            for (int mi = 0; mi < 4; ++mi)
#pragma unroll
                for (int ni = 0; ni < 4; ++ni) {
                    const int p = ni >> 1, q = ni & 1;
                    mma_f16(acc[mi][ni], af[mi], bhf[p * 4 + q], bhf[p * 4 + q + 2]);
                }
#pragma unroll
            for (int mi = 0; mi < 4; ++mi)
#pragma unroll
                for (int ni = 0; ni < 4; ++ni) {
                    const int p = ni >> 1, q = ni & 1;
                    mma_f16(acc[mi][ni], af[mi], blf[p * 4 + q], blf[p * 4 + q + 2]);
                }
        }
        __syncthreads();
    }

    const int rbase = bm + warp_m * 64 + (lane >> 2);
    const int cbase = bn + warp_n * 32 + (lane & 3) * 2;
#pragma unroll
    for (int mi = 0; mi < 4; ++mi)
#pragma unroll
        for (int ni = 0; ni < 4; ++ni) {
            float* c0 = C + (size_t)(rbase + mi * 16) * N + cbase + ni * 8;
            float* c1 = C + (size_t)(rbase + mi * 16 + 8) * N + cbase + ni * 8;
            *(float2*)c0 = make_float2(acc[mi][ni][0], acc[mi][ni][1]);
            *(float2*)c1 = make_float2(acc[mi][ni][2], acc[mi][ni][3]);
        }
}

// ---------------------------------------------------------------------------
// fp32 -> fp16 convert (vectorized x4)
// ---------------------------------------------------------------------------
__global__ __launch_bounds__(256)
void cvt_f16_kernel(const float* __restrict__ in, __half* __restrict__ out, int n4) {
    int i = blockIdx.x * blockDim.x + threadIdx.x;
    if (i >= n4) return;
    float4 v = ((const float4*)in)[i];
    uint32_t lo = pack_h2(v.x, v.y);
    uint32_t hi = pack_h2(v.z, v.w);
    ((uint2*)out)[i] = make_uint2(lo, hi);
}

// ---------------------------------------------------------------------------
// Fused transpose of Wq|Wk|Wv into concat fp16 buffer [NQKV, E]
// ---------------------------------------------------------------------------
__global__ __launch_bounds__(256)
void tsplit3_kernel(const float* __restrict__ Wq, const float* __restrict__ Wk,
                    const float* __restrict__ Wv, __half* __restrict__ Tf) {
    __shared__ float t[32][33];
    const int z = blockIdx.z;
    const float* W = (z == 0) ? Wq : (z == 1) ? Wk : Wv;
    const int N = (z == 0) ? (H_ * D_) : (HKV_ * D_);
    const int nofs = (z == 0) ? 0 : (z == 1) ? 2048 : 2560;
    const int n0 = blockIdx.x * 32, k0 = blockIdx.y * 32;
    if (n0 >= N) return;
    const int tx = threadIdx.x, ty = threadIdx.y;
#pragma unroll
    for (int i = 0; i < 4; ++i)
        t[ty + i * 8][tx] = W[(size_t)(k0 + ty + i * 8) * N + n0 + tx];
    __syncthreads();
#pragma unroll
    for (int i = 0; i < 4; ++i) {
        float v = t[tx][ty + i * 8];
        Tf[(size_t)(nofs + n0 + ty + i * 8) * E_ + k0 + tx] = __float2half_rn(v);
    }
}

// ---------------------------------------------------------------------------
// Transpose + fp16 hi/lo split for Wo
// ---------------------------------------------------------------------------
__global__ __launch_bounds__(256)
void tsplit_wo_kernel(const float* __restrict__ W, __half* __restrict__ Th,
                      __half* __restrict__ Tl) {
    __shared__ float t[32][33];
    const int tx = threadIdx.x, ty = threadIdx.y;
    const int n0 = blockIdx.x * 32, k0 = blockIdx.y * 32;
#pragma unroll
    for (int i = 0; i < 4; ++i)
        t[ty + i * 8][tx] = W[(size_t)(k0 + ty + i * 8) * E_ + n0 + tx];
    __syncthreads();
#pragma unroll
    for (int i = 0; i < 4; ++i) {
        float v = t[tx][ty + i * 8];
        __half h = __float2half_rn(v);
        size_t o = (size_t)(n0 + ty + i * 8) * E_ + k0 + tx;
        Th[o] = h;
        Tl[o] = __float2half_rn(v - __half2float(h));
    }
}

// ---------------------------------------------------------------------------
// RoPE from fused fp32 buffer -> fp16
// ---------------------------------------------------------------------------
__global__ __launch_bounds__(256)
void rope_f16_kernel(const float* __restrict__ qkv, __half* __restrict__ out,
                     int nh, int colbase) {
    int idx = blockIdx.x * blockDim.x + threadIdx.x;
    int total = B_ * T_ * nh * 32;
    if (idx >= total) return;
    int i = idx & 31;
    int h = (idx >> 5) % nh;
    int t = (idx / (32 * nh)) % T_;
    int b = idx / (32 * nh * T_);

    float inv_freq = expf(-(float)i * (9.210340371976184f / 32.0f));
    float ang = (float)t * inv_freq;
    float c = cosf(ang), s = sinf(ang);

    size_t row = (size_t)(b * T_ + t);
    const float* src = qkv + row * NQK + colbase + h * 64;
    float x1 = src[i];
    float x2 = src[32 + i];
    __half* dst = out + row * nh * 64 + h * 64;
    dst[i]      = __float2half_rn(x1 * c - x2 * s);
    dst[32 + i] = __float2half_rn(x2 * c + x1 * s);
}

// ---------------------------------------------------------------------------
// FA2-style causal attention, fp16 mma.sync. Writes Yf fp16.
// ---------------------------------------------------------------------------
#define AROWB 144
#define KVREG (64 * AROWB)              // 9216
#define KVBUF (2 * KVREG)               // 18432
#define QREG  (128 * AROWB)             // 18432
#define ATT_SMEM (QREG + 2 * KVBUF)     // 55296

__global__ __launch_bounds__(256)
void attn_f16_kernel(__half* __restrict__ Yf,
                     const __half* __restrict__ Qf, const __half* __restrict__ Kf,
                     const __half* __restrict__ Vf) {
    extern __shared__ char smem[];
    const uint32_t sbase = smem_u32(smem);
    const uint32_t sQ = sbase;
    const uint32_t sKV = sbase + QREG;

    const int tid = threadIdx.x;
    const int wid = tid >> 5, lane = tid & 31;
    const int qb = blockIdx.x;
    const int h  = blockIdx.y;
    const int b  = blockIdx.z;
    const int kh = h >> 2;
    const int bT0 = b * T_;

    const int row0 = qb * 128 + wid * 16 + (lane >> 2);
    const int row1 = row0 + 8;
    const int rowmin_w = qb * 128 + wid * 16;
    const int rowmax_w = rowmin_w + 15;

#pragma unroll
    for (int j = 0; j < 4; ++j) {
        int c = tid + j * 256;
        int row = c >> 3, part = c & 7;
        cp_async16(sQ + row * AROWB + part * 16,
                   Qf + (size_t)(bT0 + qb * 128 + row) * (H_ * D_) + h * 64 + part * 8);
    }
#pragma unroll
    for (int j = 0; j < 4; ++j) {
        int c = tid + j * 256;
        int reg = c >> 9, idx = c & 511;
        int row = idx >> 3, part = idx & 7;
        const __half* src = reg ? Vf : Kf;
        cp_async16(sKV + reg * KVREG + row * AROWB + part * 16,
                   src + (size_t)(bT0 + row) * (HKV_ * D_) + kh * 64 + part * 8);
    }
    CP_COMMIT();
    CP_WAIT(0);
    __syncthreads();

    uint32_t qf[4][4];
#pragma unroll
    for (int ks = 0; ks < 4; ++ks) {
        uint32_t qa = (wid * 16 + (lane & 15)) * AROWB + ks * 32 + (lane >> 4) * 16;
        ldmx4(qf[ks], sQ + qa);
    }

    float o[8][4];
#pragma unroll
    for (int j = 0; j < 8; ++j)
#pragma unroll
        for (int k = 0; k < 4; ++k) o[j][k] = 0.0f;
    float m0 = -1e30f, m1 = -1e30f, l0 = 0.0f, l1 = 0.0f;
    const float scale = 0.125f;

    const int NT = 2 * qb + 2;
    for (int it = 0; it < NT; ++it) {
        if (it + 1 < NT) {
            uint32_t sb = sKV + ((it + 1) & 1) * KVBUF;
#pragma unroll
            for (int j = 0; j < 4; ++j) {
                int c = tid + j * 256;
                int reg = c >> 9, idx = c & 511;
                int row = idx >> 3, part = idx & 7;
                const __half* src = reg ? Vf : Kf;
                cp_async16(sb + reg * KVREG + row * AROWB + part * 16,
                           src + (size_t)(bT0 + (it + 1) * 64 + row) * (HKV_ * D_) + kh * 64 + part * 8);
            }
            CP_COMMIT();
            CP_WAIT(1);
        } else {
            CP_WAIT(0);
        }
        __syncthreads();

        const int kt = it;
        if (kt * 64 <= rowmax_w) {
            const uint32_t sb = sKV + (it & 1) * KVBUF;
            const uint32_t sK = sb, sV = sb + KVREG;

            float s[8][4];
#pragma unroll
            for (int j = 0; j < 8; ++j)
#pragma unroll
                for (int k = 0; k < 4; ++k) s[j][k] = 0.0f;

#pragma unroll
            for (int ks = 0; ks < 4; ++ks) {
#pragma unroll
                for (int pg = 0; pg < 2; ++pg) {
                    uint32_t kf[2][4];
#pragma unroll
                    for (int pp = 0; pp < 2; ++pp) {
                        uint32_t ka = ((2 * pg + pp) * 16 + (lane & 15)) * AROWB + ks * 32 + (lane >> 4) * 16;
                        ldmx4(kf[pp], sK + ka);
                    }
#pragma unroll
                    for (int pp = 0; pp < 2; ++pp)
#pragma unroll
                        for (int q = 0; q < 2; ++q)
                            mma_f16(s[(2 * pg + pp) * 2 + q], qf[ks], kf[pp][q], kf[pp][q + 2]);
                }
            }

            const bool needs_mask = (kt * 64 + 63) > rowmin_w;
#pragma unroll
            for (int j = 0; j < 8; ++j) {
#pragma unroll
                for (int k = 0; k < 4; ++k) s[j][k] *= scale;
                if (needs_mask) {
                    int colb = kt * 64 + j * 8 + 2 * (lane & 3);
                    if (colb > row0)     s[j][0] = -1e30f;
                    if (colb + 1 > row0) s[j][1] = -1e30f;
                    if (colb > row1)     s[j][2] = -1e30f;
                    if (colb + 1 > row1) s[j][3] = -1e30f;
                }
            }

            float mx0 = -1e30f, mx1 = -1e30f;
#pragma unroll
            for (int j = 0; j < 8; ++j) {
                mx0 = fmaxf(mx0, fmaxf(s[j][0], s[j][1]));
                mx1 = fmaxf(mx1, fmaxf(s[j][2], s[j][3]));
            }
            mx0 = fmaxf(mx0, __shfl_xor_sync(0xFFFFFFFF, mx0, 1));
            mx0 = fmaxf(mx0, __shfl_xor_sync(0xFFFFFFFF, mx0, 2));
            mx1 = fmaxf(mx1, __shfl_xor_sync(0xFFFFFFFF, mx1, 1));
            mx1 = fmaxf(mx1, __shfl_xor_sync(0xFFFFFFFF, mx1, 2));

            float mn0 = fmaxf(m0, mx0), mn1 = fmaxf(m1, mx1);
            float c0 = __expf(m0 - mn0), c1 = __expf(m1 - mn1);
            m0 = mn0; m1 = mn1;
            l0 *= c0; l1 *= c1;
#pragma unroll
            for (int j = 0; j < 8; ++j) {
                o[j][0] *= c0; o[j][1] *= c0; o[j][2] *= c1; o[j][3] *= c1;
            }
#pragma unroll
            for (int j = 0; j < 8; ++j) {
                s[j][0] = __expf(s[j][0] - mn0);
                s[j][1] = __expf(s[j][1] - mn0);
                s[j][2] = __expf(s[j][2] - mn1);
                s[j][3] = __expf(s[j][3] - mn1);
                l0 += s[j][0] + s[j][1];
                l1 += s[j][2] + s[j][3];
            }

#pragma unroll
            for (int ks = 0; ks < 4; ++ks) {
                uint32_t pa[4];
                pa[0] = pack_h2(s[2 * ks][0], s[2 * ks][1]);
                pa[1] = pack_h2(s[2 * ks][2], s[2 * ks][3]);
                pa[2] = pack_h2(s[2 * ks + 1][0], s[2 * ks + 1][1]);
                pa[3] = pack_h2(s[2 * ks + 1][2], s[2 * ks + 1][3]);
#pragma unroll
                for (int pg = 0; pg < 2; ++pg) {
                    uint32_t vf[2][4];
#pragma unroll
                    for (int pp = 0; pp < 2; ++pp) {
                        uint32_t va = (ks * 16 + (lane & 15)) * AROWB + (2 * pg + pp) * 32 + (lane >> 4) * 16;
                        ldmx4t(vf[pp], sV + va);
                    }
#pragma unroll
                    for (int pp = 0; pp < 2; ++pp)
#pragma unroll
                        for (int q = 0; q < 2; ++q)
                            mma_f16(o[(2 * pg + pp) * 2 + q], pa, vf[pp][2 * q], vf[pp][2 * q + 1]);
                }
            }
        }
        __syncthreads();
    }

    l0 += __shfl_xor_sync(0xFFFFFFFF, l0, 1);
    l0 += __shfl_xor_sync(0xFFFFFFFF, l0, 2);
    l1 += __shfl_xor_sync(0xFFFFFFFF, l1, 1);
    l1 += __shfl_xor_sync(0xFFFFFFFF, l1, 2);
    float inv0 = 1.0f / l0, inv1 = 1.0f / l1;

#pragma unroll
    for (int j = 0; j < 8; ++j) {
        int col = j * 8 + 2 * (lane & 3);
        size_t a0 = ((size_t)(bT0 + row0) * H_ + h) * 64 + col;
        size_t a1 = ((size_t)(bT0 + row1) * H_ + h) * 64 + col;
        *(uint32_t*)&Yf[a0] = pack_h2(o[j][0] * inv0, o[j][1] * inv0);
        *(uint32_t*)&Yf[a1] = pack_h2(o[j][2] * inv1, o[j][3] * inv1);
    }
}

// ---------------------------------------------------------------------------
// kernel_launch — QKV gemm stays our 4th launch (ncu capture target)
// ---------------------------------------------------------------------------
extern "C" void kernel_launch(void* const* d_in, const int* in_sizes, int n_in,
                              void* d_out, int out_size) {
    const float* x  = (const float*)d_in[0];
    const float* Wq = (const float*)d_in[1];
    const float* Wk = (const float*)d_in[2];
    const float* Wv = (const float*)d_in[3];
    const float* Wo = (const float*)d_in[4];
    float* out = (float*)d_out;

    float* pQKV;
    cudaGetSymbolAddress((void**)&pQKV, g_QKV);
    __half *pxf, *pQf, *pKf, *pVf, *pYf, *pWcf, *pWoh, *pWol;
    cudaGetSymbolAddress((void**)&pxf, g_xf);
    cudaGetSymbolAddress((void**)&pQf, g_Qf);
    cudaGetSymbolAddress((void**)&pKf, g_Kf);
    cudaGetSymbolAddress((void**)&pVf, g_Vf);
    cudaGetSymbolAddress((void**)&pYf, g_Yf);
    cudaGetSymbolAddress((void**)&pWcf, g_Wcf);
    cudaGetSymbolAddress((void**)&pWoh, g_Woh);
    cudaGetSymbolAddress((void**)&pWol, g_Wol);

    cudaFuncSetAttribute(gemm1_kernel, cudaFuncAttributeMaxDynamicSharedMemorySize, G1_SMEM);
    cudaFuncSetAttribute(gemm2_kernel, cudaFuncAttributeMaxDynamicSharedMemorySize, G2_SMEM);
    cudaFuncSetAttribute(attn_f16_kernel, cudaFuncAttributeMaxDynamicSharedMemorySize, ATT_SMEM);

    // #1 x -> fp16
    {
        int n4 = (BT_ * E_) / 4;
        cvt_f16_kernel<<<(n4 + 255) / 256, 256>>>(x, pxf, n4);
    }
    // #2 fused transpose Wq|Wk|Wv -> fp16 concat
    tsplit3_kernel<<<dim3(64, 64, 3), dim3(32, 8)>>>(Wq, Wk, Wv, pWcf);
    // #3 transpose + hi/lo split Wo
    tsplit_wo_kernel<<<dim3(64, 64), dim3(32, 8)>>>(Wo, pWoh, pWol);

    // #4 fused QKV projection, single-term fp16 (ncu capture target)
    gemm1_kernel<<<dim3(NQKV / 128, BT_ / 128), 256, G1_SMEM>>>(
        pQKV, pVf, pxf, pWcf, BT_, NQKV, E_, 1);

    // #5, #6 RoPE -> fp16
    {
        int nq = B_ * T_ * H_ * 32;
        rope_f16_kernel<<<(nq + 255) / 256, 256>>>(pQKV, pQf, H_, 0);
        int nk = B_ * T_ * HKV_ * 32;
        rope_f16_kernel<<<(nk + 255) / 256, 256>>>(pQKV, pKf, HKV_, 2048);
    }

    // #7 attention
    attn_f16_kernel<<<dim3(T_ / 128, H_, B_), 256, ATT_SMEM>>>(pYf, pQf, pKf, pVf);

    // #8 output projection, 2-term fp16
    gemm2_kernel<<<dim3(E_ / 128, BT_ / 128), 256, G2_SMEM>>>(
        out, pYf, pWoh, pWol, BT_, E_, E_);
}

// round 9
// speedup vs baseline: 2.6114x; 1.1650x over previous
#include <cuda_runtime.h>
#include <cuda_bf16.h>
#include <cuda_fp16.h>
#include <cstdint>
#include <math.h>

// Problem constants
#define B_  2
#define T_  2048
#define E_  2048
#define H_  32
#define HKV_ 8
#define D_  64
#define BT_ (B_*T_)  // 4096
#define NQKV 3072    // 2048 Q + 512 K + 512 V
#define NQK  2560    // fp32 part of fused output (Q+K)

// ---------------------------------------------------------------------------
// Scratch (static device globals — allocation-free rule)
// ---------------------------------------------------------------------------
__device__ float  g_QKV[BT_ * NQK];             // pre-rope Q|K fp32
__device__ __half g_xf[BT_ * E_];               // x in fp16
__device__ __half g_Qf[BT_ * H_ * D_];
__device__ __half g_Kf[BT_ * HKV_ * D_];
__device__ __half g_Vf[BT_ * HKV_ * D_];
__device__ __half g_Yf[BT_ * E_];               // attention output fp16
__device__ __half g_Wcf[NQKV * E_];             // concat Wq|Wk|Wv transposed [N,K] fp16
__device__ __half g_Wof[E_ * E_];               // Wo transposed fp16

// ---------------------------------------------------------------------------
// PTX helpers
// ---------------------------------------------------------------------------
__device__ __forceinline__ uint32_t smem_u32(const void* p) {
    uint32_t a;
    asm("{ .reg .u64 t; cvta.to.shared.u64 t, %1; cvt.u32.u64 %0, t; }" : "=r"(a) : "l"(p));
    return a;
}
__device__ __forceinline__ void ldmx4(uint32_t* r, uint32_t addr) {
    asm volatile("ldmatrix.sync.aligned.m8n8.x4.shared.b16 {%0,%1,%2,%3}, [%4];"
                 : "=r"(r[0]), "=r"(r[1]), "=r"(r[2]), "=r"(r[3]) : "r"(addr));
}
__device__ __forceinline__ void ldmx4t(uint32_t* r, uint32_t addr) {
    asm volatile("ldmatrix.sync.aligned.m8n8.x4.trans.shared.b16 {%0,%1,%2,%3}, [%4];"
                 : "=r"(r[0]), "=r"(r[1]), "=r"(r[2]), "=r"(r[3]) : "r"(addr));
}
__device__ __forceinline__ void mma_f16(float* acc, const uint32_t* a, const uint32_t b0,
                                        const uint32_t b1) {
    asm volatile(
        "mma.sync.aligned.m16n8k16.row.col.f32.f16.f16.f32 "
        "{%0,%1,%2,%3}, {%4,%5,%6,%7}, {%8,%9}, {%0,%1,%2,%3};"
        : "+f"(acc[0]), "+f"(acc[1]), "+f"(acc[2]), "+f"(acc[3])
        : "r"(a[0]), "r"(a[1]), "r"(a[2]), "r"(a[3]), "r"(b0), "r"(b1));
}
__device__ __forceinline__ void cp_async16(uint32_t saddr, const void* gaddr) {
    asm volatile("cp.async.cg.shared.global [%0], [%1], 16;" :: "r"(saddr), "l"(gaddr));
}
#define CP_COMMIT() asm volatile("cp.async.commit_group;" ::: "memory")
#define CP_WAIT(n)  asm volatile("cp.async.wait_group %0;" :: "n"(n) : "memory")

__device__ __forceinline__ uint32_t pack_h2(float lo, float hi) {
    __half2 v = __floats2half2_rn(lo, hi);
    return *reinterpret_cast<uint32_t*>(&v);
}

#define ROWB   80
#define REGB   (128 * ROWB)          // 10240 bytes per 128-row region

// ---------------------------------------------------------------------------
// gemm1: single-term fp16 GEMM, wide warp tiles.
// A[M,K], B[N,K] fp16. CTA tile 128x128, BK=32, 128 threads (4 warps),
// warp tile 64x64 (2x2 warp grid). Feed ratio: 8 LDSM.x4 per 32 MMAs.
// mode 1 epilogue: bn<NQK -> fp32 (stride NQK); else V -> fp16 (stride 512).
// mode 0: plain fp32 out stride N.
// ---------------------------------------------------------------------------
#define G1_STG (2 * REGB)            // A + B regions = 20480
#define G1_SMEM (2 * G1_STG)         // 40960 (double buffered)

__device__ __forceinline__ void g1_issue(uint32_t sbuf, const __half* a, const __half* b,
                                         int K, int tid) {
    const __half* srcs[2] = {a, b};
#pragma unroll
    for (int reg = 0; reg < 2; ++reg) {
        const __half* s = srcs[reg];
        uint32_t sr = sbuf + reg * REGB;
#pragma unroll
        for (int j = 0; j < 4; ++j) {
            int c = tid + j * 128;          // 0..511
            int row = c >> 2, part = c & 3;
            cp_async16(sr + row * ROWB + part * 16, s + (size_t)row * K + part * 8);
        }
    }
}

__global__ __launch_bounds__(128)
void gemm1_kernel(float* __restrict__ C, __half* __restrict__ Cv,
                  const __half* __restrict__ A, const __half* __restrict__ B,
                  int M, int N, int K, int mode) {
    extern __shared__ char smem[];
    const uint32_t sbase = smem_u32(smem);
    const int tid = threadIdx.x;
    const int wid = tid >> 5, lane = tid & 31;
    const int warp_m = wid >> 1;          // 0..1 -> 64-row slab
    const int warp_n = wid & 1;           // 0..1 -> 64-col slab
    const int bm = blockIdx.y * 128, bn = blockIdx.x * 128;

    const __half* pA = A + (size_t)bm * K;
    const __half* pB = B + (size_t)bn * K;

    float acc[4][8][4];
#pragma unroll
    for (int i = 0; i < 4; ++i)
#pragma unroll
        for (int j = 0; j < 8; ++j)
#pragma unroll
            for (int k = 0; k < 4; ++k) acc[i][j][k] = 0.0f;

    const int NIT = K / 32;

    const uint32_t a_row = warp_m * 64 + (lane & 15);
    const uint32_t a_coff = (lane >> 4) * 16;
    const uint32_t b_rowbase = warp_n * 64 + (lane & 15);
    const uint32_t b_coff = (lane >> 4) * 16;

    g1_issue(sbase, pA, pB, K, tid);
    CP_COMMIT();

    for (int it = 0; it < NIT; ++it) {
        const uint32_t sbuf = sbase + (it & 1) * G1_STG;
        if (it + 1 < NIT) {
            g1_issue(sbase + ((it + 1) & 1) * G1_STG, pA + (it + 1) * 32, pB + (it + 1) * 32, K, tid);
            CP_COMMIT();
            CP_WAIT(1);
        } else {
            CP_WAIT(0);
        }
        __syncthreads();

        const uint32_t sA = sbuf, sB = sbuf + REGB;
#pragma unroll
        for (int ks = 0; ks < 2; ++ks) {
            const uint32_t kb = ks * 32;
            uint32_t bf[16];
#pragma unroll
            for (int p = 0; p < 4; ++p) {
                uint32_t ba = (b_rowbase + p * 16) * ROWB + kb + b_coff;
                ldmx4(&bf[p * 4], sB + ba);
            }
            uint32_t af[4][4];
#pragma unroll
            for (int mi = 0; mi < 4; ++mi) {
                uint32_t aa = (a_row + mi * 16) * ROWB + kb + a_coff;
                ldmx4(af[mi], sA + aa);
            }
#pragma unroll
            for (int mi = 0; mi < 4; ++mi)
#pragma unroll
                for (int ni = 0; ni < 8; ++ni) {
                    const int p = ni >> 1, q = ni & 1;
                    mma_f16(acc[mi][ni], af[mi], bf[p * 4 + q], bf[p * 4 + q + 2]);
                }
        }
        __syncthreads();
    }

    const int rbase = bm + warp_m * 64 + (lane >> 2);
    const int cbase = bn + warp_n * 64 + (lane & 3) * 2;

    if (mode == 0 || bn < NQK) {
        const int ldc = (mode == 0) ? N : NQK;
#pragma unroll
        for (int mi = 0; mi < 4; ++mi)
#pragma unroll
            for (int ni = 0; ni < 8; ++ni) {
                float* c0 = C + (size_t)(rbase + mi * 16) * ldc + cbase + ni * 8;
                float* c1 = C + (size_t)(rbase + mi * 16 + 8) * ldc + cbase + ni * 8;
                *(float2*)c0 = make_float2(acc[mi][ni][0], acc[mi][ni][1]);
                *(float2*)c1 = make_float2(acc[mi][ni][2], acc[mi][ni][3]);
            }
    } else {
        const int cb = cbase - NQK;
#pragma unroll
        for (int mi = 0; mi < 4; ++mi)
#pragma unroll
            for (int ni = 0; ni < 8; ++ni) {
                *(uint32_t*)&Cv[(size_t)(rbase + mi * 16) * 512 + cb + ni * 8] =
                    pack_h2(acc[mi][ni][0], acc[mi][ni][1]);
                *(uint32_t*)&Cv[(size_t)(rbase + mi * 16 + 8) * 512 + cb + ni * 8] =
                    pack_h2(acc[mi][ni][2], acc[mi][ni][3]);
            }
    }
}

// ---------------------------------------------------------------------------
// fp32 -> fp16 convert (vectorized x4)
// ---------------------------------------------------------------------------
__global__ __launch_bounds__(256)
void cvt_f16_kernel(const float* __restrict__ in, __half* __restrict__ out, int n4) {
    int i = blockIdx.x * blockDim.x + threadIdx.x;
    if (i >= n4) return;
    float4 v = ((const float4*)in)[i];
    uint32_t lo = pack_h2(v.x, v.y);
    uint32_t hi = pack_h2(v.z, v.w);
    ((uint2*)out)[i] = make_uint2(lo, hi);
}

// ---------------------------------------------------------------------------
// Fused transpose of Wq|Wk|Wv into concat fp16 buffer [NQKV, E]
// ---------------------------------------------------------------------------
__global__ __launch_bounds__(256)
void tsplit3_kernel(const float* __restrict__ Wq, const float* __restrict__ Wk,
                    const float* __restrict__ Wv, __half* __restrict__ Tf) {
    __shared__ float t[32][33];
    const int z = blockIdx.z;
    const float* W = (z == 0) ? Wq : (z == 1) ? Wk : Wv;
    const int N = (z == 0) ? (H_ * D_) : (HKV_ * D_);
    const int nofs = (z == 0) ? 0 : (z == 1) ? 2048 : 2560;
    const int n0 = blockIdx.x * 32, k0 = blockIdx.y * 32;
    if (n0 >= N) return;
    const int tx = threadIdx.x, ty = threadIdx.y;
#pragma unroll
    for (int i = 0; i < 4; ++i)
        t[ty + i * 8][tx] = W[(size_t)(k0 + ty + i * 8) * N + n0 + tx];
    __syncthreads();
#pragma unroll
    for (int i = 0; i < 4; ++i) {
        float v = t[tx][ty + i * 8];
        Tf[(size_t)(nofs + n0 + ty + i * 8) * E_ + k0 + tx] = __float2half_rn(v);
    }
}

// ---------------------------------------------------------------------------
// Transpose Wo -> fp16 [N,K]
// ---------------------------------------------------------------------------
__global__ __launch_bounds__(256)
void twof16_kernel(const float* __restrict__ W, __half* __restrict__ Tf) {
    __shared__ float t[32][33];
    const int tx = threadIdx.x, ty = threadIdx.y;
    const int n0 = blockIdx.x * 32, k0 = blockIdx.y * 32;
#pragma unroll
    for (int i = 0; i < 4; ++i)
        t[ty + i * 8][tx] = W[(size_t)(k0 + ty + i * 8) * E_ + n0 + tx];
    __syncthreads();
#pragma unroll
    for (int i = 0; i < 4; ++i) {
        float v = t[tx][ty + i * 8];
        Tf[(size_t)(n0 + ty + i * 8) * E_ + k0 + tx] = __float2half_rn(v);
    }
}

// ---------------------------------------------------------------------------
// RoPE from fused fp32 buffer -> fp16
// ---------------------------------------------------------------------------
__global__ __launch_bounds__(256)
void rope_f16_kernel(const float* __restrict__ qkv, __half* __restrict__ out,
                     int nh, int colbase) {
    int idx = blockIdx.x * blockDim.x + threadIdx.x;
    int total = B_ * T_ * nh * 32;
    if (idx >= total) return;
    int i = idx & 31;
    int h = (idx >> 5) % nh;
    int t = (idx / (32 * nh)) % T_;
    int b = idx / (32 * nh * T_);

    float inv_freq = expf(-(float)i * (9.210340371976184f / 32.0f));
    float ang = (float)t * inv_freq;
    float c = cosf(ang), s = sinf(ang);

    size_t row = (size_t)(b * T_ + t);
    const float* src = qkv + row * NQK + colbase + h * 64;
    float x1 = src[i];
    float x2 = src[32 + i];
    __half* dst = out + row * nh * 64 + h * 64;
    dst[i]      = __float2half_rn(x1 * c - x2 * s);
    dst[32 + i] = __float2half_rn(x2 * c + x1 * s);
}

// ---------------------------------------------------------------------------
// FA2-style causal attention, fp16 mma.sync. Writes Yf fp16.
// ---------------------------------------------------------------------------
#define AROWB 144
#define KVREG (64 * AROWB)              // 9216
#define KVBUF (2 * KVREG)               // 18432
#define QREG  (128 * AROWB)             // 18432
#define ATT_SMEM (QREG + 2 * KVBUF)     // 55296

__global__ __launch_bounds__(256)
void attn_f16_kernel(__half* __restrict__ Yf,
                     const __half* __restrict__ Qf, const __half* __restrict__ Kf,
                     const __half* __restrict__ Vf) {
    extern __shared__ char smem[];
    const uint32_t sbase = smem_u32(smem);
    const uint32_t sQ = sbase;
    const uint32_t sKV = sbase + QREG;

    const int tid = threadIdx.x;
    const int wid = tid >> 5, lane = tid & 31;
    const int qb = blockIdx.x;
    const int h  = blockIdx.y;
    const int b  = blockIdx.z;
    const int kh = h >> 2;
    const int bT0 = b * T_;

    const int row0 = qb * 128 + wid * 16 + (lane >> 2);
    const int row1 = row0 + 8;
    const int rowmin_w = qb * 128 + wid * 16;
    const int rowmax_w = rowmin_w + 15;

#pragma unroll
    for (int j = 0; j < 4; ++j) {
        int c = tid + j * 256;
        int row = c >> 3, part = c & 7;
        cp_async16(sQ + row * AROWB + part * 16,
                   Qf + (size_t)(bT0 + qb * 128 + row) * (H_ * D_) + h * 64 + part * 8);
    }
#pragma unroll
    for (int j = 0; j < 4; ++j) {
        int c = tid + j * 256;
        int reg = c >> 9, idx = c & 511;
        int row = idx >> 3, part = idx & 7;
        const __half* src = reg ? Vf : Kf;
        cp_async16(sKV + reg * KVREG + row * AROWB + part * 16,
                   src + (size_t)(bT0 + row) * (HKV_ * D_) + kh * 64 + part * 8);
    }
    CP_COMMIT();
    CP_WAIT(0);
    __syncthreads();

    uint32_t qf[4][4];
#pragma unroll
    for (int ks = 0; ks < 4; ++ks) {
        uint32_t qa = (wid * 16 + (lane & 15)) * AROWB + ks * 32 + (lane >> 4) * 16;
        ldmx4(qf[ks], sQ + qa);
    }

    float o[8][4];
#pragma unroll
    for (int j = 0; j < 8; ++j)
#pragma unroll
        for (int k = 0; k < 4; ++k) o[j][k] = 0.0f;
    float m0 = -1e30f, m1 = -1e30f, l0 = 0.0f, l1 = 0.0f;
    const float scale = 0.125f;

    const int NT = 2 * qb + 2;
    for (int it = 0; it < NT; ++it) {
        if (it + 1 < NT) {
            uint32_t sb = sKV + ((it + 1) & 1) * KVBUF;
#pragma unroll
            for (int j = 0; j < 4; ++j) {
                int c = tid + j * 256;
                int reg = c >> 9, idx = c & 511;
                int row = idx >> 3, part = idx & 7;
                const __half* src = reg ? Vf : Kf;
                cp_async16(sb + reg * KVREG + row * AROWB + part * 16,
                           src + (size_t)(bT0 + (it + 1) * 64 + row) * (HKV_ * D_) + kh * 64 + part * 8);
            }
            CP_COMMIT();
            CP_WAIT(1);
        } else {
            CP_WAIT(0);
        }
        __syncthreads();

        const int kt = it;
        if (kt * 64 <= rowmax_w) {
            const uint32_t sb = sKV + (it & 1) * KVBUF;
            const uint32_t sK = sb, sV = sb + KVREG;

            float s[8][4];
#pragma unroll
            for (int j = 0; j < 8; ++j)
#pragma unroll
                for (int k = 0; k < 4; ++k) s[j][k] = 0.0f;

#pragma unroll
            for (int ks = 0; ks < 4; ++ks) {
#pragma unroll
                for (int pg = 0; pg < 2; ++pg) {
                    uint32_t kf[2][4];
#pragma unroll
                    for (int pp = 0; pp < 2; ++pp) {
                        uint32_t ka = ((2 * pg + pp) * 16 + (lane & 15)) * AROWB + ks * 32 + (lane >> 4) * 16;
                        ldmx4(kf[pp], sK + ka);
                    }
#pragma unroll
                    for (int pp = 0; pp < 2; ++pp)
#pragma unroll
                        for (int q = 0; q < 2; ++q)
                            mma_f16(s[(2 * pg + pp) * 2 + q], qf[ks], kf[pp][q], kf[pp][q + 2]);
                }
            }

            const bool needs_mask = (kt * 64 + 63) > rowmin_w;
#pragma unroll
            for (int j = 0; j < 8; ++j) {
#pragma unroll
                for (int k = 0; k < 4; ++k) s[j][k] *= scale;
                if (needs_mask) {
                    int colb = kt * 64 + j * 8 + 2 * (lane & 3);
                    if (colb > row0)     s[j][0] = -1e30f;
                    if (colb + 1 > row0) s[j][1] = -1e30f;
                    if (colb > row1)     s[j][2] = -1e30f;
                    if (colb + 1 > row1) s[j][3] = -1e30f;
                }
            }

            float mx0 = -1e30f, mx1 = -1e30f;
#pragma unroll
            for (int j = 0; j < 8; ++j) {
                mx0 = fmaxf(mx0, fmaxf(s[j][0], s[j][1]));
                mx1 = fmaxf(mx1, fmaxf(s[j][2], s[j][3]));
            }
            mx0 = fmaxf(mx0, __shfl_xor_sync(0xFFFFFFFF, mx0, 1));
            mx0 = fmaxf(mx0, __shfl_xor_sync(0xFFFFFFFF, mx0, 2));
            mx1 = fmaxf(mx1, __shfl_xor_sync(0xFFFFFFFF, mx1, 1));
            mx1 = fmaxf(mx1, __shfl_xor_sync(0xFFFFFFFF, mx1, 2));

            float mn0 = fmaxf(m0, mx0), mn1 = fmaxf(m1, mx1);
            float c0 = __expf(m0 - mn0), c1 = __expf(m1 - mn1);
            m0 = mn0; m1 = mn1;
            l0 *= c0; l1 *= c1;
#pragma unroll
            for (int j = 0; j < 8; ++j) {
                o[j][0] *= c0; o[j][1] *= c0; o[j][2] *= c1; o[j][3] *= c1;
            }
#pragma unroll
            for (int j = 0; j < 8; ++j) {
                s[j][0] = __expf(s[j][0] - mn0);
                s[j][1] = __expf(s[j][1] - mn0);
                s[j][2] = __expf(s[j][2] - mn1);
                s[j][3] = __expf(s[j][3] - mn1);
                l0 += s[j][0] + s[j][1];
                l1 += s[j][2] + s[j][3];
            }

#pragma unroll
            for (int ks = 0; ks < 4; ++ks) {
                uint32_t pa[4];
                pa[0] = pack_h2(s[2 * ks][0], s[2 * ks][1]);
                pa[1] = pack_h2(s[2 * ks][2], s[2 * ks][3]);
                pa[2] = pack_h2(s[2 * ks + 1][0], s[2 * ks + 1][1]);
                pa[3] = pack_h2(s[2 * ks + 1][2], s[2 * ks + 1][3]);
#pragma unroll
                for (int pg = 0; pg < 2; ++pg) {
                    uint32_t vf[2][4];
#pragma unroll
                    for (int pp = 0; pp < 2; ++pp) {
                        uint32_t va = (ks * 16 + (lane & 15)) * AROWB + (2 * pg + pp) * 32 + (lane >> 4) * 16;
                        ldmx4t(vf[pp], sV + va);
                    }
#pragma unroll
                    for (int pp = 0; pp < 2; ++pp)
#pragma unroll
                        for (int q = 0; q < 2; ++q)
                            mma_f16(o[(2 * pg + pp) * 2 + q], pa, vf[pp][2 * q], vf[pp][2 * q + 1]);
                }
            }
        }
        __syncthreads();
    }

    l0 += __shfl_xor_sync(0xFFFFFFFF, l0, 1);
    l0 += __shfl_xor_sync(0xFFFFFFFF, l0, 2);
    l1 += __shfl_xor_sync(0xFFFFFFFF, l1, 1);
    l1 += __shfl_xor_sync(0xFFFFFFFF, l1, 2);
    float inv0 = 1.0f / l0, inv1 = 1.0f / l1;

#pragma unroll
    for (int j = 0; j < 8; ++j) {
        int col = j * 8 + 2 * (lane & 3);
        size_t a0 = ((size_t)(bT0 + row0) * H_ + h) * 64 + col;
        size_t a1 = ((size_t)(bT0 + row1) * H_ + h) * 64 + col;
        *(uint32_t*)&Yf[a0] = pack_h2(o[j][0] * inv0, o[j][1] * inv0);
        *(uint32_t*)&Yf[a1] = pack_h2(o[j][2] * inv1, o[j][3] * inv1);
    }
}

// ---------------------------------------------------------------------------
// kernel_launch — QKV gemm stays our 4th launch (ncu capture target)
// ---------------------------------------------------------------------------
extern "C" void kernel_launch(void* const* d_in, const int* in_sizes, int n_in,
                              void* d_out, int out_size) {
    const float* x  = (const float*)d_in[0];
    const float* Wq = (const float*)d_in[1];
    const float* Wk = (const float*)d_in[2];
    const float* Wv = (const float*)d_in[3];
    const float* Wo = (const float*)d_in[4];
    float* out = (float*)d_out;

    float* pQKV;
    cudaGetSymbolAddress((void**)&pQKV, g_QKV);
    __half *pxf, *pQf, *pKf, *pVf, *pYf, *pWcf, *pWof;
    cudaGetSymbolAddress((void**)&pxf, g_xf);
    cudaGetSymbolAddress((void**)&pQf, g_Qf);
    cudaGetSymbolAddress((void**)&pKf, g_Kf);
    cudaGetSymbolAddress((void**)&pVf, g_Vf);
    cudaGetSymbolAddress((void**)&pYf, g_Yf);
    cudaGetSymbolAddress((void**)&pWcf, g_Wcf);
    cudaGetSymbolAddress((void**)&pWof, g_Wof);

    cudaFuncSetAttribute(gemm1_kernel, cudaFuncAttributeMaxDynamicSharedMemorySize, G1_SMEM);
    cudaFuncSetAttribute(attn_f16_kernel, cudaFuncAttributeMaxDynamicSharedMemorySize, ATT_SMEM);

    // #1 x -> fp16
    {
        int n4 = (BT_ * E_) / 4;
        cvt_f16_kernel<<<(n4 + 255) / 256, 256>>>(x, pxf, n4);
    }
    // #2 fused transpose Wq|Wk|Wv -> fp16 concat
    tsplit3_kernel<<<dim3(64, 64, 3), dim3(32, 8)>>>(Wq, Wk, Wv, pWcf);
    // #3 transpose Wo -> fp16
    twof16_kernel<<<dim3(64, 64), dim3(32, 8)>>>(Wo, pWof);

    // #4 fused QKV projection, single-term fp16, wide warp tiles (ncu target)
    gemm1_kernel<<<dim3(NQKV / 128, BT_ / 128), 128, G1_SMEM>>>(
        pQKV, pVf, pxf, pWcf, BT_, NQKV, E_, 1);

    // #5, #6 RoPE -> fp16
    {
        int nq = B_ * T_ * H_ * 32;
        rope_f16_kernel<<<(nq + 255) / 256, 256>>>(pQKV, pQf, H_, 0);
        int nk = B_ * T_ * HKV_ * 32;
        rope_f16_kernel<<<(nk + 255) / 256, 256>>>(pQKV, pKf, HKV_, 2048);
    }

    // #7 attention
    attn_f16_kernel<<<dim3(T_ / 128, H_, B_), 256, ATT_SMEM>>>(pYf, pQf, pKf, pVf);

    // #8 output projection, single-term fp16
    gemm1_kernel<<<dim3(E_ / 128, BT_ / 128), 128, G1_SMEM>>>(
        out, nullptr, pYf, pWof, BT_, E_, E_, 0);
}

// round 10
// speedup vs baseline: 2.8459x; 1.0898x over previous
#include <cuda_runtime.h>
#include <cuda_bf16.h>
#include <cuda_fp16.h>
#include <cstdint>
#include <math.h>

// Problem constants
#define B_  2
#define T_  2048
#define E_  2048
#define H_  32
#define HKV_ 8
#define D_  64
#define BT_ (B_*T_)  // 4096
#define NQKV 3072    // 2048 Q + 512 K + 512 V

// ---------------------------------------------------------------------------
// Scratch (static device globals — allocation-free rule)
// ---------------------------------------------------------------------------
__device__ __half g_xf[BT_ * E_];               // x in fp16
__device__ __half g_Qf[BT_ * H_ * D_];          // post-rope Q fp16
__device__ __half g_Kf[BT_ * HKV_ * D_];        // post-rope K fp16
__device__ __half g_Vf[BT_ * HKV_ * D_];
__device__ __half g_Yf[BT_ * E_];               // attention output fp16
__device__ __half g_Wcf[NQKV * E_];             // concat Wq|Wk|Wv transposed [N,K] fp16
__device__ __half g_Wof[E_ * E_];               // Wo transposed fp16
__device__ float2 g_tab[T_ * 32];               // rope cos/sin table

// ---------------------------------------------------------------------------
// PTX helpers
// ---------------------------------------------------------------------------
__device__ __forceinline__ uint32_t smem_u32(const void* p) {
    uint32_t a;
    asm("{ .reg .u64 t; cvta.to.shared.u64 t, %1; cvt.u32.u64 %0, t; }" : "=r"(a) : "l"(p));
    return a;
}
__device__ __forceinline__ void ldmx4(uint32_t* r, uint32_t addr) {
    asm volatile("ldmatrix.sync.aligned.m8n8.x4.shared.b16 {%0,%1,%2,%3}, [%4];"
                 : "=r"(r[0]), "=r"(r[1]), "=r"(r[2]), "=r"(r[3]) : "r"(addr));
}
__device__ __forceinline__ void ldmx4t(uint32_t* r, uint32_t addr) {
    asm volatile("ldmatrix.sync.aligned.m8n8.x4.trans.shared.b16 {%0,%1,%2,%3}, [%4];"
                 : "=r"(r[0]), "=r"(r[1]), "=r"(r[2]), "=r"(r[3]) : "r"(addr));
}
__device__ __forceinline__ void mma_f16(float* acc, const uint32_t* a, const uint32_t b0,
                                        const uint32_t b1) {
    asm volatile(
        "mma.sync.aligned.m16n8k16.row.col.f32.f16.f16.f32 "
        "{%0,%1,%2,%3}, {%4,%5,%6,%7}, {%8,%9}, {%0,%1,%2,%3};"
        : "+f"(acc[0]), "+f"(acc[1]), "+f"(acc[2]), "+f"(acc[3])
        : "r"(a[0]), "r"(a[1]), "r"(a[2]), "r"(a[3]), "r"(b0), "r"(b1));
}
__device__ __forceinline__ void cp_async16(uint32_t saddr, const void* gaddr) {
    asm volatile("cp.async.cg.shared.global [%0], [%1], 16;" :: "r"(saddr), "l"(gaddr));
}
#define CP_COMMIT() asm volatile("cp.async.commit_group;" ::: "memory")
#define CP_WAIT(n)  asm volatile("cp.async.wait_group %0;" :: "n"(n) : "memory")

__device__ __forceinline__ uint32_t pack_h2(float lo, float hi) {
    __half2 v = __floats2half2_rn(lo, hi);
    return *reinterpret_cast<uint32_t*>(&v);
}

#define ROWB   80
#define REGB   (128 * ROWB)          // 10240 bytes per 128-row region

// ---------------------------------------------------------------------------
// gemm1: single-term fp16 GEMM, wide warp tiles, 3-stage cp.async pipeline.
// A[M,K], B[N,K] fp16. CTA tile 128x128, BK=32, 128 threads (4 warps),
// warp tile 64x64. One __syncthreads per iteration.
// mode 0: plain fp32 out stride N.
// mode 1: fused QKV epilogue with in-register RoPE:
//   warp col-block (64 wide) == one head. cols < 2048 -> rope -> Qf fp16;
//   cols [2048,2560) -> rope -> Kf fp16; cols >= 2560 -> Vf fp16.
// ---------------------------------------------------------------------------
#define G1_STG (2 * REGB)            // A + B regions = 20480
#define NSTG   3
#define G1_SMEM (NSTG * G1_STG)      // 61440 (3 CTAs/SM with 128 thr, 165 regs)

__device__ __forceinline__ void g1_issue(uint32_t sbuf, const __half* a, const __half* b,
                                         int K, int tid) {
    const __half* srcs[2] = {a, b};
#pragma unroll
    for (int reg = 0; reg < 2; ++reg) {
        const __half* s = srcs[reg];
        uint32_t sr = sbuf + reg * REGB;
#pragma unroll
        for (int j = 0; j < 4; ++j) {
            int c = tid + j * 128;          // 0..511
            int row = c >> 2, part = c & 3;
            cp_async16(sr + row * ROWB + part * 16, s + (size_t)row * K + part * 8);
        }
    }
}

__global__ __launch_bounds__(128)
void gemm1_kernel(float* __restrict__ C,
                  __half* __restrict__ Oq, __half* __restrict__ Ok, __half* __restrict__ Ov,
                  const float2* __restrict__ tab,
                  const __half* __restrict__ A, const __half* __restrict__ B,
                  int M, int N, int K, int mode) {
    extern __shared__ char smem[];
    const uint32_t sbase = smem_u32(smem);
    const int tid = threadIdx.x;
    const int wid = tid >> 5, lane = tid & 31;
    const int warp_m = wid >> 1;          // 0..1 -> 64-row slab
    const int warp_n = wid & 1;           // 0..1 -> 64-col slab
    const int bm = blockIdx.y * 128, bn = blockIdx.x * 128;

    const __half* pA = A + (size_t)bm * K;
    const __half* pB = B + (size_t)bn * K;

    float acc[4][8][4];
#pragma unroll
    for (int i = 0; i < 4; ++i)
#pragma unroll
        for (int j = 0; j < 8; ++j)
#pragma unroll
            for (int k = 0; k < 4; ++k) acc[i][j][k] = 0.0f;

    const int NIT = K / 32;               // 64

    const uint32_t a_row = warp_m * 64 + (lane & 15);
    const uint32_t a_coff = (lane >> 4) * 16;
    const uint32_t b_rowbase = warp_n * 64 + (lane & 15);
    const uint32_t b_coff = (lane >> 4) * 16;

    // Prologue: stages 0, 1
#pragma unroll
    for (int s = 0; s < NSTG - 1; ++s) {
        g1_issue(sbase + s * G1_STG, pA + s * 32, pB + s * 32, K, tid);
        CP_COMMIT();
    }

    int buf = 0;
    for (int it = 0; it < NIT; ++it) {
        CP_WAIT(NSTG - 2);               // stage `it` resident
        __syncthreads();                 // all warps done with buffer being refilled

        const int nx = it + NSTG - 1;
        if (nx < NIT) {
            int nbuf = buf + (NSTG - 1); if (nbuf >= NSTG) nbuf -= NSTG;
            g1_issue(sbase + nbuf * G1_STG, pA + nx * 32, pB + nx * 32, K, tid);
        }
        CP_COMMIT();                     // empty group near tail keeps counts aligned

        const uint32_t sbuf = sbase + buf * G1_STG;
        const uint32_t sA = sbuf, sB = sbuf + REGB;
#pragma unroll
        for (int ks = 0; ks < 2; ++ks) {
            const uint32_t kb = ks * 32;
            uint32_t bf[16];
#pragma unroll
            for (int p = 0; p < 4; ++p) {
                uint32_t ba = (b_rowbase + p * 16) * ROWB + kb + b_coff;
                ldmx4(&bf[p * 4], sB + ba);
            }
            uint32_t af[4][4];
#pragma unroll
            for (int mi = 0; mi < 4; ++mi) {
                uint32_t aa = (a_row + mi * 16) * ROWB + kb + a_coff;
                ldmx4(af[mi], sA + aa);
            }
#pragma unroll
            for (int mi = 0; mi < 4; ++mi)
#pragma unroll
                for (int ni = 0; ni < 8; ++ni) {
                    const int p = ni >> 1, q = ni & 1;
                    mma_f16(acc[mi][ni], af[mi], bf[p * 4 + q], bf[p * 4 + q + 2]);
                }
        }
        if (++buf == NSTG) buf = 0;
    }

    const int rbase = bm + warp_m * 64 + (lane >> 2);
    const int j0 = (lane & 3) * 2;             // col-in-head base, < 8
    const int ch = bn + warp_n * 64;           // warp's global col base (one head)

    if (mode == 0) {
        const int cbase = ch + j0;
#pragma unroll
        for (int mi = 0; mi < 4; ++mi)
#pragma unroll
            for (int ni = 0; ni < 8; ++ni) {
                float* c0 = C + (size_t)(rbase + mi * 16) * N + cbase + ni * 8;
                float* c1 = C + (size_t)(rbase + mi * 16 + 8) * N + cbase + ni * 8;
                *(float2*)c0 = make_float2(acc[mi][ni][0], acc[mi][ni][1]);
                *(float2*)c1 = make_float2(acc[mi][ni][2], acc[mi][ni][3]);
            }
        return;
    }

    if (ch < 2560) {
        // Q or K: apply RoPE in-register, store fp16
        __half* dst;
        int ldc, cofs;
        if (ch < 2048) { dst = Oq; ldc = H_ * D_;  cofs = ch; }
        else           { dst = Ok; ldc = HKV_ * D_; cofs = ch - 2048; }
#pragma unroll
        for (int mi = 0; mi < 4; ++mi) {
#pragma unroll
            for (int hf = 0; hf < 2; ++hf) {
                const int r = rbase + mi * 16 + hf * 8;
                const int t = r & (T_ - 1);
                const float2* trow = tab + t * 32;
#pragma unroll
                for (int ni0 = 0; ni0 < 4; ++ni0) {
                    const int j = j0 + ni0 * 8;          // < 32
                    float a1 = acc[mi][ni0][2 * hf + 0];
                    float a2 = acc[mi][ni0][2 * hf + 1];
                    float b1 = acc[mi][ni0 + 4][2 * hf + 0];
                    float b2 = acc[mi][ni0 + 4][2 * hf + 1];
                    float2 cs1 = trow[j];
                    float2 cs2 = trow[j + 1];
                    float o1 = a1 * cs1.x - b1 * cs1.y;
                    float p1 = b1 * cs1.x + a1 * cs1.y;
                    float o2 = a2 * cs2.x - b2 * cs2.y;
                    float p2 = b2 * cs2.x + a2 * cs2.y;
                    size_t base = (size_t)r * ldc + cofs + j;
                    *(uint32_t*)&dst[base]      = pack_h2(o1, o2);
                    *(uint32_t*)&dst[base + 32] = pack_h2(p1, p2);
                }
            }
        }
    } else {
        // V: plain fp16 store
        const int cbase = ch - 2560 + j0;
#pragma unroll
        for (int mi = 0; mi < 4; ++mi)
#pragma unroll
            for (int ni = 0; ni < 8; ++ni) {
                *(uint32_t*)&Ov[(size_t)(rbase + mi * 16) * 512 + cbase + ni * 8] =
                    pack_h2(acc[mi][ni][0], acc[mi][ni][1]);
                *(uint32_t*)&Ov[(size_t)(rbase + mi * 16 + 8) * 512 + cbase + ni * 8] =
                    pack_h2(acc[mi][ni][2], acc[mi][ni][3]);
            }
    }
}

// ---------------------------------------------------------------------------
// Rope table: tab[t*32+i] = (cos, sin)(t * 10000^(-i/32))
// ---------------------------------------------------------------------------
__global__ __launch_bounds__(256)
void rope_tab_kernel(float2* __restrict__ tab) {
    int idx = blockIdx.x * blockDim.x + threadIdx.x;
    if (idx >= T_ * 32) return;
    int i = idx & 31, t = idx >> 5;
    float inv_freq = expf(-(float)i * (9.210340371976184f / 32.0f));
    float ang = (float)t * inv_freq;
    tab[idx] = make_float2(cosf(ang), sinf(ang));
}

// ---------------------------------------------------------------------------
// fp32 -> fp16 convert (vectorized x4)
// ---------------------------------------------------------------------------
__global__ __launch_bounds__(256)
void cvt_f16_kernel(const float* __restrict__ in, __half* __restrict__ out, int n4) {
    int i = blockIdx.x * blockDim.x + threadIdx.x;
    if (i >= n4) return;
    float4 v = ((const float4*)in)[i];
    ((uint2*)out)[i] = make_uint2(pack_h2(v.x, v.y), pack_h2(v.z, v.w));
}

// ---------------------------------------------------------------------------
// Fused transpose of Wq|Wk|Wv into concat fp16 buffer [NQKV, E]
// ---------------------------------------------------------------------------
__global__ __launch_bounds__(256)
void tsplit3_kernel(const float* __restrict__ Wq, const float* __restrict__ Wk,
                    const float* __restrict__ Wv, __half* __restrict__ Tf) {
    __shared__ float t[32][33];
    const int z = blockIdx.z;
    const float* W = (z == 0) ? Wq : (z == 1) ? Wk : Wv;
    const int N = (z == 0) ? (H_ * D_) : (HKV_ * D_);
    const int nofs = (z == 0) ? 0 : (z == 1) ? 2048 : 2560;
    const int n0 = blockIdx.x * 32, k0 = blockIdx.y * 32;
    if (n0 >= N) return;
    const int tx = threadIdx.x, ty = threadIdx.y;
#pragma unroll
    for (int i = 0; i < 4; ++i)
        t[ty + i * 8][tx] = W[(size_t)(k0 + ty + i * 8) * N + n0 + tx];
    __syncthreads();
#pragma unroll
    for (int i = 0; i < 4; ++i) {
        float v = t[tx][ty + i * 8];
        Tf[(size_t)(nofs + n0 + ty + i * 8) * E_ + k0 + tx] = __float2half_rn(v);
    }
}

// ---------------------------------------------------------------------------
// Transpose Wo -> fp16 [N,K]
// ---------------------------------------------------------------------------
__global__ __launch_bounds__(256)
void twof16_kernel(const float* __restrict__ W, __half* __restrict__ Tf) {
    __shared__ float t[32][33];
    const int tx = threadIdx.x, ty = threadIdx.y;
    const int n0 = blockIdx.x * 32, k0 = blockIdx.y * 32;
#pragma unroll
    for (int i = 0; i < 4; ++i)
        t[ty + i * 8][tx] = W[(size_t)(k0 + ty + i * 8) * E_ + n0 + tx];
    __syncthreads();
#pragma unroll
    for (int i = 0; i < 4; ++i) {
        float v = t[tx][ty + i * 8];
        Tf[(size_t)(n0 + ty + i * 8) * E_ + k0 + tx] = __float2half_rn(v);
    }
}

// ---------------------------------------------------------------------------
// FA2-style causal attention, fp16 mma.sync. Writes Yf fp16.
// ---------------------------------------------------------------------------
#define AROWB 144
#define KVREG (64 * AROWB)              // 9216
#define KVBUF (2 * KVREG)               // 18432
#define QREG  (128 * AROWB)             // 18432
#define ATT_SMEM (QREG + 2 * KVBUF)     // 55296

__global__ __launch_bounds__(256)
void attn_f16_kernel(__half* __restrict__ Yf,
                     const __half* __restrict__ Qf, const __half* __restrict__ Kf,
                     const __half* __restrict__ Vf) {
    extern __shared__ char smem[];
    const uint32_t sbase = smem_u32(smem);
    const uint32_t sQ = sbase;
    const uint32_t sKV = sbase + QREG;

    const int tid = threadIdx.x;
    const int wid = tid >> 5, lane = tid & 31;
    const int qb = blockIdx.x;
    const int h  = blockIdx.y;
    const int b  = blockIdx.z;
    const int kh = h >> 2;
    const int bT0 = b * T_;

    const int row0 = qb * 128 + wid * 16 + (lane >> 2);
    const int row1 = row0 + 8;
    const int rowmin_w = qb * 128 + wid * 16;
    const int rowmax_w = rowmin_w + 15;

#pragma unroll
    for (int j = 0; j < 4; ++j) {
        int c = tid + j * 256;
        int row = c >> 3, part = c & 7;
        cp_async16(sQ + row * AROWB + part * 16,
                   Qf + (size_t)(bT0 + qb * 128 + row) * (H_ * D_) + h * 64 + part * 8);
    }
#pragma unroll
    for (int j = 0; j < 4; ++j) {
        int c = tid + j * 256;
        int reg = c >> 9, idx = c & 511;
        int row = idx >> 3, part = idx & 7;
        const __half* src = reg ? Vf : Kf;
        cp_async16(sKV + reg * KVREG + row * AROWB + part * 16,
                   src + (size_t)(bT0 + row) * (HKV_ * D_) + kh * 64 + part * 8);
    }
    CP_COMMIT();
    CP_WAIT(0);
    __syncthreads();

    uint32_t qf[4][4];
#pragma unroll
    for (int ks = 0; ks < 4; ++ks) {
        uint32_t qa = (wid * 16 + (lane & 15)) * AROWB + ks * 32 + (lane >> 4) * 16;
        ldmx4(qf[ks], sQ + qa);
    }

    float o[8][4];
#pragma unroll
    for (int j = 0; j < 8; ++j)
#pragma unroll
        for (int k = 0; k < 4; ++k) o[j][k] = 0.0f;
    float m0 = -1e30f, m1 = -1e30f, l0 = 0.0f, l1 = 0.0f;
    const float scale = 0.125f;

    const int NT = 2 * qb + 2;
    for (int it = 0; it < NT; ++it) {
        if (it + 1 < NT) {
            uint32_t sb = sKV + ((it + 1) & 1) * KVBUF;
#pragma unroll
            for (int j = 0; j < 4; ++j) {
                int c = tid + j * 256;
                int reg = c >> 9, idx = c & 511;
                int row = idx >> 3, part = idx & 7;
                const __half* src = reg ? Vf : Kf;
                cp_async16(sb + reg * KVREG + row * AROWB + part * 16,
                           src + (size_t)(bT0 + (it + 1) * 64 + row) * (HKV_ * D_) + kh * 64 + part * 8);
            }
            CP_COMMIT();
            CP_WAIT(1);
        } else {
            CP_WAIT(0);
        }
        __syncthreads();

        const int kt = it;
        if (kt * 64 <= rowmax_w) {
            const uint32_t sb = sKV + (it & 1) * KVBUF;
            const uint32_t sK = sb, sV = sb + KVREG;

            float s[8][4];
#pragma unroll
            for (int j = 0; j < 8; ++j)
#pragma unroll
                for (int k = 0; k < 4; ++k) s[j][k] = 0.0f;

#pragma unroll
            for (int ks = 0; ks < 4; ++ks) {
#pragma unroll
                for (int pg = 0; pg < 2; ++pg) {
                    uint32_t kf[2][4];
#pragma unroll
                    for (int pp = 0; pp < 2; ++pp) {
                        uint32_t ka = ((2 * pg + pp) * 16 + (lane & 15)) * AROWB + ks * 32 + (lane >> 4) * 16;
                        ldmx4(kf[pp], sK + ka);
                    }
#pragma unroll
                    for (int pp = 0; pp < 2; ++pp)
#pragma unroll
                        for (int q = 0; q < 2; ++q)
                            mma_f16(s[(2 * pg + pp) * 2 + q], qf[ks], kf[pp][q], kf[pp][q + 2]);
                }
            }

            const bool needs_mask = (kt * 64 + 63) > rowmin_w;
#pragma unroll
            for (int j = 0; j < 8; ++j) {
#pragma unroll
                for (int k = 0; k < 4; ++k) s[j][k] *= scale;
                if (needs_mask) {
                    int colb = kt * 64 + j * 8 + 2 * (lane & 3);
                    if (colb > row0)     s[j][0] = -1e30f;
                    if (colb + 1 > row0) s[j][1] = -1e30f;
                    if (colb > row1)     s[j][2] = -1e30f;
                    if (colb + 1 > row1) s[j][3] = -1e30f;
                }
            }

            float mx0 = -1e30f, mx1 = -1e30f;
#pragma unroll
            for (int j = 0; j < 8; ++j) {
                mx0 = fmaxf(mx0, fmaxf(s[j][0], s[j][1]));
                mx1 = fmaxf(mx1, fmaxf(s[j][2], s[j][3]));
            }
            mx0 = fmaxf(mx0, __shfl_xor_sync(0xFFFFFFFF, mx0, 1));
            mx0 = fmaxf(mx0, __shfl_xor_sync(0xFFFFFFFF, mx0, 2));
            mx1 = fmaxf(mx1, __shfl_xor_sync(0xFFFFFFFF, mx1, 1));
            mx1 = fmaxf(mx1, __shfl_xor_sync(0xFFFFFFFF, mx1, 2));

            float mn0 = fmaxf(m0, mx0), mn1 = fmaxf(m1, mx1);
            float c0 = __expf(m0 - mn0), c1 = __expf(m1 - mn1);
            m0 = mn0; m1 = mn1;
            l0 *= c0; l1 *= c1;
#pragma unroll
            for (int j = 0; j < 8; ++j) {
                o[j][0] *= c0; o[j][1] *= c0; o[j][2] *= c1; o[j][3] *= c1;
            }
#pragma unroll
            for (int j = 0; j < 8; ++j) {
                s[j][0] = __expf(s[j][0] - mn0);
                s[j][1] = __expf(s[j][1] - mn0);
                s[j][2] = __expf(s[j][2] - mn1);
                s[j][3] = __expf(s[j][3] - mn1);
                l0 += s[j][0] + s[j][1];
                l1 += s[j][2] + s[j][3];
            }

#pragma unroll
            for (int ks = 0; ks < 4; ++ks) {
                uint32_t pa[4];
                pa[0] = pack_h2(s[2 * ks][0], s[2 * ks][1]);
                pa[1] = pack_h2(s[2 * ks][2], s[2 * ks][3]);
                pa[2] = pack_h2(s[2 * ks + 1][0], s[2 * ks + 1][1]);
                pa[3] = pack_h2(s[2 * ks + 1][2], s[2 * ks + 1][3]);
#pragma unroll
                for (int pg = 0; pg < 2; ++pg) {
                    uint32_t vf[2][4];
#pragma unroll
                    for (int pp = 0; pp < 2; ++pp) {
                        uint32_t va = (ks * 16 + (lane & 15)) * AROWB + (2 * pg + pp) * 32 + (lane >> 4) * 16;
                        ldmx4t(vf[pp], sV + va);
                    }
#pragma unroll
                    for (int pp = 0; pp < 2; ++pp)
#pragma unroll
                        for (int q = 0; q < 2; ++q)
                            mma_f16(o[(2 * pg + pp) * 2 + q], pa, vf[pp][2 * q], vf[pp][2 * q + 1]);
                }
            }
        }
        __syncthreads();
    }

    l0 += __shfl_xor_sync(0xFFFFFFFF, l0, 1);
    l0 += __shfl_xor_sync(0xFFFFFFFF, l0, 2);
    l1 += __shfl_xor_sync(0xFFFFFFFF, l1, 1);
    l1 += __shfl_xor_sync(0xFFFFFFFF, l1, 2);
    float inv0 = 1.0f / l0, inv1 = 1.0f / l1;

#pragma unroll
    for (int j = 0; j < 8; ++j) {
        int col = j * 8 + 2 * (lane & 3);
        size_t a0 = ((size_t)(bT0 + row0) * H_ + h) * 64 + col;
        size_t a1 = ((size_t)(bT0 + row1) * H_ + h) * 64 + col;
        *(uint32_t*)&Yf[a0] = pack_h2(o[j][0] * inv0, o[j][1] * inv0);
        *(uint32_t*)&Yf[a1] = pack_h2(o[j][2] * inv1, o[j][3] * inv1);
    }
}

// ---------------------------------------------------------------------------
// kernel_launch — QKV gemm stays our 4th launch (ncu capture target)
// ---------------------------------------------------------------------------
extern "C" void kernel_launch(void* const* d_in, const int* in_sizes, int n_in,
                              void* d_out, int out_size) {
    const float* x  = (const float*)d_in[0];
    const float* Wq = (const float*)d_in[1];
    const float* Wk = (const float*)d_in[2];
    const float* Wv = (const float*)d_in[3];
    const float* Wo = (const float*)d_in[4];
    float* out = (float*)d_out;

    __half *pxf, *pQf, *pKf, *pVf, *pYf, *pWcf, *pWof;
    float2* ptab;
    cudaGetSymbolAddress((void**)&pxf, g_xf);
    cudaGetSymbolAddress((void**)&pQf, g_Qf);
    cudaGetSymbolAddress((void**)&pKf, g_Kf);
    cudaGetSymbolAddress((void**)&pVf, g_Vf);
    cudaGetSymbolAddress((void**)&pYf, g_Yf);
    cudaGetSymbolAddress((void**)&pWcf, g_Wcf);
    cudaGetSymbolAddress((void**)&pWof, g_Wof);
    cudaGetSymbolAddress((void**)&ptab, g_tab);

    cudaFuncSetAttribute(gemm1_kernel, cudaFuncAttributeMaxDynamicSharedMemorySize, G1_SMEM);
    cudaFuncSetAttribute(attn_f16_kernel, cudaFuncAttributeMaxDynamicSharedMemorySize, ATT_SMEM);

    // #1 rope cos/sin table
    rope_tab_kernel<<<(T_ * 32 + 255) / 256, 256>>>(ptab);
    // #2 x -> fp16
    {
        int n4 = (BT_ * E_) / 4;
        cvt_f16_kernel<<<(n4 + 255) / 256, 256>>>(x, pxf, n4);
    }
    // #3 fused transpose Wq|Wk|Wv -> fp16 concat
    tsplit3_kernel<<<dim3(64, 64, 3), dim3(32, 8)>>>(Wq, Wk, Wv, pWcf);

    // #4 fused QKV projection with in-epilogue RoPE (ncu capture target)
    gemm1_kernel<<<dim3(NQKV / 128, BT_ / 128), 128, G1_SMEM>>>(
        nullptr, pQf, pKf, pVf, ptab, pxf, pWcf, BT_, NQKV, E_, 1);

    // #5 transpose Wo -> fp16
    twof16_kernel<<<dim3(64, 64), dim3(32, 8)>>>(Wo, pWof);

    // #6 attention
    attn_f16_kernel<<<dim3(T_ / 128, H_, B_), 256, ATT_SMEM>>>(pYf, pQf, pKf, pVf);

    // #7 output projection, single-term fp16
    gemm1_kernel<<<dim3(E_ / 128, BT_ / 128), 128, G1_SMEM>>>(
        out, nullptr, nullptr, nullptr, nullptr, pYf, pWof, BT_, E_, E_, 0);
}

// round 11
// speedup vs baseline: 2.9068x; 1.0214x over previous
#include <cuda_runtime.h>
#include <cuda_bf16.h>
#include <cuda_fp16.h>
#include <cstdint>
#include <math.h>

// Problem constants
#define B_  2
#define T_  2048
#define E_  2048
#define H_  32
#define HKV_ 8
#define D_  64
#define BT_ (B_*T_)  // 4096
#define NQKV 3072    // 2048 Q + 512 K + 512 V

// ---------------------------------------------------------------------------
// Scratch (static device globals — allocation-free rule)
// ---------------------------------------------------------------------------
__device__ __half g_xf[BT_ * E_];               // x in fp16
__device__ __half g_Qf[BT_ * H_ * D_];          // post-rope Q fp16
__device__ __half g_Kf[BT_ * HKV_ * D_];        // post-rope K fp16
__device__ __half g_Vf[BT_ * HKV_ * D_];
__device__ __half g_Yf[BT_ * E_];               // attention output fp16
__device__ __half g_Wcf[NQKV * E_];             // concat Wq|Wk|Wv transposed [N,K] fp16
__device__ __half g_Wof[E_ * E_];               // Wo transposed fp16
__device__ float2 g_tab[T_ * 32];               // rope cos/sin table

// ---------------------------------------------------------------------------
// PTX helpers
// ---------------------------------------------------------------------------
__device__ __forceinline__ uint32_t smem_u32(const void* p) {
    uint32_t a;
    asm("{ .reg .u64 t; cvta.to.shared.u64 t, %1; cvt.u32.u64 %0, t; }" : "=r"(a) : "l"(p));
    return a;
}
__device__ __forceinline__ void ldmx4(uint32_t* r, uint32_t addr) {
    asm volatile("ldmatrix.sync.aligned.m8n8.x4.shared.b16 {%0,%1,%2,%3}, [%4];"
                 : "=r"(r[0]), "=r"(r[1]), "=r"(r[2]), "=r"(r[3]) : "r"(addr));
}
__device__ __forceinline__ void ldmx4t(uint32_t* r, uint32_t addr) {
    asm volatile("ldmatrix.sync.aligned.m8n8.x4.trans.shared.b16 {%0,%1,%2,%3}, [%4];"
                 : "=r"(r[0]), "=r"(r[1]), "=r"(r[2]), "=r"(r[3]) : "r"(addr));
}
__device__ __forceinline__ void mma_f16(float* acc, const uint32_t* a, const uint32_t b0,
                                        const uint32_t b1) {
    asm volatile(
        "mma.sync.aligned.m16n8k16.row.col.f32.f16.f16.f32 "
        "{%0,%1,%2,%3}, {%4,%5,%6,%7}, {%8,%9}, {%0,%1,%2,%3};"
        : "+f"(acc[0]), "+f"(acc[1]), "+f"(acc[2]), "+f"(acc[3])
        : "r"(a[0]), "r"(a[1]), "r"(a[2]), "r"(a[3]), "r"(b0), "r"(b1));
}
__device__ __forceinline__ void cp_async16(uint32_t saddr, const void* gaddr) {
    asm volatile("cp.async.cg.shared.global [%0], [%1], 16;" :: "r"(saddr), "l"(gaddr));
}
#define CP_COMMIT() asm volatile("cp.async.commit_group;" ::: "memory")
#define CP_WAIT(n)  asm volatile("cp.async.wait_group %0;" :: "n"(n) : "memory")

__device__ __forceinline__ uint32_t pack_h2(float lo, float hi) {
    __half2 v = __floats2half2_rn(lo, hi);
    return *reinterpret_cast<uint32_t*>(&v);
}

// ---------------------------------------------------------------------------
// gemm1: single-term fp16 GEMM, BK=64, 2-stage cp.async, race-safe ordering.
// A[M,K], B[N,K] fp16. CTA tile 128x128, 128 threads (4 warps), warp 64x64.
// Row layout: 128B data + 16B pad = 144B (conflict-free ldmatrix).
// mode 0: plain fp32 out stride N.
// mode 1: fused QKV epilogue with in-register RoPE (as round 10).
// ---------------------------------------------------------------------------
#define ROWB   144
#define REGB   (128 * ROWB)          // 18432 per region (128 rows x 64 halves)
#define G1_STG (2 * REGB)            // A + B = 36864
#define G1_SMEM (2 * G1_STG)         // 73728 (double buffered) -> 3 CTAs/SM

__device__ __forceinline__ void g1_issue(uint32_t sbuf, const __half* a, const __half* b,
                                         int K, int tid) {
    const __half* srcs[2] = {a, b};
#pragma unroll
    for (int reg = 0; reg < 2; ++reg) {
        const __half* s = srcs[reg];
        uint32_t sr = sbuf + reg * REGB;
#pragma unroll
        for (int j = 0; j < 8; ++j) {
            int c = tid + j * 128;          // 0..1023
            int row = c >> 3, part = c & 7;
            cp_async16(sr + row * ROWB + part * 16, s + (size_t)row * K + part * 8);
        }
    }
}

__global__ __launch_bounds__(128)
void gemm1_kernel(float* __restrict__ C,
                  __half* __restrict__ Oq, __half* __restrict__ Ok, __half* __restrict__ Ov,
                  const float2* __restrict__ tab,
                  const __half* __restrict__ A, const __half* __restrict__ B,
                  int M, int N, int K, int mode) {
    extern __shared__ char smem[];
    const uint32_t sbase = smem_u32(smem);
    const int tid = threadIdx.x;
    const int wid = tid >> 5, lane = tid & 31;
    const int warp_m = wid >> 1;          // 0..1 -> 64-row slab
    const int warp_n = wid & 1;           // 0..1 -> 64-col slab
    const int bm = blockIdx.y * 128, bn = blockIdx.x * 128;

    const __half* pA = A + (size_t)bm * K;
    const __half* pB = B + (size_t)bn * K;

    float acc[4][8][4];
#pragma unroll
    for (int i = 0; i < 4; ++i)
#pragma unroll
        for (int j = 0; j < 8; ++j)
#pragma unroll
            for (int k = 0; k < 4; ++k) acc[i][j][k] = 0.0f;

    const int NIT = K / 64;               // 32

    const uint32_t a_row = warp_m * 64 + (lane & 15);
    const uint32_t a_coff = (lane >> 4) * 16;
    const uint32_t b_rowbase = warp_n * 64 + (lane & 15);
    const uint32_t b_coff = (lane >> 4) * 16;

    g1_issue(sbase, pA, pB, K, tid);
    CP_COMMIT();

    int buf = 0;
    for (int it = 0; it < NIT; ++it) {
        CP_WAIT(0);                      // current stage resident
        __syncthreads();                 // everyone done with the other buffer
        if (it + 1 < NIT) {
            g1_issue(sbase + (buf ^ 1) * G1_STG,
                     pA + (it + 1) * 64, pB + (it + 1) * 64, K, tid);
            CP_COMMIT();
        }

        const uint32_t sbuf = sbase + buf * G1_STG;
        const uint32_t sA = sbuf, sB = sbuf + REGB;
#pragma unroll
        for (int ks = 0; ks < 4; ++ks) {
            const uint32_t kb = ks * 32;
            uint32_t bf[16];
#pragma unroll
            for (int p = 0; p < 4; ++p) {
                uint32_t ba = (b_rowbase + p * 16) * ROWB + kb + b_coff;
                ldmx4(&bf[p * 4], sB + ba);
            }
            uint32_t af[4][4];
#pragma unroll
            for (int mi = 0; mi < 4; ++mi) {
                uint32_t aa = (a_row + mi * 16) * ROWB + kb + a_coff;
                ldmx4(af[mi], sA + aa);
            }
#pragma unroll
            for (int mi = 0; mi < 4; ++mi)
#pragma unroll
                for (int ni = 0; ni < 8; ++ni) {
                    const int p = ni >> 1, q = ni & 1;
                    mma_f16(acc[mi][ni], af[mi], bf[p * 4 + q], bf[p * 4 + q + 2]);
                }
        }
        buf ^= 1;
    }

    const int rbase = bm + warp_m * 64 + (lane >> 2);
    const int j0 = (lane & 3) * 2;             // col-in-head base, < 8
    const int ch = bn + warp_n * 64;           // warp's global col base (one head)

    if (mode == 0) {
        const int cbase = ch + j0;
#pragma unroll
        for (int mi = 0; mi < 4; ++mi)
#pragma unroll
            for (int ni = 0; ni < 8; ++ni) {
                float* c0 = C + (size_t)(rbase + mi * 16) * N + cbase + ni * 8;
                float* c1 = C + (size_t)(rbase + mi * 16 + 8) * N + cbase + ni * 8;
                *(float2*)c0 = make_float2(acc[mi][ni][0], acc[mi][ni][1]);
                *(float2*)c1 = make_float2(acc[mi][ni][2], acc[mi][ni][3]);
            }
        return;
    }

    if (ch < 2560) {
        // Q or K: apply RoPE in-register, store fp16
        __half* dst;
        int ldc, cofs;
        if (ch < 2048) { dst = Oq; ldc = H_ * D_;  cofs = ch; }
        else           { dst = Ok; ldc = HKV_ * D_; cofs = ch - 2048; }
#pragma unroll
        for (int mi = 0; mi < 4; ++mi) {
#pragma unroll
            for (int hf = 0; hf < 2; ++hf) {
                const int r = rbase + mi * 16 + hf * 8;
                const int t = r & (T_ - 1);
                const float2* trow = tab + t * 32;
#pragma unroll
                for (int ni0 = 0; ni0 < 4; ++ni0) {
                    const int j = j0 + ni0 * 8;          // < 32
                    float a1 = acc[mi][ni0][2 * hf + 0];
                    float a2 = acc[mi][ni0][2 * hf + 1];
                    float b1 = acc[mi][ni0 + 4][2 * hf + 0];
                    float b2 = acc[mi][ni0 + 4][2 * hf + 1];
                    float2 cs1 = trow[j];
                    float2 cs2 = trow[j + 1];
                    float o1 = a1 * cs1.x - b1 * cs1.y;
                    float p1 = b1 * cs1.x + a1 * cs1.y;
                    float o2 = a2 * cs2.x - b2 * cs2.y;
                    float p2 = b2 * cs2.x + a2 * cs2.y;
                    size_t base = (size_t)r * ldc + cofs + j;
                    *(uint32_t*)&dst[base]      = pack_h2(o1, o2);
                    *(uint32_t*)&dst[base + 32] = pack_h2(p1, p2);
                }
            }
        }
    } else {
        // V: plain fp16 store
        const int cbase = ch - 2560 + j0;
#pragma unroll
        for (int mi = 0; mi < 4; ++mi)
#pragma unroll
            for (int ni = 0; ni < 8; ++ni) {
                *(uint32_t*)&Ov[(size_t)(rbase + mi * 16) * 512 + cbase + ni * 8] =
                    pack_h2(acc[mi][ni][0], acc[mi][ni][1]);
                *(uint32_t*)&Ov[(size_t)(rbase + mi * 16 + 8) * 512 + cbase + ni * 8] =
                    pack_h2(acc[mi][ni][2], acc[mi][ni][3]);
            }
    }
}

// ---------------------------------------------------------------------------
// Rope table: tab[t*32+i] = (cos, sin)(t * 10000^(-i/32))
// ---------------------------------------------------------------------------
__global__ __launch_bounds__(256)
void rope_tab_kernel(float2* __restrict__ tab) {
    int idx = blockIdx.x * blockDim.x + threadIdx.x;
    if (idx >= T_ * 32) return;
    int i = idx & 31, t = idx >> 5;
    float inv_freq = expf(-(float)i * (9.210340371976184f / 32.0f));
    float ang = (float)t * inv_freq;
    tab[idx] = make_float2(cosf(ang), sinf(ang));
}

// ---------------------------------------------------------------------------
// fp32 -> fp16 convert (vectorized x4)
// ---------------------------------------------------------------------------
__global__ __launch_bounds__(256)
void cvt_f16_kernel(const float* __restrict__ in, __half* __restrict__ out, int n4) {
    int i = blockIdx.x * blockDim.x + threadIdx.x;
    if (i >= n4) return;
    float4 v = ((const float4*)in)[i];
    ((uint2*)out)[i] = make_uint2(pack_h2(v.x, v.y), pack_h2(v.z, v.w));
}

// ---------------------------------------------------------------------------
// Fused transpose of Wq|Wk|Wv into concat fp16 buffer [NQKV, E]
// ---------------------------------------------------------------------------
__global__ __launch_bounds__(256)
void tsplit3_kernel(const float* __restrict__ Wq, const float* __restrict__ Wk,
                    const float* __restrict__ Wv, __half* __restrict__ Tf) {
    __shared__ float t[32][33];
    const int z = blockIdx.z;
    const float* W = (z == 0) ? Wq : (z == 1) ? Wk : Wv;
    const int N = (z == 0) ? (H_ * D_) : (HKV_ * D_);
    const int nofs = (z == 0) ? 0 : (z == 1) ? 2048 : 2560;
    const int n0 = blockIdx.x * 32, k0 = blockIdx.y * 32;
    if (n0 >= N) return;
    const int tx = threadIdx.x, ty = threadIdx.y;
#pragma unroll
    for (int i = 0; i < 4; ++i)
        t[ty + i * 8][tx] = W[(size_t)(k0 + ty + i * 8) * N + n0 + tx];
    __syncthreads();
#pragma unroll
    for (int i = 0; i < 4; ++i) {
        float v = t[tx][ty + i * 8];
        Tf[(size_t)(nofs + n0 + ty + i * 8) * E_ + k0 + tx] = __float2half_rn(v);
    }
}

// ---------------------------------------------------------------------------
// Transpose Wo -> fp16 [N,K]
// ---------------------------------------------------------------------------
__global__ __launch_bounds__(256)
void twof16_kernel(const float* __restrict__ W, __half* __restrict__ Tf) {
    __shared__ float t[32][33];
    const int tx = threadIdx.x, ty = threadIdx.y;
    const int n0 = blockIdx.x * 32, k0 = blockIdx.y * 32;
#pragma unroll
    for (int i = 0; i < 4; ++i)
        t[ty + i * 8][tx] = W[(size_t)(k0 + ty + i * 8) * E_ + n0 + tx];
    __syncthreads();
#pragma unroll
    for (int i = 0; i < 4; ++i) {
        float v = t[tx][ty + i * 8];
        Tf[(size_t)(n0 + ty + i * 8) * E_ + k0 + tx] = __float2half_rn(v);
    }
}

// ---------------------------------------------------------------------------
// FA2-style causal attention, fp16 mma.sync, race-safe KV pipeline.
// Grid x reversed: big (late-qb) CTAs launch first for tail balance.
// ---------------------------------------------------------------------------
#define AROWB 144
#define KVREG (64 * AROWB)              // 9216
#define KVBUF (2 * KVREG)               // 18432
#define QREG  (128 * AROWB)             // 18432
#define ATT_SMEM (QREG + 2 * KVBUF)     // 55296

__global__ __launch_bounds__(256)
void attn_f16_kernel(__half* __restrict__ Yf,
                     const __half* __restrict__ Qf, const __half* __restrict__ Kf,
                     const __half* __restrict__ Vf) {
    extern __shared__ char smem[];
    const uint32_t sbase = smem_u32(smem);
    const uint32_t sQ = sbase;
    const uint32_t sKV = sbase + QREG;

    const int tid = threadIdx.x;
    const int wid = tid >> 5, lane = tid & 31;
    const int qb = gridDim.x - 1 - blockIdx.x;    // reversed: big tiles first
    const int h  = blockIdx.y;
    const int b  = blockIdx.z;
    const int kh = h >> 2;
    const int bT0 = b * T_;

    const int row0 = qb * 128 + wid * 16 + (lane >> 2);
    const int row1 = row0 + 8;
    const int rowmin_w = qb * 128 + wid * 16;
    const int rowmax_w = rowmin_w + 15;

#pragma unroll
    for (int j = 0; j < 4; ++j) {
        int c = tid + j * 256;
        int row = c >> 3, part = c & 7;
        cp_async16(sQ + row * AROWB + part * 16,
                   Qf + (size_t)(bT0 + qb * 128 + row) * (H_ * D_) + h * 64 + part * 8);
    }
#pragma unroll
    for (int j = 0; j < 4; ++j) {
        int c = tid + j * 256;
        int reg = c >> 9, idx = c & 511;
        int row = idx >> 3, part = idx & 7;
        const __half* src = reg ? Vf : Kf;
        cp_async16(sKV + reg * KVREG + row * AROWB + part * 16,
                   src + (size_t)(bT0 + row) * (HKV_ * D_) + kh * 64 + part * 8);
    }
    CP_COMMIT();
    CP_WAIT(0);
    __syncthreads();

    uint32_t qf[4][4];
#pragma unroll
    for (int ks = 0; ks < 4; ++ks) {
        uint32_t qa = (wid * 16 + (lane & 15)) * AROWB + ks * 32 + (lane >> 4) * 16;
        ldmx4(qf[ks], sQ + qa);
    }

    float o[8][4];
#pragma unroll
    for (int j = 0; j < 8; ++j)
#pragma unroll
        for (int k = 0; k < 4; ++k) o[j][k] = 0.0f;
    float m0 = -1e30f, m1 = -1e30f, l0 = 0.0f, l1 = 0.0f;
    const float scale = 0.125f;

    const int NT = 2 * qb + 2;
    int buf = 0;
    for (int it = 0; it < NT; ++it) {
        CP_WAIT(0);                      // tile `it` resident
        __syncthreads();                 // everyone done with the other buffer
        if (it + 1 < NT) {
            uint32_t sb = sKV + (buf ^ 1) * KVBUF;
#pragma unroll
            for (int j = 0; j < 4; ++j) {
                int c = tid + j * 256;
                int reg = c >> 9, idx = c & 511;
                int row = idx >> 3, part = idx & 7;
                const __half* src = reg ? Vf : Kf;
                cp_async16(sb + reg * KVREG + row * AROWB + part * 16,
                           src + (size_t)(bT0 + (it + 1) * 64 + row) * (HKV_ * D_) + kh * 64 + part * 8);
            }
            CP_COMMIT();
        }

        const int kt = it;
        if (kt * 64 <= rowmax_w) {
            const uint32_t sb = sKV + buf * KVBUF;
            const uint32_t sK = sb, sV = sb + KVREG;

            float s[8][4];
#pragma unroll
            for (int j = 0; j < 8; ++j)
#pragma unroll
                for (int k = 0; k < 4; ++k) s[j][k] = 0.0f;

#pragma unroll
            for (int ks = 0; ks < 4; ++ks) {
#pragma unroll
                for (int pg = 0; pg < 2; ++pg) {
                    uint32_t kf[2][4];
#pragma unroll
                    for (int pp = 0; pp < 2; ++pp) {
                        uint32_t ka = ((2 * pg + pp) * 16 + (lane & 15)) * AROWB + ks * 32 + (lane >> 4) * 16;
                        ldmx4(kf[pp], sK + ka);
                    }
#pragma unroll
                    for (int pp = 0; pp < 2; ++pp)
#pragma unroll
                        for (int q = 0; q < 2; ++q)
                            mma_f16(s[(2 * pg + pp) * 2 + q], qf[ks], kf[pp][q], kf[pp][q + 2]);
                }
            }

            const bool needs_mask = (kt * 64 + 63) > rowmin_w;
#pragma unroll
            for (int j = 0; j < 8; ++j) {
#pragma unroll
                for (int k = 0; k < 4; ++k) s[j][k] *= scale;
                if (needs_mask) {
                    int colb = kt * 64 + j * 8 + 2 * (lane & 3);
                    if (colb > row0)     s[j][0] = -1e30f;
                    if (colb + 1 > row0) s[j][1] = -1e30f;
                    if (colb > row1)     s[j][2] = -1e30f;
                    if (colb + 1 > row1) s[j][3] = -1e30f;
                }
            }

            float mx0 = -1e30f, mx1 = -1e30f;
#pragma unroll
            for (int j = 0; j < 8; ++j) {
                mx0 = fmaxf(mx0, fmaxf(s[j][0], s[j][1]));
                mx1 = fmaxf(mx1, fmaxf(s[j][2], s[j][3]));
            }
            mx0 = fmaxf(mx0, __shfl_xor_sync(0xFFFFFFFF, mx0, 1));
            mx0 = fmaxf(mx0, __shfl_xor_sync(0xFFFFFFFF, mx0, 2));
            mx1 = fmaxf(mx1, __shfl_xor_sync(0xFFFFFFFF, mx1, 1));
            mx1 = fmaxf(mx1, __shfl_xor_sync(0xFFFFFFFF, mx1, 2));

            float mn0 = fmaxf(m0, mx0), mn1 = fmaxf(m1, mx1);
            float c0 = __expf(m0 - mn0), c1 = __expf(m1 - mn1);
            m0 = mn0; m1 = mn1;
            l0 *= c0; l1 *= c1;
#pragma unroll
            for (int j = 0; j < 8; ++j) {
                o[j][0] *= c0; o[j][1] *= c0; o[j][2] *= c1; o[j][3] *= c1;
            }
#pragma unroll
            for (int j = 0; j < 8; ++j) {
                s[j][0] = __expf(s[j][0] - mn0);
                s[j][1] = __expf(s[j][1] - mn0);
                s[j][2] = __expf(s[j][2] - mn1);
                s[j][3] = __expf(s[j][3] - mn1);
                l0 += s[j][0] + s[j][1];
                l1 += s[j][2] + s[j][3];
            }

#pragma unroll
            for (int ks = 0; ks < 4; ++ks) {
                uint32_t pa[4];
                pa[0] = pack_h2(s[2 * ks][0], s[2 * ks][1]);
                pa[1] = pack_h2(s[2 * ks][2], s[2 * ks][3]);
                pa[2] = pack_h2(s[2 * ks + 1][0], s[2 * ks + 1][1]);
                pa[3] = pack_h2(s[2 * ks + 1][2], s[2 * ks + 1][3]);
#pragma unroll
                for (int pg = 0; pg < 2; ++pg) {
                    uint32_t vf[2][4];
#pragma unroll
                    for (int pp = 0; pp < 2; ++pp) {
                        uint32_t va = (ks * 16 + (lane & 15)) * AROWB + (2 * pg + pp) * 32 + (lane >> 4) * 16;
                        ldmx4t(vf[pp], sV + va);
                    }
#pragma unroll
                    for (int pp = 0; pp < 2; ++pp)
#pragma unroll
                        for (int q = 0; q < 2; ++q)
                            mma_f16(o[(2 * pg + pp) * 2 + q], pa, vf[pp][2 * q], vf[pp][2 * q + 1]);
                }
            }
        }
        buf ^= 1;
    }

    l0 += __shfl_xor_sync(0xFFFFFFFF, l0, 1);
    l0 += __shfl_xor_sync(0xFFFFFFFF, l0, 2);
    l1 += __shfl_xor_sync(0xFFFFFFFF, l1, 1);
    l1 += __shfl_xor_sync(0xFFFFFFFF, l1, 2);
    float inv0 = 1.0f / l0, inv1 = 1.0f / l1;

#pragma unroll
    for (int j = 0; j < 8; ++j) {
        int col = j * 8 + 2 * (lane & 3);
        size_t a0 = ((size_t)(bT0 + row0) * H_ + h) * 64 + col;
        size_t a1 = ((size_t)(bT0 + row1) * H_ + h) * 64 + col;
        *(uint32_t*)&Yf[a0] = pack_h2(o[j][0] * inv0, o[j][1] * inv0);
        *(uint32_t*)&Yf[a1] = pack_h2(o[j][2] * inv1, o[j][3] * inv1);
    }
}

// ---------------------------------------------------------------------------
// kernel_launch — QKV gemm stays our 4th launch (ncu capture target)
// ---------------------------------------------------------------------------
extern "C" void kernel_launch(void* const* d_in, const int* in_sizes, int n_in,
                              void* d_out, int out_size) {
    const float* x  = (const float*)d_in[0];
    const float* Wq = (const float*)d_in[1];
    const float* Wk = (const float*)d_in[2];
    const float* Wv = (const float*)d_in[3];
    const float* Wo = (const float*)d_in[4];
    float* out = (float*)d_out;

    __half *pxf, *pQf, *pKf, *pVf, *pYf, *pWcf, *pWof;
    float2* ptab;
    cudaGetSymbolAddress((void**)&pxf, g_xf);
    cudaGetSymbolAddress((void**)&pQf, g_Qf);
    cudaGetSymbolAddress((void**)&pKf, g_Kf);
    cudaGetSymbolAddress((void**)&pVf, g_Vf);
    cudaGetSymbolAddress((void**)&pYf, g_Yf);
    cudaGetSymbolAddress((void**)&pWcf, g_Wcf);
    cudaGetSymbolAddress((void**)&pWof, g_Wof);
    cudaGetSymbolAddress((void**)&ptab, g_tab);

    cudaFuncSetAttribute(gemm1_kernel, cudaFuncAttributeMaxDynamicSharedMemorySize, G1_SMEM);
    cudaFuncSetAttribute(attn_f16_kernel, cudaFuncAttributeMaxDynamicSharedMemorySize, ATT_SMEM);

    // #1 rope cos/sin table
    rope_tab_kernel<<<(T_ * 32 + 255) / 256, 256>>>(ptab);
    // #2 x -> fp16
    {
        int n4 = (BT_ * E_) / 4;
        cvt_f16_kernel<<<(n4 + 255) / 256, 256>>>(x, pxf, n4);
    }
    // #3 fused transpose Wq|Wk|Wv -> fp16 concat
    tsplit3_kernel<<<dim3(64, 64, 3), dim3(32, 8)>>>(Wq, Wk, Wv, pWcf);

    // #4 fused QKV projection with in-epilogue RoPE (ncu capture target)
    gemm1_kernel<<<dim3(NQKV / 128, BT_ / 128), 128, G1_SMEM>>>(
        nullptr, pQf, pKf, pVf, ptab, pxf, pWcf, BT_, NQKV, E_, 1);

    // #5 transpose Wo -> fp16
    twof16_kernel<<<dim3(64, 64), dim3(32, 8)>>>(Wo, pWof);

    // #6 attention
    attn_f16_kernel<<<dim3(T_ / 128, H_, B_), 256, ATT_SMEM>>>(pYf, pQf, pKf, pVf);

    // #7 output projection, single-term fp16
    gemm1_kernel<<<dim3(E_ / 128, BT_ / 128), 128, G1_SMEM>>>(
        out, nullptr, nullptr, nullptr, nullptr, pYf, pWof, BT_, E_, E_, 0);
}

// round 12
// speedup vs baseline: 2.9850x; 1.0269x over previous
#include <cuda_runtime.h>
#include <cuda_bf16.h>
#include <cuda_fp16.h>
#include <cstdint>
#include <math.h>

// Problem constants
#define B_  2
#define T_  2048
#define E_  2048
#define H_  32
#define HKV_ 8
#define D_  64
#define BT_ (B_*T_)  // 4096
#define NQKV 3072    // 2048 Q + 512 K + 512 V

// ---------------------------------------------------------------------------
// Scratch (static device globals — allocation-free rule)
// ---------------------------------------------------------------------------
__device__ __half g_xf[BT_ * E_];               // x in fp16
__device__ __half g_Qf[BT_ * H_ * D_];          // post-rope Q fp16
__device__ __half g_Kf[BT_ * HKV_ * D_];        // post-rope K fp16
__device__ __half g_Vf[BT_ * HKV_ * D_];
__device__ __half g_Yf[BT_ * E_];               // attention output fp16
__device__ __half g_Wcf[NQKV * E_];             // concat Wq|Wk|Wv transposed [N,K] fp16
__device__ __half g_Wof[E_ * E_];               // Wo transposed fp16
__device__ float2 g_tab[T_ * 32];               // rope cos/sin table

// ---------------------------------------------------------------------------
// PTX helpers
// ---------------------------------------------------------------------------
__device__ __forceinline__ uint32_t smem_u32(const void* p) {
    uint32_t a;
    asm("{ .reg .u64 t; cvta.to.shared.u64 t, %1; cvt.u32.u64 %0, t; }" : "=r"(a) : "l"(p));
    return a;
}
__device__ __forceinline__ void ldmx4(uint32_t* r, uint32_t addr) {
    asm volatile("ldmatrix.sync.aligned.m8n8.x4.shared.b16 {%0,%1,%2,%3}, [%4];"
                 : "=r"(r[0]), "=r"(r[1]), "=r"(r[2]), "=r"(r[3]) : "r"(addr));
}
__device__ __forceinline__ void ldmx4t(uint32_t* r, uint32_t addr) {
    asm volatile("ldmatrix.sync.aligned.m8n8.x4.trans.shared.b16 {%0,%1,%2,%3}, [%4];"
                 : "=r"(r[0]), "=r"(r[1]), "=r"(r[2]), "=r"(r[3]) : "r"(addr));
}
__device__ __forceinline__ void mma_f16(float* acc, const uint32_t* a, const uint32_t b0,
                                        const uint32_t b1) {
    asm volatile(
        "mma.sync.aligned.m16n8k16.row.col.f32.f16.f16.f32 "
        "{%0,%1,%2,%3}, {%4,%5,%6,%7}, {%8,%9}, {%0,%1,%2,%3};"
        : "+f"(acc[0]), "+f"(acc[1]), "+f"(acc[2]), "+f"(acc[3])
        : "r"(a[0]), "r"(a[1]), "r"(a[2]), "r"(a[3]), "r"(b0), "r"(b1));
}
__device__ __forceinline__ void cp_async16(uint32_t saddr, const void* gaddr) {
    asm volatile("cp.async.cg.shared.global [%0], [%1], 16;" :: "r"(saddr), "l"(gaddr));
}
#define CP_COMMIT() asm volatile("cp.async.commit_group;" ::: "memory")
#define CP_WAIT(n)  asm volatile("cp.async.wait_group %0;" :: "n"(n) : "memory")

__device__ __forceinline__ uint32_t pack_h2(float lo, float hi) {
    __half2 v = __floats2half2_rn(lo, hi);
    return *reinterpret_cast<uint32_t*>(&v);
}

// ---------------------------------------------------------------------------
// gemm1: single-term fp16 GEMM, BK=64, 2-stage cp.async, race-safe ordering.
// A[M,K], B[N,K] fp16. CTA tile 128x128, 128 threads (4 warps), warp 64x64.
// __launch_bounds__(128, 3): cap regs at 170 -> 3 CTAs/SM (12 warps).
// mode 0: plain fp32 out stride N.
// mode 1: fused QKV epilogue with in-register RoPE.
// ---------------------------------------------------------------------------
#define ROWB   144
#define REGB   (128 * ROWB)          // 18432 per region (128 rows x 64 halves)
#define G1_STG (2 * REGB)            // A + B = 36864
#define G1_SMEM (2 * G1_STG)         // 73728 (double buffered)

__device__ __forceinline__ void g1_issue(uint32_t sbuf, const __half* a, const __half* b,
                                         int K, int tid) {
    const __half* srcs[2] = {a, b};
#pragma unroll
    for (int reg = 0; reg < 2; ++reg) {
        const __half* s = srcs[reg];
        uint32_t sr = sbuf + reg * REGB;
#pragma unroll
        for (int j = 0; j < 8; ++j) {
            int c = tid + j * 128;          // 0..1023
            int row = c >> 3, part = c & 7;
            cp_async16(sr + row * ROWB + part * 16, s + (size_t)row * K + part * 8);
        }
    }
}

__global__ __launch_bounds__(128, 3)
void gemm1_kernel(float* __restrict__ C,
                  __half* __restrict__ Oq, __half* __restrict__ Ok, __half* __restrict__ Ov,
                  const float2* __restrict__ tab,
                  const __half* __restrict__ A, const __half* __restrict__ B,
                  int M, int N, int K, int mode) {
    extern __shared__ char smem[];
    const uint32_t sbase = smem_u32(smem);
    const int tid = threadIdx.x;
    const int wid = tid >> 5, lane = tid & 31;
    const int warp_m = wid >> 1;          // 0..1 -> 64-row slab
    const int warp_n = wid & 1;           // 0..1 -> 64-col slab
    const int bm = blockIdx.y * 128, bn = blockIdx.x * 128;

    const __half* pA = A + (size_t)bm * K;
    const __half* pB = B + (size_t)bn * K;

    float acc[4][8][4];
#pragma unroll
    for (int i = 0; i < 4; ++i)
#pragma unroll
        for (int j = 0; j < 8; ++j)
#pragma unroll
            for (int k = 0; k < 4; ++k) acc[i][j][k] = 0.0f;

    const int NIT = K / 64;               // 32

    const uint32_t a_row = warp_m * 64 + (lane & 15);
    const uint32_t a_coff = (lane >> 4) * 16;
    const uint32_t b_rowbase = warp_n * 64 + (lane & 15);
    const uint32_t b_coff = (lane >> 4) * 16;

    g1_issue(sbase, pA, pB, K, tid);
    CP_COMMIT();

    int buf = 0;
    for (int it = 0; it < NIT; ++it) {
        CP_WAIT(0);                      // current stage resident
        __syncthreads();                 // everyone done with the other buffer
        if (it + 1 < NIT) {
            g1_issue(sbase + (buf ^ 1) * G1_STG,
                     pA + (it + 1) * 64, pB + (it + 1) * 64, K, tid);
            CP_COMMIT();
        }

        const uint32_t sbuf = sbase + buf * G1_STG;
        const uint32_t sA = sbuf, sB = sbuf + REGB;
#pragma unroll
        for (int ks = 0; ks < 4; ++ks) {
            const uint32_t kb = ks * 32;
            uint32_t bf[16];
#pragma unroll
            for (int p = 0; p < 4; ++p) {
                uint32_t ba = (b_rowbase + p * 16) * ROWB + kb + b_coff;
                ldmx4(&bf[p * 4], sB + ba);
            }
            uint32_t af[4][4];
#pragma unroll
            for (int mi = 0; mi < 4; ++mi) {
                uint32_t aa = (a_row + mi * 16) * ROWB + kb + a_coff;
                ldmx4(af[mi], sA + aa);
            }
#pragma unroll
            for (int mi = 0; mi < 4; ++mi)
#pragma unroll
                for (int ni = 0; ni < 8; ++ni) {
                    const int p = ni >> 1, q = ni & 1;
                    mma_f16(acc[mi][ni], af[mi], bf[p * 4 + q], bf[p * 4 + q + 2]);
                }
        }
        buf ^= 1;
    }

    const int rbase = bm + warp_m * 64 + (lane >> 2);
    const int j0 = (lane & 3) * 2;             // col-in-head base, < 8
    const int ch = bn + warp_n * 64;           // warp's global col base (one head)

    if (mode == 0) {
        const int cbase = ch + j0;
#pragma unroll
        for (int mi = 0; mi < 4; ++mi)
#pragma unroll
            for (int ni = 0; ni < 8; ++ni) {
                float* c0 = C + (size_t)(rbase + mi * 16) * N + cbase + ni * 8;
                float* c1 = C + (size_t)(rbase + mi * 16 + 8) * N + cbase + ni * 8;
                *(float2*)c0 = make_float2(acc[mi][ni][0], acc[mi][ni][1]);
                *(float2*)c1 = make_float2(acc[mi][ni][2], acc[mi][ni][3]);
            }
        return;
    }

    if (ch < 2560) {
        // Q or K: apply RoPE in-register, store fp16
        __half* dst;
        int ldc, cofs;
        if (ch < 2048) { dst = Oq; ldc = H_ * D_;  cofs = ch; }
        else           { dst = Ok; ldc = HKV_ * D_; cofs = ch - 2048; }
#pragma unroll
        for (int mi = 0; mi < 4; ++mi) {
#pragma unroll
            for (int hf = 0; hf < 2; ++hf) {
                const int r = rbase + mi * 16 + hf * 8;
                const int t = r & (T_ - 1);
                const float2* trow = tab + t * 32;
#pragma unroll
                for (int ni0 = 0; ni0 < 4; ++ni0) {
                    const int j = j0 + ni0 * 8;          // < 32
                    float a1 = acc[mi][ni0][2 * hf + 0];
                    float a2 = acc[mi][ni0][2 * hf + 1];
                    float b1 = acc[mi][ni0 + 4][2 * hf + 0];
                    float b2 = acc[mi][ni0 + 4][2 * hf + 1];
                    float2 cs1 = trow[j];
                    float2 cs2 = trow[j + 1];
                    float o1 = a1 * cs1.x - b1 * cs1.y;
                    float p1 = b1 * cs1.x + a1 * cs1.y;
                    float o2 = a2 * cs2.x - b2 * cs2.y;
                    float p2 = b2 * cs2.x + a2 * cs2.y;
                    size_t base = (size_t)r * ldc + cofs + j;
                    *(uint32_t*)&dst[base]      = pack_h2(o1, o2);
                    *(uint32_t*)&dst[base + 32] = pack_h2(p1, p2);
                }
            }
        }
    } else {
        // V: plain fp16 store
        const int cbase = ch - 2560 + j0;
#pragma unroll
        for (int mi = 0; mi < 4; ++mi)
#pragma unroll
            for (int ni = 0; ni < 8; ++ni) {
                *(uint32_t*)&Ov[(size_t)(rbase + mi * 16) * 512 + cbase + ni * 8] =
                    pack_h2(acc[mi][ni][0], acc[mi][ni][1]);
                *(uint32_t*)&Ov[(size_t)(rbase + mi * 16 + 8) * 512 + cbase + ni * 8] =
                    pack_h2(acc[mi][ni][2], acc[mi][ni][3]);
            }
    }
}

// ---------------------------------------------------------------------------
// Rope table: tab[t*32+i] = (cos, sin)(t * 10000^(-i/32))
// ---------------------------------------------------------------------------
__global__ __launch_bounds__(256)
void rope_tab_kernel(float2* __restrict__ tab) {
    int idx = blockIdx.x * blockDim.x + threadIdx.x;
    if (idx >= T_ * 32) return;
    int i = idx & 31, t = idx >> 5;
    float inv_freq = expf(-(float)i * (9.210340371976184f / 32.0f));
    float ang = (float)t * inv_freq;
    tab[idx] = make_float2(cosf(ang), sinf(ang));
}

// ---------------------------------------------------------------------------
// fp32 -> fp16 convert (vectorized x4)
// ---------------------------------------------------------------------------
__global__ __launch_bounds__(256)
void cvt_f16_kernel(const float* __restrict__ in, __half* __restrict__ out, int n4) {
    int i = blockIdx.x * blockDim.x + threadIdx.x;
    if (i >= n4) return;
    float4 v = ((const float4*)in)[i];
    ((uint2*)out)[i] = make_uint2(pack_h2(v.x, v.y), pack_h2(v.z, v.w));
}

// ---------------------------------------------------------------------------
// Vectorized transpose W[K,N] fp32 -> Tf[N,K] fp16, h2-packed stores.
// Tile: 32 n-cols x 64 k-rows. Block (32, 8).
// Load: W[k][n] coalesced (tx = n). Store: Tf[n][k] as uint32 (2 halves, tx = k/2).
// ---------------------------------------------------------------------------
__global__ __launch_bounds__(256)
void txpose_kernel(const float* __restrict__ W, __half* __restrict__ Tf,
                   int K, int N, int nofs) {
    __shared__ float t[64][33];          // [k][n], pad to kill bank conflicts
    const int tx = threadIdx.x, ty = threadIdx.y;
    const int n0 = blockIdx.x * 32, k0 = blockIdx.y * 64;
#pragma unroll
    for (int i = 0; i < 8; ++i)
        t[ty + i * 8][tx] = W[(size_t)(k0 + ty + i * 8) * N + n0 + tx];
    __syncthreads();
    // 32 n-rows x 32 uint32 (=64 halves). thread (tx,ty): n = ty+i*8, kpair = tx
#pragma unroll
    for (int i = 0; i < 4; ++i) {
        int n = ty + i * 8;
        uint32_t v = pack_h2(t[2 * tx][n], t[2 * tx + 1][n]);
        *(uint32_t*)&Tf[(size_t)(nofs + n0 + n) * K + k0 + 2 * tx] = v;
    }
}

// Fused Wq|Wk|Wv variant (z selects matrix, writes into concat buffer)
__global__ __launch_bounds__(256)
void txpose3_kernel(const float* __restrict__ Wq, const float* __restrict__ Wk,
                    const float* __restrict__ Wv, __half* __restrict__ Tf) {
    __shared__ float t[64][33];
    const int z = blockIdx.z;
    const float* W = (z == 0) ? Wq : (z == 1) ? Wk : Wv;
    const int N = (z == 0) ? (H_ * D_) : (HKV_ * D_);
    const int nofs = (z == 0) ? 0 : (z == 1) ? 2048 : 2560;
    const int n0 = blockIdx.x * 32, k0 = blockIdx.y * 64;
    if (n0 >= N) return;
    const int tx = threadIdx.x, ty = threadIdx.y;
#pragma unroll
    for (int i = 0; i < 8; ++i)
        t[ty + i * 8][tx] = W[(size_t)(k0 + ty + i * 8) * N + n0 + tx];
    __syncthreads();
#pragma unroll
    for (int i = 0; i < 4; ++i) {
        int n = ty + i * 8;
        uint32_t v = pack_h2(t[2 * tx][n], t[2 * tx + 1][n]);
        *(uint32_t*)&Tf[(size_t)(nofs + n0 + n) * E_ + k0 + 2 * tx] = v;
    }
}

// ---------------------------------------------------------------------------
// FA2-style causal attention, fp16 mma.sync, race-safe KV pipeline.
// Grid x reversed: big (late-qb) CTAs launch first for tail balance.
// ---------------------------------------------------------------------------
#define AROWB 144
#define KVREG (64 * AROWB)              // 9216
#define KVBUF (2 * KVREG)               // 18432
#define QREG  (128 * AROWB)             // 18432
#define ATT_SMEM (QREG + 2 * KVBUF)     // 55296

__global__ __launch_bounds__(256)
void attn_f16_kernel(__half* __restrict__ Yf,
                     const __half* __restrict__ Qf, const __half* __restrict__ Kf,
                     const __half* __restrict__ Vf) {
    extern __shared__ char smem[];
    const uint32_t sbase = smem_u32(smem);
    const uint32_t sQ = sbase;
    const uint32_t sKV = sbase + QREG;

    const int tid = threadIdx.x;
    const int wid = tid >> 5, lane = tid & 31;
    const int qb = gridDim.x - 1 - blockIdx.x;    // reversed: big tiles first
    const int h  = blockIdx.y;
    const int b  = blockIdx.z;
    const int kh = h >> 2;
    const int bT0 = b * T_;

    const int row0 = qb * 128 + wid * 16 + (lane >> 2);
    const int row1 = row0 + 8;
    const int rowmin_w = qb * 128 + wid * 16;
    const int rowmax_w = rowmin_w + 15;

#pragma unroll
    for (int j = 0; j < 4; ++j) {
        int c = tid + j * 256;
        int row = c >> 3, part = c & 7;
        cp_async16(sQ + row * AROWB + part * 16,
                   Qf + (size_t)(bT0 + qb * 128 + row) * (H_ * D_) + h * 64 + part * 8);
    }
#pragma unroll
    for (int j = 0; j < 4; ++j) {
        int c = tid + j * 256;
        int reg = c >> 9, idx = c & 511;
        int row = idx >> 3, part = idx & 7;
        const __half* src = reg ? Vf : Kf;
        cp_async16(sKV + reg * KVREG + row * AROWB + part * 16,
                   src + (size_t)(bT0 + row) * (HKV_ * D_) + kh * 64 + part * 8);
    }
    CP_COMMIT();
    CP_WAIT(0);
    __syncthreads();

    uint32_t qf[4][4];
#pragma unroll
    for (int ks = 0; ks < 4; ++ks) {
        uint32_t qa = (wid * 16 + (lane & 15)) * AROWB + ks * 32 + (lane >> 4) * 16;
        ldmx4(qf[ks], sQ + qa);
    }

    float o[8][4];
#pragma unroll
    for (int j = 0; j < 8; ++j)
#pragma unroll
        for (int k = 0; k < 4; ++k) o[j][k] = 0.0f;
    float m0 = -1e30f, m1 = -1e30f, l0 = 0.0f, l1 = 0.0f;
    const float scale = 0.125f;

    const int NT = 2 * qb + 2;
    int buf = 0;
    for (int it = 0; it < NT; ++it) {
        CP_WAIT(0);                      // tile `it` resident
        __syncthreads();                 // everyone done with the other buffer
        if (it + 1 < NT) {
            uint32_t sb = sKV + (buf ^ 1) * KVBUF;
#pragma unroll
            for (int j = 0; j < 4; ++j) {
                int c = tid + j * 256;
                int reg = c >> 9, idx = c & 511;
                int row = idx >> 3, part = idx & 7;
                const __half* src = reg ? Vf : Kf;
                cp_async16(sb + reg * KVREG + row * AROWB + part * 16,
                           src + (size_t)(bT0 + (it + 1) * 64 + row) * (HKV_ * D_) + kh * 64 + part * 8);
            }
            CP_COMMIT();
        }

        const int kt = it;
        if (kt * 64 <= rowmax_w) {
            const uint32_t sb = sKV + buf * KVBUF;
            const uint32_t sK = sb, sV = sb + KVREG;

            float s[8][4];
#pragma unroll
            for (int j = 0; j < 8; ++j)
#pragma unroll
                for (int k = 0; k < 4; ++k) s[j][k] = 0.0f;

#pragma unroll
            for (int ks = 0; ks < 4; ++ks) {
#pragma unroll
                for (int pg = 0; pg < 2; ++pg) {
                    uint32_t kf[2][4];
#pragma unroll
                    for (int pp = 0; pp < 2; ++pp) {
                        uint32_t ka = ((2 * pg + pp) * 16 + (lane & 15)) * AROWB + ks * 32 + (lane >> 4) * 16;
                        ldmx4(kf[pp], sK + ka);
                    }
#pragma unroll
                    for (int pp = 0; pp < 2; ++pp)
#pragma unroll
                        for (int q = 0; q < 2; ++q)
                            mma_f16(s[(2 * pg + pp) * 2 + q], qf[ks], kf[pp][q], kf[pp][q + 2]);
                }
            }

            const bool needs_mask = (kt * 64 + 63) > rowmin_w;
#pragma unroll
            for (int j = 0; j < 8; ++j) {
#pragma unroll
                for (int k = 0; k < 4; ++k) s[j][k] *= scale;
                if (needs_mask) {
                    int colb = kt * 64 + j * 8 + 2 * (lane & 3);
                    if (colb > row0)     s[j][0] = -1e30f;
                    if (colb + 1 > row0) s[j][1] = -1e30f;
                    if (colb > row1)     s[j][2] = -1e30f;
                    if (colb + 1 > row1) s[j][3] = -1e30f;
                }
            }

            float mx0 = -1e30f, mx1 = -1e30f;
#pragma unroll
            for (int j = 0; j < 8; ++j) {
                mx0 = fmaxf(mx0, fmaxf(s[j][0], s[j][1]));
                mx1 = fmaxf(mx1, fmaxf(s[j][2], s[j][3]));
            }
            mx0 = fmaxf(mx0, __shfl_xor_sync(0xFFFFFFFF, mx0, 1));
            mx0 = fmaxf(mx0, __shfl_xor_sync(0xFFFFFFFF, mx0, 2));
            mx1 = fmaxf(mx1, __shfl_xor_sync(0xFFFFFFFF, mx1, 1));
            mx1 = fmaxf(mx1, __shfl_xor_sync(0xFFFFFFFF, mx1, 2));

            float mn0 = fmaxf(m0, mx0), mn1 = fmaxf(m1, mx1);
            float c0 = __expf(m0 - mn0), c1 = __expf(m1 - mn1);
            m0 = mn0; m1 = mn1;
            l0 *= c0; l1 *= c1;
#pragma unroll
            for (int j = 0; j < 8; ++j) {
                o[j][0] *= c0; o[j][1] *= c0; o[j][2] *= c1; o[j][3] *= c1;
            }
#pragma unroll
            for (int j = 0; j < 8; ++j) {
                s[j][0] = __expf(s[j][0] - mn0);
                s[j][1] = __expf(s[j][1] - mn0);
                s[j][2] = __expf(s[j][2] - mn1);
                s[j][3] = __expf(s[j][3] - mn1);
                l0 += s[j][0] + s[j][1];
                l1 += s[j][2] + s[j][3];
            }

#pragma unroll
            for (int ks = 0; ks < 4; ++ks) {
                uint32_t pa[4];
                pa[0] = pack_h2(s[2 * ks][0], s[2 * ks][1]);
                pa[1] = pack_h2(s[2 * ks][2], s[2 * ks][3]);
                pa[2] = pack_h2(s[2 * ks + 1][0], s[2 * ks + 1][1]);
                pa[3] = pack_h2(s[2 * ks + 1][2], s[2 * ks + 1][3]);
#pragma unroll
                for (int pg = 0; pg < 2; ++pg) {
                    uint32_t vf[2][4];
#pragma unroll
                    for (int pp = 0; pp < 2; ++pp) {
                        uint32_t va = (ks * 16 + (lane & 15)) * AROWB + (2 * pg + pp) * 32 + (lane >> 4) * 16;
                        ldmx4t(vf[pp], sV + va);
                    }
#pragma unroll
                    for (int pp = 0; pp < 2; ++pp)
#pragma unroll
                        for (int q = 0; q < 2; ++q)
                            mma_f16(o[(2 * pg + pp) * 2 + q], pa, vf[pp][2 * q], vf[pp][2 * q + 1]);
                }
            }
        }
        buf ^= 1;
    }

    l0 += __shfl_xor_sync(0xFFFFFFFF, l0, 1);
    l0 += __shfl_xor_sync(0xFFFFFFFF, l0, 2);
    l1 += __shfl_xor_sync(0xFFFFFFFF, l1, 1);
    l1 += __shfl_xor_sync(0xFFFFFFFF, l1, 2);
    float inv0 = 1.0f / l0, inv1 = 1.0f / l1;

#pragma unroll
    for (int j = 0; j < 8; ++j) {
        int col = j * 8 + 2 * (lane & 3);
        size_t a0 = ((size_t)(bT0 + row0) * H_ + h) * 64 + col;
        size_t a1 = ((size_t)(bT0 + row1) * H_ + h) * 64 + col;
        *(uint32_t*)&Yf[a0] = pack_h2(o[j][0] * inv0, o[j][1] * inv0);
        *(uint32_t*)&Yf[a1] = pack_h2(o[j][2] * inv1, o[j][3] * inv1);
    }
}

// ---------------------------------------------------------------------------
// kernel_launch — QKV gemm stays our 4th launch (ncu capture target)
// ---------------------------------------------------------------------------
extern "C" void kernel_launch(void* const* d_in, const int* in_sizes, int n_in,
                              void* d_out, int out_size) {
    const float* x  = (const float*)d_in[0];
    const float* Wq = (const float*)d_in[1];
    const float* Wk = (const float*)d_in[2];
    const float* Wv = (const float*)d_in[3];
    const float* Wo = (const float*)d_in[4];
    float* out = (float*)d_out;

    __half *pxf, *pQf, *pKf, *pVf, *pYf, *pWcf, *pWof;
    float2* ptab;
    cudaGetSymbolAddress((void**)&pxf, g_xf);
    cudaGetSymbolAddress((void**)&pQf, g_Qf);
    cudaGetSymbolAddress((void**)&pKf, g_Kf);
    cudaGetSymbolAddress((void**)&pVf, g_Vf);
    cudaGetSymbolAddress((void**)&pYf, g_Yf);
    cudaGetSymbolAddress((void**)&pWcf, g_Wcf);
    cudaGetSymbolAddress((void**)&pWof, g_Wof);
    cudaGetSymbolAddress((void**)&ptab, g_tab);

    cudaFuncSetAttribute(gemm1_kernel, cudaFuncAttributeMaxDynamicSharedMemorySize, G1_SMEM);
    cudaFuncSetAttribute(attn_f16_kernel, cudaFuncAttributeMaxDynamicSharedMemorySize, ATT_SMEM);

    // #1 rope cos/sin table
    rope_tab_kernel<<<(T_ * 32 + 255) / 256, 256>>>(ptab);
    // #2 x -> fp16
    {
        int n4 = (BT_ * E_) / 4;
        cvt_f16_kernel<<<(n4 + 255) / 256, 256>>>(x, pxf, n4);
    }
    // #3 fused transpose Wq|Wk|Wv -> fp16 concat (vectorized stores)
    txpose3_kernel<<<dim3(64, 32, 3), dim3(32, 8)>>>(Wq, Wk, Wv, pWcf);

    // #4 fused QKV projection with in-epilogue RoPE (ncu capture target)
    gemm1_kernel<<<dim3(NQKV / 128, BT_ / 128), 128, G1_SMEM>>>(
        nullptr, pQf, pKf, pVf, ptab, pxf, pWcf, BT_, NQKV, E_, 1);

    // #5 transpose Wo -> fp16 (vectorized stores)
    txpose_kernel<<<dim3(64, 32), dim3(32, 8)>>>(Wo, pWof, E_, E_, 0);

    // #6 attention
    attn_f16_kernel<<<dim3(T_ / 128, H_, B_), 256, ATT_SMEM>>>(pYf, pQf, pKf, pVf);

    // #7 output projection, single-term fp16
    gemm1_kernel<<<dim3(E_ / 128, BT_ / 128), 128, G1_SMEM>>>(
        out, nullptr, nullptr, nullptr, nullptr, pYf, pWof, BT_, E_, E_, 0);
}